// round 5
// baseline (speedup 1.0000x reference)
#include <cuda_runtime.h>
#include <math.h>

// Problem constants
#define BB   8
#define LL   1024
#define DD   1024
#define HH   16
#define HDIM 64
#define MTOT (BB*LL)          // 8192 rows for the big GEMMs

// ---------------------------------------------------------------------------
// Scratch (device globals: no cudaMalloc allowed)
// ---------------------------------------------------------------------------
__device__ float g_Q[(size_t)MTOT * DD];       // 32 MB
__device__ float g_K[(size_t)MTOT * DD];       // 32 MB
__device__ float g_V[(size_t)MTOT * DD];       // 32 MB
__device__ float g_attn[(size_t)MTOT * DD];    // 32 MB
__device__ float g_colsum[(size_t)BB * HH * LL]; // 512 KB

// ---------------------------------------------------------------------------
// SGEMM: C[M,N] = A[M,K] @ B[K,N] + bias[N]
// 128x128 block, BK=8, 256 threads, 8x8 per thread. M%128==0, N%128==0, K%8==0.
// ---------------------------------------------------------------------------
__global__ __launch_bounds__(256) void sgemm_bias_kernel(
    const float* __restrict__ A, const float* __restrict__ B,
    const float* __restrict__ bias, float* __restrict__ C,
    int M, int N, int K)
{
    __shared__ float As[8][128];   // transposed A tile: As[k][m]
    __shared__ float Bs[8][128];   // Bs[k][n]

    const int tid  = threadIdx.x;
    const int tRow = tid >> 4;     // 0..15
    const int tCol = tid & 15;     // 0..15

    const int cRow = blockIdx.y;   // M tile
    const int cCol = blockIdx.x;   // N tile

    // A tile loads: 128x8 floats = 256 float4 (one per thread)
    const int aRow = tid >> 1;            // 0..127
    const int aCol = (tid & 1) << 2;      // 0 or 4
    // B tile loads: 8x128 floats = 256 float4
    const int bRow = tid >> 5;            // 0..7
    const int bCol = (tid & 31) << 2;     // 0..124

    const float* Ab = A + (size_t)cRow * 128 * K;
    const float* Bb = B + (size_t)cCol * 128;

    float acc[8][8];
    #pragma unroll
    for (int i = 0; i < 8; i++)
        #pragma unroll
        for (int j = 0; j < 8; j++) acc[i][j] = 0.0f;

    for (int k0 = 0; k0 < K; k0 += 8) {
        float4 av = *(const float4*)(Ab + (size_t)aRow * K + k0 + aCol);
        As[aCol + 0][aRow] = av.x;
        As[aCol + 1][aRow] = av.y;
        As[aCol + 2][aRow] = av.z;
        As[aCol + 3][aRow] = av.w;
        float4 bv = *(const float4*)(Bb + (size_t)(k0 + bRow) * N + bCol);
        *(float4*)(&Bs[bRow][bCol]) = bv;
        __syncthreads();

        #pragma unroll
        for (int k = 0; k < 8; k++) {
            float ra[8], rb[8];
            float4 a0 = *(const float4*)(&As[k][tRow * 8]);
            float4 a1 = *(const float4*)(&As[k][tRow * 8 + 4]);
            ra[0]=a0.x; ra[1]=a0.y; ra[2]=a0.z; ra[3]=a0.w;
            ra[4]=a1.x; ra[5]=a1.y; ra[6]=a1.z; ra[7]=a1.w;
            float4 b0 = *(const float4*)(&Bs[k][tCol * 8]);
            float4 b1 = *(const float4*)(&Bs[k][tCol * 8 + 4]);
            rb[0]=b0.x; rb[1]=b0.y; rb[2]=b0.z; rb[3]=b0.w;
            rb[4]=b1.x; rb[5]=b1.y; rb[6]=b1.z; rb[7]=b1.w;
            #pragma unroll
            for (int i = 0; i < 8; i++)
                #pragma unroll
                for (int j = 0; j < 8; j++)
                    acc[i][j] = fmaf(ra[i], rb[j], acc[i][j]);
        }
        __syncthreads();
    }

    // epilogue with bias
    const int colBase = cCol * 128 + tCol * 8;
    float bsv[8];
    #pragma unroll
    for (int j = 0; j < 8; j++) bsv[j] = bias[colBase + j];
    #pragma unroll
    for (int i = 0; i < 8; i++) {
        const size_t row = (size_t)cRow * 128 + tRow * 8 + i;
        float4 o0, o1;
        o0.x = acc[i][0] + bsv[0]; o0.y = acc[i][1] + bsv[1];
        o0.z = acc[i][2] + bsv[2]; o0.w = acc[i][3] + bsv[3];
        o1.x = acc[i][4] + bsv[4]; o1.y = acc[i][5] + bsv[5];
        o1.z = acc[i][6] + bsv[6]; o1.w = acc[i][7] + bsv[7];
        *(float4*)(C + row * N + colBase)     = o0;
        *(float4*)(C + row * N + colBase + 4) = o1;
    }
}

// ---------------------------------------------------------------------------
// Column-softmax stats: Z[bh, k] = sum_q exp(Q_h[q] . K_h[k] / 32)
// Grid: (8 k-tiles, 128 bh). 256 threads; 8x8 S micro-tile per thread.
// Smem: Ks[64][128] + Qs[64][128] + red[16][128] = 73728 B
// ---------------------------------------------------------------------------
__global__ __launch_bounds__(256, 1) void attn_colsum_kernel(
    const float* __restrict__ Q, const float* __restrict__ Kg,
    float* __restrict__ colsum)
{
    extern __shared__ float sm[];
    float* Ks  = sm;            // [d][k]  64*128
    float* Qs  = sm + 8192;     // [d][q]  64*128
    float* red = sm + 16384;    // [16][128]

    const int tid  = threadIdx.x;
    const int tRow = tid >> 4;     // q-group 0..15
    const int tCol = tid & 15;     // k-group 0..15
    const int kt   = blockIdx.x;   // 0..7
    const int bh   = blockIdx.y;   // 0..127
    const int b    = bh >> 4;
    const int h    = bh & 15;
    const float scale = 0.03125f;  // 1/sqrt(1024)

    // load K tile (scaled, transposed): Ks[d][r]
    {
        const size_t baseK = ((size_t)b * LL + (size_t)kt * 128) * DD + h * HDIM;
        for (int l = tid; l < 2048; l += 256) {
            int r  = l >> 4;
            int d4 = (l & 15) << 2;
            float4 v = *(const float4*)(Kg + baseK + (size_t)r * DD + d4);
            Ks[(d4 + 0) * 128 + r] = v.x * scale;
            Ks[(d4 + 1) * 128 + r] = v.y * scale;
            Ks[(d4 + 2) * 128 + r] = v.z * scale;
            Ks[(d4 + 3) * 128 + r] = v.w * scale;
        }
    }

    float esum[8];
    #pragma unroll
    for (int j = 0; j < 8; j++) esum[j] = 0.0f;

    for (int qt = 0; qt < 8; qt++) {
        __syncthreads();  // prior GEMM done reading Qs
        const size_t baseQ = ((size_t)b * LL + (size_t)qt * 128) * DD + h * HDIM;
        for (int l = tid; l < 2048; l += 256) {
            int r  = l >> 4;
            int d4 = (l & 15) << 2;
            float4 v = *(const float4*)(Q + baseQ + (size_t)r * DD + d4);
            Qs[(d4 + 0) * 128 + r] = v.x;
            Qs[(d4 + 1) * 128 + r] = v.y;
            Qs[(d4 + 2) * 128 + r] = v.z;
            Qs[(d4 + 3) * 128 + r] = v.w;
        }
        __syncthreads();  // Qs ready (and Ks on first iter)

        float acc[8][8];
        #pragma unroll
        for (int i = 0; i < 8; i++)
            #pragma unroll
            for (int j = 0; j < 8; j++) acc[i][j] = 0.0f;

        #pragma unroll 8
        for (int d = 0; d < 64; d++) {
            float ra[8], rb[8];
            float4 a0 = *(const float4*)(Qs + d * 128 + tRow * 8);
            float4 a1 = *(const float4*)(Qs + d * 128 + tRow * 8 + 4);
            ra[0]=a0.x; ra[1]=a0.y; ra[2]=a0.z; ra[3]=a0.w;
            ra[4]=a1.x; ra[5]=a1.y; ra[6]=a1.z; ra[7]=a1.w;
            float4 b0 = *(const float4*)(Ks + d * 128 + tCol * 8);
            float4 b1 = *(const float4*)(Ks + d * 128 + tCol * 8 + 4);
            rb[0]=b0.x; rb[1]=b0.y; rb[2]=b0.z; rb[3]=b0.w;
            rb[4]=b1.x; rb[5]=b1.y; rb[6]=b1.z; rb[7]=b1.w;
            #pragma unroll
            for (int i = 0; i < 8; i++)
                #pragma unroll
                for (int j = 0; j < 8; j++)
                    acc[i][j] = fmaf(ra[i], rb[j], acc[i][j]);
        }
        // scores are tiny (|S| < ~0.5): exp without max subtraction is safe
        #pragma unroll
        for (int i = 0; i < 8; i++)
            #pragma unroll
            for (int j = 0; j < 8; j++)
                esum[j] += __expf(acc[i][j]);
    }

    __syncthreads();
    #pragma unroll
    for (int j = 0; j < 8; j++)
        red[tRow * 128 + tCol * 8 + j] = esum[j];
    __syncthreads();
    if (tid < 128) {
        float s = 0.0f;
        #pragma unroll
        for (int r = 0; r < 16; r++) s += red[r * 128 + tid];
        colsum[(size_t)bh * LL + kt * 128 + tid] = s;
    }
}

// ---------------------------------------------------------------------------
// AV kernel: out[bh, q, :] = sum_k exp(S_qk)/Z_k * V[k,:]
// Grid: (8 q-tiles, 128 bh). 256 threads.
// Smem: Qs[64][128] + KVs(8192) + Asm[128][132] = 133120 B
// ---------------------------------------------------------------------------
__global__ __launch_bounds__(256, 1) void attn_av_kernel(
    const float* __restrict__ Q, const float* __restrict__ Kg,
    const float* __restrict__ Vg, const float* __restrict__ colsum,
    float* __restrict__ O)
{
    extern __shared__ float sm[];
    float* Qs  = sm;            // [d][q]  64*128
    float* KVs = sm + 8192;     // Ks[d][k] (64*128)  then  Vs[k][d] (128*64)
    float* Asm = sm + 16384;    // A transposed: [k][q], pitch 132
    const int AP = 132;

    const int tid  = threadIdx.x;
    const int tRow = tid >> 4;     // q-group 0..15 (GEMM1 rows, GEMM2 rows)
    const int tCol = tid & 15;     // k-group (GEMM1) / d-group (GEMM2)
    const int qt   = blockIdx.x;   // 0..7
    const int bh   = blockIdx.y;   // 0..127
    const int b    = bh >> 4;
    const int h    = bh & 15;
    const float scale = 0.03125f;

    // load Q tile transposed: Qs[d][r]
    {
        const size_t baseQ = ((size_t)b * LL + (size_t)qt * 128) * DD + h * HDIM;
        for (int l = tid; l < 2048; l += 256) {
            int r  = l >> 4;
            int d4 = (l & 15) << 2;
            float4 v = *(const float4*)(Q + baseQ + (size_t)r * DD + d4);
            Qs[(d4 + 0) * 128 + r] = v.x;
            Qs[(d4 + 1) * 128 + r] = v.y;
            Qs[(d4 + 2) * 128 + r] = v.z;
            Qs[(d4 + 3) * 128 + r] = v.w;
        }
    }

    float acc2[8][4];
    #pragma unroll
    for (int i = 0; i < 8; i++)
        #pragma unroll
        for (int j = 0; j < 4; j++) acc2[i][j] = 0.0f;

    for (int kt = 0; kt < 8; kt++) {
        __syncthreads();  // prior GEMM2 done reading KVs(Vs)/Asm; Qs stores visible via next sync
        const size_t baseK = ((size_t)b * LL + (size_t)kt * 128) * DD + h * HDIM;
        // load K tile (scaled, transposed): KVs = Ks[d][r]
        for (int l = tid; l < 2048; l += 256) {
            int r  = l >> 4;
            int d4 = (l & 15) << 2;
            float4 v = *(const float4*)(Kg + baseK + (size_t)r * DD + d4);
            KVs[(d4 + 0) * 128 + r] = v.x * scale;
            KVs[(d4 + 1) * 128 + r] = v.y * scale;
            KVs[(d4 + 2) * 128 + r] = v.z * scale;
            KVs[(d4 + 3) * 128 + r] = v.w * scale;
        }
        __syncthreads();  // Ks (+Qs) ready

        // GEMM1: S[q][k] = Qs^T . Ks
        float acc[8][8];
        #pragma unroll
        for (int i = 0; i < 8; i++)
            #pragma unroll
            for (int j = 0; j < 8; j++) acc[i][j] = 0.0f;

        #pragma unroll 8
        for (int d = 0; d < 64; d++) {
            float ra[8], rb[8];
            float4 a0 = *(const float4*)(Qs + d * 128 + tRow * 8);
            float4 a1 = *(const float4*)(Qs + d * 128 + tRow * 8 + 4);
            ra[0]=a0.x; ra[1]=a0.y; ra[2]=a0.z; ra[3]=a0.w;
            ra[4]=a1.x; ra[5]=a1.y; ra[6]=a1.z; ra[7]=a1.w;
            float4 b0 = *(const float4*)(KVs + d * 128 + tCol * 8);
            float4 b1 = *(const float4*)(KVs + d * 128 + tCol * 8 + 4);
            rb[0]=b0.x; rb[1]=b0.y; rb[2]=b0.z; rb[3]=b0.w;
            rb[4]=b1.x; rb[5]=b1.y; rb[6]=b1.z; rb[7]=b1.w;
            #pragma unroll
            for (int i = 0; i < 8; i++)
                #pragma unroll
                for (int j = 0; j < 8; j++)
                    acc[i][j] = fmaf(ra[i], rb[j], acc[i][j]);
        }
        __syncthreads();  // everyone done reading Ks before V overwrites KVs

        // per-column 1/Z
        float zin[8];
        const float* zp = colsum + (size_t)bh * LL + kt * 128 + tCol * 8;
        #pragma unroll
        for (int j = 0; j < 8; j++) zin[j] = 1.0f / zp[j];

        // A = exp(S)/Z, stored transposed: Asm[k][q]
        #pragma unroll
        for (int j = 0; j < 8; j++)
            #pragma unroll
            for (int i = 0; i < 8; i++)
                Asm[(tCol * 8 + j) * AP + tRow * 8 + i] = __expf(acc[i][j]) * zin[j];

        // load V tile natural layout: Vs[r][d]
        for (int l = tid; l < 2048; l += 256) {
            int r  = l >> 4;
            int d4 = (l & 15) << 2;
            float4 v = *(const float4*)(Vg + baseK + (size_t)r * DD + d4);
            *(float4*)(KVs + r * 64 + d4) = v;
        }
        __syncthreads();  // Asm + Vs ready

        // GEMM2: out[q][d] += A[q][k] * V[k][d]
        #pragma unroll 8
        for (int k = 0; k < 128; k++) {
            float ra[8];
            float4 a0 = *(const float4*)(Asm + k * AP + tRow * 8);
            float4 a1 = *(const float4*)(Asm + k * AP + tRow * 8 + 4);
            ra[0]=a0.x; ra[1]=a0.y; ra[2]=a0.z; ra[3]=a0.w;
            ra[4]=a1.x; ra[5]=a1.y; ra[6]=a1.z; ra[7]=a1.w;
            float4 bv = *(const float4*)(KVs + k * 64 + tCol * 4);
            #pragma unroll
            for (int i = 0; i < 8; i++) {
                acc2[i][0] = fmaf(ra[i], bv.x, acc2[i][0]);
                acc2[i][1] = fmaf(ra[i], bv.y, acc2[i][1]);
                acc2[i][2] = fmaf(ra[i], bv.z, acc2[i][2]);
                acc2[i][3] = fmaf(ra[i], bv.w, acc2[i][3]);
            }
        }
    }

    // write out tile: O[b, q, h*64 + d]
    #pragma unroll
    for (int i = 0; i < 8; i++) {
        const size_t q = (size_t)qt * 128 + tRow * 8 + i;
        float4 o;
        o.x = acc2[i][0]; o.y = acc2[i][1]; o.z = acc2[i][2]; o.w = acc2[i][3];
        *(float4*)(O + ((size_t)b * LL + q) * DD + h * HDIM + tCol * 4) = o;
    }
}

// ---------------------------------------------------------------------------
// Launch
// ---------------------------------------------------------------------------
extern "C" void kernel_launch(void* const* d_in, const int* in_sizes, int n_in,
                              void* d_out, int out_size)
{
    (void)in_sizes; (void)n_in; (void)out_size;

    const float* x_q = (const float*)d_in[0];
    const float* x_k = (const float*)d_in[1];
    const float* x_v = (const float*)d_in[2];
    // d_in[3] = mask: unused (reference never applies it)
    const float* Wq  = (const float*)d_in[4];
    const float* bq  = (const float*)d_in[5];
    const float* Wk  = (const float*)d_in[6];
    const float* bk  = (const float*)d_in[7];
    const float* Wv  = (const float*)d_in[8];
    const float* bv  = (const float*)d_in[9];
    const float* Wo  = (const float*)d_in[10];
    const float* bo  = (const float*)d_in[11];

    float *pQ, *pK, *pV, *pA, *pZ;
    cudaGetSymbolAddress((void**)&pQ, g_Q);
    cudaGetSymbolAddress((void**)&pK, g_K);
    cudaGetSymbolAddress((void**)&pV, g_V);
    cudaGetSymbolAddress((void**)&pA, g_attn);
    cudaGetSymbolAddress((void**)&pZ, g_colsum);

    const dim3 gGemm(DD / 128, MTOT / 128);   // (8, 64)
    const dim3 tGemm(256);

    // Projections
    sgemm_bias_kernel<<<gGemm, tGemm>>>(x_q, Wq, bq, pQ, MTOT, DD, DD);
    sgemm_bias_kernel<<<gGemm, tGemm>>>(x_k, Wk, bk, pK, MTOT, DD, DD);
    sgemm_bias_kernel<<<gGemm, tGemm>>>(x_v, Wv, bv, pV, MTOT, DD, DD);

    // Column softmax sums
    const size_t smem1 = (8192 + 8192 + 2048) * sizeof(float);   // 73728
    cudaFuncSetAttribute(attn_colsum_kernel,
                         cudaFuncAttributeMaxDynamicSharedMemorySize, (int)smem1);
    attn_colsum_kernel<<<dim3(8, BB * HH), 256, smem1>>>(pQ, pK, pZ);

    // A @ V
    const size_t smem2 = (8192 + 8192 + 128 * 132) * sizeof(float);  // 133120
    cudaFuncSetAttribute(attn_av_kernel,
                         cudaFuncAttributeMaxDynamicSharedMemorySize, (int)smem2);
    attn_av_kernel<<<dim3(8, BB * HH), 256, smem2>>>(pQ, pK, pV, pZ, pA);

    // Output projection -> d_out
    sgemm_bias_kernel<<<gGemm, tGemm>>>(pA, Wo, bo, (float*)d_out, MTOT, DD, DD);
}

// round 7
// speedup vs baseline: 1.5586x; 1.5586x over previous
#include <cuda_runtime.h>
#include <cuda_bf16.h>
#include <cstdint>
#include <math.h>

// Problem constants
#define BB   8
#define LL   1024
#define DD   1024
#define HH   16
#define HDIM 64
#define MTOT (BB*LL)          // 8192 rows for the big GEMMs

// ---------------------------------------------------------------------------
// Scratch (device globals: no cudaMalloc allowed)
// ---------------------------------------------------------------------------
__device__ float g_Q[(size_t)MTOT * DD];         // 32 MB
__device__ float g_K[(size_t)MTOT * DD];         // 32 MB
__device__ float g_V[(size_t)MTOT * DD];         // 32 MB
__device__ float g_attn[(size_t)MTOT * DD];      // 32 MB
__device__ float g_colsum[(size_t)BB * HH * LL]; // 512 KB
// split-bf16 operand buffers (reused across GEMMs via stream ordering)
__device__ __nv_bfloat16 g_Ah[(size_t)MTOT * DD];   // 16 MB (activations hi)
__device__ __nv_bfloat16 g_Al[(size_t)MTOT * DD];   // 16 MB (activations lo)
__device__ uint32_t g_Wph[(size_t)(DD/2) * DD];     // 2 MB  (W k-pair packed, hi)
__device__ uint32_t g_Wpl[(size_t)(DD/2) * DD];     // 2 MB  (W k-pair packed, lo)

// ---------------------------------------------------------------------------
// Baseline (non-arch-specific) helpers: mma.sync + cp.async
// ---------------------------------------------------------------------------
__device__ __forceinline__ void mma16816(float c[4],
    uint32_t a0, uint32_t a1, uint32_t a2, uint32_t a3,
    uint32_t b0, uint32_t b1)
{
    asm volatile(
        "mma.sync.aligned.m16n8k16.row.col.f32.bf16.bf16.f32 "
        "{%0,%1,%2,%3}, {%4,%5,%6,%7}, {%8,%9}, {%0,%1,%2,%3};"
        : "+f"(c[0]), "+f"(c[1]), "+f"(c[2]), "+f"(c[3])
        : "r"(a0), "r"(a1), "r"(a2), "r"(a3), "r"(b0), "r"(b1));
}

__device__ __forceinline__ uint32_t smem_u32(const void* p) {
    uint32_t a;
    asm("{ .reg .u64 t; cvta.to.shared.u64 t, %1; cvt.u32.u64 %0, t; }"
        : "=r"(a) : "l"(p));
    return a;
}

#define CP_ASYNC16(dst_u32, src_ptr) \
    asm volatile("cp.async.cg.shared.global [%0], [%1], 16;" \
        :: "r"(dst_u32), "l"(src_ptr) : "memory")
#define CP_COMMIT() asm volatile("cp.async.commit_group;" ::: "memory")
#define CP_WAIT(n)  asm volatile("cp.async.wait_group %0;" :: "n"(n) : "memory")

// ---------------------------------------------------------------------------
// split fp32 -> (bf16 hi, bf16 lo); n4 = element_count/4
// ---------------------------------------------------------------------------
__global__ __launch_bounds__(256) void split_kernel(
    const float* __restrict__ x, __nv_bfloat16* __restrict__ h,
    __nv_bfloat16* __restrict__ l, int n4)
{
    int i = blockIdx.x * blockDim.x + threadIdx.x;
    if (i >= n4) return;
    float4 v = ((const float4*)x)[i];
    __nv_bfloat16 h0 = __float2bfloat16(v.x);
    __nv_bfloat16 h1 = __float2bfloat16(v.y);
    __nv_bfloat16 h2 = __float2bfloat16(v.z);
    __nv_bfloat16 h3 = __float2bfloat16(v.w);
    __nv_bfloat16 l0 = __float2bfloat16(v.x - __bfloat162float(h0));
    __nv_bfloat16 l1 = __float2bfloat16(v.y - __bfloat162float(h1));
    __nv_bfloat16 l2 = __float2bfloat16(v.z - __bfloat162float(h2));
    __nv_bfloat16 l3 = __float2bfloat16(v.w - __bfloat162float(h3));
    __nv_bfloat162* hp = (__nv_bfloat162*)h;
    __nv_bfloat162* lp = (__nv_bfloat162*)l;
    hp[2*i]   = __halves2bfloat162(h0, h1);
    hp[2*i+1] = __halves2bfloat162(h2, h3);
    lp[2*i]   = __halves2bfloat162(l0, l1);
    lp[2*i+1] = __halves2bfloat162(l2, l3);
}

// ---------------------------------------------------------------------------
// pack W [K=1024, N=1024] row-major fp32 -> k-pair bf16x2 layout:
// P[k2][n] = { bf16(W[2*k2][n]), bf16(W[2*k2+1][n]) }   hi and lo residual
// ---------------------------------------------------------------------------
__global__ __launch_bounds__(256) void pack_w_kernel(
    const float* __restrict__ W, uint32_t* __restrict__ Ph,
    uint32_t* __restrict__ Pl)
{
    int i = blockIdx.x * blockDim.x + threadIdx.x;   // over 512*1024
    if (i >= (DD/2) * DD) return;
    int k2 = i >> 10, n = i & (DD - 1);
    float w0 = W[(size_t)(2*k2)     * DD + n];
    float w1 = W[(size_t)(2*k2 + 1) * DD + n];
    __nv_bfloat16 h0 = __float2bfloat16(w0);
    __nv_bfloat16 h1 = __float2bfloat16(w1);
    __nv_bfloat16 l0 = __float2bfloat16(w0 - __bfloat162float(h0));
    __nv_bfloat16 l1 = __float2bfloat16(w1 - __bfloat162float(h1));
    __nv_bfloat162 ph = __halves2bfloat162(h0, h1);   // .x = low half = k even
    __nv_bfloat162 pl = __halves2bfloat162(l0, l1);
    Ph[i] = *(uint32_t*)&ph;
    Pl[i] = *(uint32_t*)&pl;
}

// ---------------------------------------------------------------------------
// Split-bf16 HMMA GEMM: C[M,N] = (Ah+Al)@(Wh+Wl) + bias, dropping Al*Wl.
// A: [M,K] bf16 row-major (hi/lo). W packed: P[k2][n] bf16x2 (hi/lo).
// CTA tile 128x128, BK=64, 256 threads = 8 warps (2 m x 4 n), warp 64x32.
// Double-buffered smem with cp.async.
// SMEM per buffer: Ah[128][72]b16 18432 + Al 18432 + Bh[32][132]u32 16896
//                  + Bl 16896 = 70656 B; x2 = 141312 B.
// ---------------------------------------------------------------------------
#define SM_AH   0
#define SM_AL   18432
#define SM_BH   36864
#define SM_BL   53760
#define SM_BUF  70656
#define GEMM_SMEM (2 * SM_BUF)

__device__ __forceinline__ void gemm_load_tiles(
    char* sm, uint32_t smem_base, int buf, int tid, int m0, int n0, int kt,
    const __nv_bfloat16* __restrict__ Ah, const __nv_bfloat16* __restrict__ Al,
    const uint32_t* __restrict__ Bh, const uint32_t* __restrict__ Bl)
{
    const uint32_t sb = smem_base + buf * SM_BUF;
    #pragma unroll
    for (int p = 0; p < 4; p++) {
        const int idx = tid + p * 256;          // 0..1023
        const int r = idx >> 3, c = idx & 7;    // row 0..127, col-chunk 0..7
        const size_t g = (size_t)(m0 + r) * DD + kt * 64 + c * 8;
        const uint32_t d = r * 144 + c * 16;
        CP_ASYNC16(sb + SM_AH + d, Ah + g);
        CP_ASYNC16(sb + SM_AL + d, Al + g);
    }
    #pragma unroll
    for (int p = 0; p < 4; p++) {
        const int idx = tid + p * 256;
        const int r = idx >> 5, c = idx & 31;   // k2-row 0..31, col-chunk 0..31
        const size_t g = (size_t)(kt * 32 + r) * DD + n0 + c * 4;
        const uint32_t d = r * 528 + c * 16;
        CP_ASYNC16(sb + SM_BH + d, Bh + g);
        CP_ASYNC16(sb + SM_BL + d, Bl + g);
    }
}

__global__ __launch_bounds__(256, 1) void tc_gemm_split_kernel(
    const __nv_bfloat16* __restrict__ Ah, const __nv_bfloat16* __restrict__ Al,
    const uint32_t* __restrict__ Bh, const uint32_t* __restrict__ Bl,
    const float* __restrict__ bias, float* __restrict__ C)
{
    extern __shared__ char sm[];
    const uint32_t smem_base = smem_u32(sm);
    const int tid = threadIdx.x;
    const int wid = tid >> 5;
    const int lane = tid & 31;
    const int g = lane >> 2;       // group id 0..7
    const int t = lane & 3;        // thread in group
    const int wm = wid >> 2;       // 0..1  (64-row slab)
    const int wn = wid & 3;        // 0..3  (32-col slab)
    const int n0 = blockIdx.x * 128;
    const int m0 = blockIdx.y * 128;

    float c[4][4][4];
    #pragma unroll
    for (int i = 0; i < 4; i++)
        #pragma unroll
        for (int j = 0; j < 4; j++)
            #pragma unroll
            for (int q = 0; q < 4; q++) c[i][j][q] = 0.0f;

    gemm_load_tiles(sm, smem_base, 0, tid, m0, n0, 0, Ah, Al, Bh, Bl);
    CP_COMMIT();

    for (int kt = 0; kt < 16; kt++) {
        const int buf = kt & 1;
        if (kt < 15) {
            gemm_load_tiles(sm, smem_base, buf ^ 1, tid, m0, n0, kt + 1, Ah, Al, Bh, Bl);
            CP_COMMIT();
            CP_WAIT(1);
        } else {
            CP_WAIT(0);
        }
        __syncthreads();

        const char* Abh = sm + buf * SM_BUF + SM_AH;
        const char* Abl = sm + buf * SM_BUF + SM_AL;
        const char* Bbh = sm + buf * SM_BUF + SM_BH;
        const char* Bbl = sm + buf * SM_BUF + SM_BL;

        #pragma unroll
        for (int ks = 0; ks < 4; ks++) {
            uint32_t aH[4][4], aL[4][4], bH[4][2], bL[4][2];
            #pragma unroll
            for (int i = 0; i < 4; i++) {
                const int off = (wm * 64 + i * 16 + g) * 144 + ks * 32 + t * 4;
                aH[i][0] = *(const uint32_t*)(Abh + off);
                aH[i][1] = *(const uint32_t*)(Abh + off + 8 * 144);
                aH[i][2] = *(const uint32_t*)(Abh + off + 16);
                aH[i][3] = *(const uint32_t*)(Abh + off + 8 * 144 + 16);
                aL[i][0] = *(const uint32_t*)(Abl + off);
                aL[i][1] = *(const uint32_t*)(Abl + off + 8 * 144);
                aL[i][2] = *(const uint32_t*)(Abl + off + 16);
                aL[i][3] = *(const uint32_t*)(Abl + off + 8 * 144 + 16);
            }
            #pragma unroll
            for (int j = 0; j < 4; j++) {
                const int off = (ks * 8 + t) * 528 + (wn * 32 + j * 8 + g) * 4;
                bH[j][0] = *(const uint32_t*)(Bbh + off);
                bH[j][1] = *(const uint32_t*)(Bbh + off + 4 * 528);
                bL[j][0] = *(const uint32_t*)(Bbl + off);
                bL[j][1] = *(const uint32_t*)(Bbl + off + 4 * 528);
            }
            #pragma unroll
            for (int i = 0; i < 4; i++)
                #pragma unroll
                for (int j = 0; j < 4; j++)
                    mma16816(c[i][j], aH[i][0], aH[i][1], aH[i][2], aH[i][3],
                             bH[j][0], bH[j][1]);
            #pragma unroll
            for (int i = 0; i < 4; i++)
                #pragma unroll
                for (int j = 0; j < 4; j++)
                    mma16816(c[i][j], aH[i][0], aH[i][1], aH[i][2], aH[i][3],
                             bL[j][0], bL[j][1]);
            #pragma unroll
            for (int i = 0; i < 4; i++)
                #pragma unroll
                for (int j = 0; j < 4; j++)
                    mma16816(c[i][j], aL[i][0], aL[i][1], aL[i][2], aL[i][3],
                             bH[j][0], bH[j][1]);
        }
        __syncthreads();
    }

    // Epilogue: add bias, store fp32
    #pragma unroll
    for (int j = 0; j < 4; j++) {
        const int col = n0 + wn * 32 + j * 8 + 2 * t;
        const float2 bv = *(const float2*)(bias + col);
        #pragma unroll
        for (int i = 0; i < 4; i++) {
            const int row = m0 + wm * 64 + i * 16 + g;
            float* o = C + (size_t)row * DD + col;
            float2 v0 = make_float2(c[i][j][0] + bv.x, c[i][j][1] + bv.y);
            float2 v1 = make_float2(c[i][j][2] + bv.x, c[i][j][3] + bv.y);
            *(float2*)o = v0;
            *(float2*)(o + 8 * DD) = v1;
        }
    }
}

// ---------------------------------------------------------------------------
// Column-softmax stats: Z[bh, k] = sum_q exp(Q_h[q] . K_h[k] / 32)  (unchanged)
// ---------------------------------------------------------------------------
__global__ __launch_bounds__(256, 1) void attn_colsum_kernel(
    const float* __restrict__ Q, const float* __restrict__ Kg,
    float* __restrict__ colsum)
{
    extern __shared__ float smf[];
    float* Ks  = smf;            // [d][k]  64*128
    float* Qs  = smf + 8192;     // [d][q]  64*128
    float* red = smf + 16384;    // [16][128]

    const int tid  = threadIdx.x;
    const int tRow = tid >> 4;
    const int tCol = tid & 15;
    const int kt   = blockIdx.x;
    const int bh   = blockIdx.y;
    const int b    = bh >> 4;
    const int h    = bh & 15;
    const float scale = 0.03125f;

    {
        const size_t baseK = ((size_t)b * LL + (size_t)kt * 128) * DD + h * HDIM;
        for (int l = tid; l < 2048; l += 256) {
            int r  = l >> 4;
            int d4 = (l & 15) << 2;
            float4 v = *(const float4*)(Kg + baseK + (size_t)r * DD + d4);
            Ks[(d4 + 0) * 128 + r] = v.x * scale;
            Ks[(d4 + 1) * 128 + r] = v.y * scale;
            Ks[(d4 + 2) * 128 + r] = v.z * scale;
            Ks[(d4 + 3) * 128 + r] = v.w * scale;
        }
    }

    float esum[8];
    #pragma unroll
    for (int j = 0; j < 8; j++) esum[j] = 0.0f;

    for (int qt = 0; qt < 8; qt++) {
        __syncthreads();
        const size_t baseQ = ((size_t)b * LL + (size_t)qt * 128) * DD + h * HDIM;
        for (int l = tid; l < 2048; l += 256) {
            int r  = l >> 4;
            int d4 = (l & 15) << 2;
            float4 v = *(const float4*)(Q + baseQ + (size_t)r * DD + d4);
            Qs[(d4 + 0) * 128 + r] = v.x;
            Qs[(d4 + 1) * 128 + r] = v.y;
            Qs[(d4 + 2) * 128 + r] = v.z;
            Qs[(d4 + 3) * 128 + r] = v.w;
        }
        __syncthreads();

        float acc[8][8];
        #pragma unroll
        for (int i = 0; i < 8; i++)
            #pragma unroll
            for (int j = 0; j < 8; j++) acc[i][j] = 0.0f;

        #pragma unroll 8
        for (int d = 0; d < 64; d++) {
            float ra[8], rb[8];
            float4 a0 = *(const float4*)(Qs + d * 128 + tRow * 8);
            float4 a1 = *(const float4*)(Qs + d * 128 + tRow * 8 + 4);
            ra[0]=a0.x; ra[1]=a0.y; ra[2]=a0.z; ra[3]=a0.w;
            ra[4]=a1.x; ra[5]=a1.y; ra[6]=a1.z; ra[7]=a1.w;
            float4 b0 = *(const float4*)(Ks + d * 128 + tCol * 8);
            float4 b1 = *(const float4*)(Ks + d * 128 + tCol * 8 + 4);
            rb[0]=b0.x; rb[1]=b0.y; rb[2]=b0.z; rb[3]=b0.w;
            rb[4]=b1.x; rb[5]=b1.y; rb[6]=b1.z; rb[7]=b1.w;
            #pragma unroll
            for (int i = 0; i < 8; i++)
                #pragma unroll
                for (int j = 0; j < 8; j++)
                    acc[i][j] = fmaf(ra[i], rb[j], acc[i][j]);
        }
        #pragma unroll
        for (int i = 0; i < 8; i++)
            #pragma unroll
            for (int j = 0; j < 8; j++)
                esum[j] += __expf(acc[i][j]);
    }

    __syncthreads();
    #pragma unroll
    for (int j = 0; j < 8; j++)
        red[tRow * 128 + tCol * 8 + j] = esum[j];
    __syncthreads();
    if (tid < 128) {
        float s = 0.0f;
        #pragma unroll
        for (int r = 0; r < 16; r++) s += red[r * 128 + tid];
        colsum[(size_t)bh * LL + kt * 128 + tid] = s;
    }
}

// ---------------------------------------------------------------------------
// AV kernel (unchanged)
// ---------------------------------------------------------------------------
__global__ __launch_bounds__(256, 1) void attn_av_kernel(
    const float* __restrict__ Q, const float* __restrict__ Kg,
    const float* __restrict__ Vg, const float* __restrict__ colsum,
    float* __restrict__ O)
{
    extern __shared__ float smf[];
    float* Qs  = smf;
    float* KVs = smf + 8192;
    float* Asm = smf + 16384;
    const int AP = 132;

    const int tid  = threadIdx.x;
    const int tRow = tid >> 4;
    const int tCol = tid & 15;
    const int qt   = blockIdx.x;
    const int bh   = blockIdx.y;
    const int b    = bh >> 4;
    const int h    = bh & 15;
    const float scale = 0.03125f;

    {
        const size_t baseQ = ((size_t)b * LL + (size_t)qt * 128) * DD + h * HDIM;
        for (int l = tid; l < 2048; l += 256) {
            int r  = l >> 4;
            int d4 = (l & 15) << 2;
            float4 v = *(const float4*)(Q + baseQ + (size_t)r * DD + d4);
            Qs[(d4 + 0) * 128 + r] = v.x;
            Qs[(d4 + 1) * 128 + r] = v.y;
            Qs[(d4 + 2) * 128 + r] = v.z;
            Qs[(d4 + 3) * 128 + r] = v.w;
        }
    }

    float acc2[8][4];
    #pragma unroll
    for (int i = 0; i < 8; i++)
        #pragma unroll
        for (int j = 0; j < 4; j++) acc2[i][j] = 0.0f;

    for (int kt = 0; kt < 8; kt++) {
        __syncthreads();
        const size_t baseK = ((size_t)b * LL + (size_t)kt * 128) * DD + h * HDIM;
        for (int l = tid; l < 2048; l += 256) {
            int r  = l >> 4;
            int d4 = (l & 15) << 2;
            float4 v = *(const float4*)(Kg + baseK + (size_t)r * DD + d4);
            KVs[(d4 + 0) * 128 + r] = v.x * scale;
            KVs[(d4 + 1) * 128 + r] = v.y * scale;
            KVs[(d4 + 2) * 128 + r] = v.z * scale;
            KVs[(d4 + 3) * 128 + r] = v.w * scale;
        }
        __syncthreads();

        float acc[8][8];
        #pragma unroll
        for (int i = 0; i < 8; i++)
            #pragma unroll
            for (int j = 0; j < 8; j++) acc[i][j] = 0.0f;

        #pragma unroll 8
        for (int d = 0; d < 64; d++) {
            float ra[8], rb[8];
            float4 a0 = *(const float4*)(Qs + d * 128 + tRow * 8);
            float4 a1 = *(const float4*)(Qs + d * 128 + tRow * 8 + 4);
            ra[0]=a0.x; ra[1]=a0.y; ra[2]=a0.z; ra[3]=a0.w;
            ra[4]=a1.x; ra[5]=a1.y; ra[6]=a1.z; ra[7]=a1.w;
            float4 b0 = *(const float4*)(KVs + d * 128 + tCol * 8);
            float4 b1 = *(const float4*)(KVs + d * 128 + tCol * 8 + 4);
            rb[0]=b0.x; rb[1]=b0.y; rb[2]=b0.z; rb[3]=b0.w;
            rb[4]=b1.x; rb[5]=b1.y; rb[6]=b1.z; rb[7]=b1.w;
            #pragma unroll
            for (int i = 0; i < 8; i++)
                #pragma unroll
                for (int j = 0; j < 8; j++)
                    acc[i][j] = fmaf(ra[i], rb[j], acc[i][j]);
        }
        __syncthreads();

        float zin[8];
        const float* zp = colsum + (size_t)bh * LL + kt * 128 + tCol * 8;
        #pragma unroll
        for (int j = 0; j < 8; j++) zin[j] = 1.0f / zp[j];

        #pragma unroll
        for (int j = 0; j < 8; j++)
            #pragma unroll
            for (int i = 0; i < 8; i++)
                Asm[(tCol * 8 + j) * AP + tRow * 8 + i] = __expf(acc[i][j]) * zin[j];

        for (int l = tid; l < 2048; l += 256) {
            int r  = l >> 4;
            int d4 = (l & 15) << 2;
            float4 v = *(const float4*)(Vg + baseK + (size_t)r * DD + d4);
            *(float4*)(KVs + r * 64 + d4) = v;
        }
        __syncthreads();

        #pragma unroll 8
        for (int k = 0; k < 128; k++) {
            float ra[8];
            float4 a0 = *(const float4*)(Asm + k * AP + tRow * 8);
            float4 a1 = *(const float4*)(Asm + k * AP + tRow * 8 + 4);
            ra[0]=a0.x; ra[1]=a0.y; ra[2]=a0.z; ra[3]=a0.w;
            ra[4]=a1.x; ra[5]=a1.y; ra[6]=a1.z; ra[7]=a1.w;
            float4 bv = *(const float4*)(KVs + k * 64 + tCol * 4);
            #pragma unroll
            for (int i = 0; i < 8; i++) {
                acc2[i][0] = fmaf(ra[i], bv.x, acc2[i][0]);
                acc2[i][1] = fmaf(ra[i], bv.y, acc2[i][1]);
                acc2[i][2] = fmaf(ra[i], bv.z, acc2[i][2]);
                acc2[i][3] = fmaf(ra[i], bv.w, acc2[i][3]);
            }
        }
    }

    #pragma unroll
    for (int i = 0; i < 8; i++) {
        const size_t q = (size_t)qt * 128 + tRow * 8 + i;
        float4 o;
        o.x = acc2[i][0]; o.y = acc2[i][1]; o.z = acc2[i][2]; o.w = acc2[i][3];
        *(float4*)(O + ((size_t)b * LL + q) * DD + h * HDIM + tCol * 4) = o;
    }
}

// ---------------------------------------------------------------------------
// Launch
// ---------------------------------------------------------------------------
extern "C" void kernel_launch(void* const* d_in, const int* in_sizes, int n_in,
                              void* d_out, int out_size)
{
    (void)in_sizes; (void)n_in; (void)out_size;

    const float* x_q = (const float*)d_in[0];
    const float* x_k = (const float*)d_in[1];
    const float* x_v = (const float*)d_in[2];
    // d_in[3] = mask: unused (reference never applies it)
    const float* Wq  = (const float*)d_in[4];
    const float* bq  = (const float*)d_in[5];
    const float* Wk  = (const float*)d_in[6];
    const float* bk  = (const float*)d_in[7];
    const float* Wv  = (const float*)d_in[8];
    const float* bv  = (const float*)d_in[9];
    const float* Wo  = (const float*)d_in[10];
    const float* bo  = (const float*)d_in[11];

    float *pQ, *pK, *pV, *pA, *pZ;
    __nv_bfloat16 *pAh, *pAl;
    uint32_t *pWh, *pWl;
    cudaGetSymbolAddress((void**)&pQ, g_Q);
    cudaGetSymbolAddress((void**)&pK, g_K);
    cudaGetSymbolAddress((void**)&pV, g_V);
    cudaGetSymbolAddress((void**)&pA, g_attn);
    cudaGetSymbolAddress((void**)&pZ, g_colsum);
    cudaGetSymbolAddress((void**)&pAh, g_Ah);
    cudaGetSymbolAddress((void**)&pAl, g_Al);
    cudaGetSymbolAddress((void**)&pWh, g_Wph);
    cudaGetSymbolAddress((void**)&pWl, g_Wpl);

    cudaFuncSetAttribute(tc_gemm_split_kernel,
                         cudaFuncAttributeMaxDynamicSharedMemorySize, GEMM_SMEM);

    const int n4 = MTOT * DD / 4;
    const dim3 gSplit((n4 + 255) / 256), tSplit(256);
    const int npack = (DD / 2) * DD;
    const dim3 gPack((npack + 255) / 256);
    const dim3 gGemm(DD / 128, MTOT / 128);   // (8, 64)

    // Q projection
    split_kernel<<<gSplit, tSplit>>>(x_q, pAh, pAl, n4);
    pack_w_kernel<<<gPack, tSplit>>>(Wq, pWh, pWl);
    tc_gemm_split_kernel<<<gGemm, 256, GEMM_SMEM>>>(pAh, pAl, pWh, pWl, bq, pQ);
    // K projection
    split_kernel<<<gSplit, tSplit>>>(x_k, pAh, pAl, n4);
    pack_w_kernel<<<gPack, tSplit>>>(Wk, pWh, pWl);
    tc_gemm_split_kernel<<<gGemm, 256, GEMM_SMEM>>>(pAh, pAl, pWh, pWl, bk, pK);
    // V projection
    split_kernel<<<gSplit, tSplit>>>(x_v, pAh, pAl, n4);
    pack_w_kernel<<<gPack, tSplit>>>(Wv, pWh, pWl);
    tc_gemm_split_kernel<<<gGemm, 256, GEMM_SMEM>>>(pAh, pAl, pWh, pWl, bv, pV);

    // Attention (fp32, unchanged)
    const size_t smem1 = (8192 + 8192 + 2048) * sizeof(float);
    cudaFuncSetAttribute(attn_colsum_kernel,
                         cudaFuncAttributeMaxDynamicSharedMemorySize, (int)smem1);
    attn_colsum_kernel<<<dim3(8, BB * HH), 256, smem1>>>(pQ, pK, pZ);

    const size_t smem2 = (8192 + 8192 + 128 * 132) * sizeof(float);
    cudaFuncSetAttribute(attn_av_kernel,
                         cudaFuncAttributeMaxDynamicSharedMemorySize, (int)smem2);
    attn_av_kernel<<<dim3(8, BB * HH), 256, smem2>>>(pQ, pK, pV, pZ, pA);

    // Output projection -> d_out
    split_kernel<<<gSplit, tSplit>>>(pA, pAh, pAl, n4);
    pack_w_kernel<<<gPack, tSplit>>>(Wo, pWh, pWl);
    tc_gemm_split_kernel<<<gGemm, 256, GEMM_SMEM>>>(pAh, pAl, pWh, pWl, bo, (float*)d_out);
}

// round 8
// speedup vs baseline: 2.7578x; 1.7694x over previous
#include <cuda_runtime.h>
#include <cuda_bf16.h>
#include <cstdint>
#include <math.h>

// Problem constants
#define BB   8
#define LL   1024
#define DD   1024
#define HH   16
#define HDIM 64
#define MTOT (BB*LL)

// ---------------------------------------------------------------------------
// Scratch (device globals: no cudaMalloc allowed)
// ---------------------------------------------------------------------------
__device__ float g_Q[(size_t)MTOT * DD];         // 32 MB (fp32 proj out)
__device__ float g_K[(size_t)MTOT * DD];         // 32 MB
__device__ float g_V[(size_t)MTOT * DD];         // 32 MB
__device__ float g_attn[(size_t)MTOT * DD];      // 32 MB
__device__ float g_colsum[(size_t)BB * HH * LL]; // 512 KB
__device__ __nv_bfloat16 g_Ah[(size_t)MTOT * DD];   // 16 MB
__device__ __nv_bfloat16 g_Al[(size_t)MTOT * DD];   // 16 MB
__device__ uint32_t g_Wph[(size_t)(DD/2) * DD];     // 2 MB
__device__ uint32_t g_Wpl[(size_t)(DD/2) * DD];     // 2 MB
// attention bf16 operands
__device__ __nv_bfloat16 g_Qh[(size_t)MTOT * DD];   // 16 MB (scaled by 1/32)
__device__ __nv_bfloat16 g_Ql[(size_t)MTOT * DD];   // 16 MB
__device__ __nv_bfloat16 g_Kh[(size_t)MTOT * DD];   // 16 MB
__device__ __nv_bfloat16 g_Kl[(size_t)MTOT * DD];   // 16 MB
// V/Z packed k-pair layout per (bh): [bh][k2=512][d=64] u32
__device__ uint32_t g_Vph[(size_t)BB * HH * (LL/2) * HDIM];  // 16 MB
__device__ uint32_t g_Vpl[(size_t)BB * HH * (LL/2) * HDIM];  // 16 MB

// ---------------------------------------------------------------------------
// Helpers: mma.sync + cp.async (baseline ISA, works on compute_103)
// ---------------------------------------------------------------------------
__device__ __forceinline__ void mma16816(float c[4],
    uint32_t a0, uint32_t a1, uint32_t a2, uint32_t a3,
    uint32_t b0, uint32_t b1)
{
    asm volatile(
        "mma.sync.aligned.m16n8k16.row.col.f32.bf16.bf16.f32 "
        "{%0,%1,%2,%3}, {%4,%5,%6,%7}, {%8,%9}, {%0,%1,%2,%3};"
        : "+f"(c[0]), "+f"(c[1]), "+f"(c[2]), "+f"(c[3])
        : "r"(a0), "r"(a1), "r"(a2), "r"(a3), "r"(b0), "r"(b1));
}

__device__ __forceinline__ uint32_t smem_u32(const void* p) {
    uint32_t a;
    asm("{ .reg .u64 t; cvta.to.shared.u64 t, %1; cvt.u32.u64 %0, t; }"
        : "=r"(a) : "l"(p));
    return a;
}

#define CP_ASYNC16(dst_u32, src_ptr) \
    asm volatile("cp.async.cg.shared.global [%0], [%1], 16;" \
        :: "r"(dst_u32), "l"(src_ptr) : "memory")
#define CP_COMMIT() asm volatile("cp.async.commit_group;" ::: "memory")
#define CP_WAIT(n)  asm volatile("cp.async.wait_group %0;" :: "n"(n) : "memory")

__device__ __forceinline__ uint32_t pack_bf2(float x, float y) {
    __nv_bfloat162 p = __floats2bfloat162_rn(x, y);  // .x = x (low)
    return *(uint32_t*)&p;
}

// ---------------------------------------------------------------------------
// split fp32 -> (bf16 hi, bf16 lo) with optional pre-scale
// ---------------------------------------------------------------------------
__global__ __launch_bounds__(256) void split_kernel(
    const float* __restrict__ x, __nv_bfloat16* __restrict__ h,
    __nv_bfloat16* __restrict__ l, int n4, float s)
{
    int i = blockIdx.x * blockDim.x + threadIdx.x;
    if (i >= n4) return;
    float4 v = ((const float4*)x)[i];
    v.x *= s; v.y *= s; v.z *= s; v.w *= s;
    __nv_bfloat16 h0 = __float2bfloat16(v.x);
    __nv_bfloat16 h1 = __float2bfloat16(v.y);
    __nv_bfloat16 h2 = __float2bfloat16(v.z);
    __nv_bfloat16 h3 = __float2bfloat16(v.w);
    __nv_bfloat16 l0 = __float2bfloat16(v.x - __bfloat162float(h0));
    __nv_bfloat16 l1 = __float2bfloat16(v.y - __bfloat162float(h1));
    __nv_bfloat16 l2 = __float2bfloat16(v.z - __bfloat162float(h2));
    __nv_bfloat16 l3 = __float2bfloat16(v.w - __bfloat162float(h3));
    __nv_bfloat162* hp = (__nv_bfloat162*)h;
    __nv_bfloat162* lp = (__nv_bfloat162*)l;
    hp[2*i]   = __halves2bfloat162(h0, h1);
    hp[2*i+1] = __halves2bfloat162(h2, h3);
    lp[2*i]   = __halves2bfloat162(l0, l1);
    lp[2*i+1] = __halves2bfloat162(l2, l3);
}

// ---------------------------------------------------------------------------
// pack W [K,N] fp32 -> k-pair bf16x2 [k2][n] (hi/lo)
// ---------------------------------------------------------------------------
__global__ __launch_bounds__(256) void pack_w_kernel(
    const float* __restrict__ W, uint32_t* __restrict__ Ph,
    uint32_t* __restrict__ Pl)
{
    int i = blockIdx.x * blockDim.x + threadIdx.x;
    if (i >= (DD/2) * DD) return;
    int k2 = i >> 10, n = i & (DD - 1);
    float w0 = W[(size_t)(2*k2)     * DD + n];
    float w1 = W[(size_t)(2*k2 + 1) * DD + n];
    __nv_bfloat16 h0 = __float2bfloat16(w0);
    __nv_bfloat16 h1 = __float2bfloat16(w1);
    Ph[i] = pack_bf2(w0, w1);
    Pl[i] = pack_bf2(w0 - __bfloat162float(h0), w1 - __bfloat162float(h1));
}

// ---------------------------------------------------------------------------
// build Vp: Vp[bh][k2][d] = bf16x2{ V[2k2,d]/Z[2k2], V[2k2+1,d]/Z[2k2+1] }
// ---------------------------------------------------------------------------
__global__ __launch_bounds__(256) void build_vp_kernel(
    const float* __restrict__ V, const float* __restrict__ Z,
    uint32_t* __restrict__ Ph, uint32_t* __restrict__ Pl)
{
    int i = blockIdx.x * blockDim.x + threadIdx.x;
    const int total = BB * HH * (LL/2) * HDIM;
    if (i >= total) return;
    int bh = i >> 15;            // /(512*64)
    int r  = (i >> 6) & 511;     // k2
    int d  = i & 63;
    int b = bh >> 4, h = bh & 15;
    float z0 = 1.0f / Z[(size_t)bh * LL + 2*r];
    float z1 = 1.0f / Z[(size_t)bh * LL + 2*r + 1];
    float v0 = V[((size_t)b * LL + 2*r)     * DD + h * HDIM + d] * z0;
    float v1 = V[((size_t)b * LL + 2*r + 1) * DD + h * HDIM + d] * z1;
    __nv_bfloat16 h0 = __float2bfloat16(v0);
    __nv_bfloat16 h1 = __float2bfloat16(v1);
    Ph[i] = pack_bf2(v0, v1);
    Pl[i] = pack_bf2(v0 - __bfloat162float(h0), v1 - __bfloat162float(h1));
}

// ---------------------------------------------------------------------------
// Split-bf16 HMMA projection GEMM (unchanged from R6, passing)
// ---------------------------------------------------------------------------
#define SM_AH   0
#define SM_AL   18432
#define SM_BH   36864
#define SM_BL   53760
#define SM_BUF  70656
#define GEMM_SMEM (2 * SM_BUF)

__device__ __forceinline__ void gemm_load_tiles(
    char* sm, uint32_t smem_base, int buf, int tid, int m0, int n0, int kt,
    const __nv_bfloat16* __restrict__ Ah, const __nv_bfloat16* __restrict__ Al,
    const uint32_t* __restrict__ Bh, const uint32_t* __restrict__ Bl)
{
    const uint32_t sb = smem_base + buf * SM_BUF;
    #pragma unroll
    for (int p = 0; p < 4; p++) {
        const int idx = tid + p * 256;
        const int r = idx >> 3, c = idx & 7;
        const size_t g = (size_t)(m0 + r) * DD + kt * 64 + c * 8;
        const uint32_t d = r * 144 + c * 16;
        CP_ASYNC16(sb + SM_AH + d, Ah + g);
        CP_ASYNC16(sb + SM_AL + d, Al + g);
    }
    #pragma unroll
    for (int p = 0; p < 4; p++) {
        const int idx = tid + p * 256;
        const int r = idx >> 5, c = idx & 31;
        const size_t g = (size_t)(kt * 32 + r) * DD + n0 + c * 4;
        const uint32_t d = r * 528 + c * 16;
        CP_ASYNC16(sb + SM_BH + d, Bh + g);
        CP_ASYNC16(sb + SM_BL + d, Bl + g);
    }
}

__global__ __launch_bounds__(256, 1) void tc_gemm_split_kernel(
    const __nv_bfloat16* __restrict__ Ah, const __nv_bfloat16* __restrict__ Al,
    const uint32_t* __restrict__ Bh, const uint32_t* __restrict__ Bl,
    const float* __restrict__ bias, float* __restrict__ C)
{
    extern __shared__ char sm[];
    const uint32_t smem_base = smem_u32(sm);
    const int tid = threadIdx.x;
    const int wid = tid >> 5;
    const int lane = tid & 31;
    const int g = lane >> 2;
    const int t = lane & 3;
    const int wm = wid >> 2;
    const int wn = wid & 3;
    const int n0 = blockIdx.x * 128;
    const int m0 = blockIdx.y * 128;

    float c[4][4][4];
    #pragma unroll
    for (int i = 0; i < 4; i++)
        #pragma unroll
        for (int j = 0; j < 4; j++)
            #pragma unroll
            for (int q = 0; q < 4; q++) c[i][j][q] = 0.0f;

    gemm_load_tiles(sm, smem_base, 0, tid, m0, n0, 0, Ah, Al, Bh, Bl);
    CP_COMMIT();

    for (int kt = 0; kt < 16; kt++) {
        const int buf = kt & 1;
        if (kt < 15) {
            gemm_load_tiles(sm, smem_base, buf ^ 1, tid, m0, n0, kt + 1, Ah, Al, Bh, Bl);
            CP_COMMIT();
            CP_WAIT(1);
        } else {
            CP_WAIT(0);
        }
        __syncthreads();

        const char* Abh = sm + buf * SM_BUF + SM_AH;
        const char* Abl = sm + buf * SM_BUF + SM_AL;
        const char* Bbh = sm + buf * SM_BUF + SM_BH;
        const char* Bbl = sm + buf * SM_BUF + SM_BL;

        #pragma unroll
        for (int ks = 0; ks < 4; ks++) {
            uint32_t aH[4][4], aL[4][4], bH[4][2], bL[4][2];
            #pragma unroll
            for (int i = 0; i < 4; i++) {
                const int off = (wm * 64 + i * 16 + g) * 144 + ks * 32 + t * 4;
                aH[i][0] = *(const uint32_t*)(Abh + off);
                aH[i][1] = *(const uint32_t*)(Abh + off + 8 * 144);
                aH[i][2] = *(const uint32_t*)(Abh + off + 16);
                aH[i][3] = *(const uint32_t*)(Abh + off + 8 * 144 + 16);
                aL[i][0] = *(const uint32_t*)(Abl + off);
                aL[i][1] = *(const uint32_t*)(Abl + off + 8 * 144);
                aL[i][2] = *(const uint32_t*)(Abl + off + 16);
                aL[i][3] = *(const uint32_t*)(Abl + off + 8 * 144 + 16);
            }
            #pragma unroll
            for (int j = 0; j < 4; j++) {
                const int off = (ks * 8 + t) * 528 + (wn * 32 + j * 8 + g) * 4;
                bH[j][0] = *(const uint32_t*)(Bbh + off);
                bH[j][1] = *(const uint32_t*)(Bbh + off + 4 * 528);
                bL[j][0] = *(const uint32_t*)(Bbl + off);
                bL[j][1] = *(const uint32_t*)(Bbl + off + 4 * 528);
            }
            #pragma unroll
            for (int i = 0; i < 4; i++)
                #pragma unroll
                for (int j = 0; j < 4; j++)
                    mma16816(c[i][j], aH[i][0], aH[i][1], aH[i][2], aH[i][3],
                             bH[j][0], bH[j][1]);
            #pragma unroll
            for (int i = 0; i < 4; i++)
                #pragma unroll
                for (int j = 0; j < 4; j++)
                    mma16816(c[i][j], aH[i][0], aH[i][1], aH[i][2], aH[i][3],
                             bL[j][0], bL[j][1]);
            #pragma unroll
            for (int i = 0; i < 4; i++)
                #pragma unroll
                for (int j = 0; j < 4; j++)
                    mma16816(c[i][j], aL[i][0], aL[i][1], aL[i][2], aL[i][3],
                             bH[j][0], bH[j][1]);
        }
        __syncthreads();
    }

    #pragma unroll
    for (int j = 0; j < 4; j++) {
        const int col = n0 + wn * 32 + j * 8 + 2 * t;
        const float2 bv = *(const float2*)(bias + col);
        #pragma unroll
        for (int i = 0; i < 4; i++) {
            const int row = m0 + wm * 64 + i * 16 + g;
            float* o = C + (size_t)row * DD + col;
            *(float2*)o = make_float2(c[i][j][0] + bv.x, c[i][j][1] + bv.y);
            *(float2*)(o + 8 * DD) = make_float2(c[i][j][2] + bv.x, c[i][j][3] + bv.y);
        }
    }
}

// ---------------------------------------------------------------------------
// HMMA colsum: Z[bh,k] = sum_q exp(S_qk). Grid (kt=8, bh=128), 256 thr.
// SMEM: KH 18432 | KL 18432 | QH 18432 | QL 18432 | RED 1024 = 74752 B
// ---------------------------------------------------------------------------
#define CS_KH  0
#define CS_KL  18432
#define CS_QH  36864
#define CS_QL  55296
#define CS_RED 73728
#define CS_SMEM 74752

__global__ __launch_bounds__(256, 1) void attn_colsum_tc(
    const __nv_bfloat16* __restrict__ Qh, const __nv_bfloat16* __restrict__ Ql,
    const __nv_bfloat16* __restrict__ Kh, const __nv_bfloat16* __restrict__ Kl,
    float* __restrict__ colsum)
{
    extern __shared__ char sm[];
    const uint32_t sb = smem_u32(sm);
    const int tid = threadIdx.x;
    const int wid = tid >> 5;
    const int lane = tid & 31;
    const int g = lane >> 2;
    const int t = lane & 3;
    const int wm = wid >> 2;
    const int wn = wid & 3;
    const int kt = blockIdx.x;
    const int bh = blockIdx.y;
    const int b = bh >> 4, h = bh & 15;

    // load K tile (persist)
    #pragma unroll
    for (int p = 0; p < 4; p++) {
        const int idx = tid + p * 256;
        const int r = idx >> 3, c = idx & 7;
        const size_t go = ((size_t)(b * LL + kt * 128 + r)) * DD + h * HDIM + c * 8;
        CP_ASYNC16(sb + CS_KH + r * 144 + c * 16, Kh + go);
        CP_ASYNC16(sb + CS_KL + r * 144 + c * 16, Kl + go);
    }
    // load Q tile 0
    #pragma unroll
    for (int p = 0; p < 4; p++) {
        const int idx = tid + p * 256;
        const int r = idx >> 3, c = idx & 7;
        const size_t go = ((size_t)(b * LL + r)) * DD + h * HDIM + c * 8;
        CP_ASYNC16(sb + CS_QH + r * 144 + c * 16, Qh + go);
        CP_ASYNC16(sb + CS_QL + r * 144 + c * 16, Ql + go);
    }
    CP_COMMIT();

    float cs[4][2];
    #pragma unroll
    for (int j = 0; j < 4; j++) { cs[j][0] = 0.0f; cs[j][1] = 0.0f; }

    for (int qt = 0; qt < 8; qt++) {
        CP_WAIT(0);
        __syncthreads();

        float acc[4][4][4];
        #pragma unroll
        for (int i = 0; i < 4; i++)
            #pragma unroll
            for (int j = 0; j < 4; j++)
                #pragma unroll
                for (int q = 0; q < 4; q++) acc[i][j][q] = 0.0f;

        #pragma unroll
        for (int ks = 0; ks < 4; ks++) {
            uint32_t aH[4][4], aL[4][4], bH[4][2], bL[4][2];
            #pragma unroll
            for (int i = 0; i < 4; i++) {
                const int off = (wm * 64 + i * 16 + g) * 144 + ks * 32 + t * 4;
                aH[i][0] = *(const uint32_t*)(sm + CS_QH + off);
                aH[i][1] = *(const uint32_t*)(sm + CS_QH + off + 8 * 144);
                aH[i][2] = *(const uint32_t*)(sm + CS_QH + off + 16);
                aH[i][3] = *(const uint32_t*)(sm + CS_QH + off + 8 * 144 + 16);
                aL[i][0] = *(const uint32_t*)(sm + CS_QL + off);
                aL[i][1] = *(const uint32_t*)(sm + CS_QL + off + 8 * 144);
                aL[i][2] = *(const uint32_t*)(sm + CS_QL + off + 16);
                aL[i][3] = *(const uint32_t*)(sm + CS_QL + off + 8 * 144 + 16);
            }
            #pragma unroll
            for (int j = 0; j < 4; j++) {
                const int off = (wn * 32 + j * 8 + g) * 144 + ks * 32 + t * 4;
                bH[j][0] = *(const uint32_t*)(sm + CS_KH + off);
                bH[j][1] = *(const uint32_t*)(sm + CS_KH + off + 16);
                bL[j][0] = *(const uint32_t*)(sm + CS_KL + off);
                bL[j][1] = *(const uint32_t*)(sm + CS_KL + off + 16);
            }
            #pragma unroll
            for (int i = 0; i < 4; i++)
                #pragma unroll
                for (int j = 0; j < 4; j++)
                    mma16816(acc[i][j], aH[i][0], aH[i][1], aH[i][2], aH[i][3],
                             bH[j][0], bH[j][1]);
            #pragma unroll
            for (int i = 0; i < 4; i++)
                #pragma unroll
                for (int j = 0; j < 4; j++)
                    mma16816(acc[i][j], aH[i][0], aH[i][1], aH[i][2], aH[i][3],
                             bL[j][0], bL[j][1]);
            #pragma unroll
            for (int i = 0; i < 4; i++)
                #pragma unroll
                for (int j = 0; j < 4; j++)
                    mma16816(acc[i][j], aL[i][0], aL[i][1], aL[i][2], aL[i][3],
                             bH[j][0], bH[j][1]);
        }

        #pragma unroll
        for (int i = 0; i < 4; i++)
            #pragma unroll
            for (int j = 0; j < 4; j++) {
                cs[j][0] += __expf(acc[i][j][0]) + __expf(acc[i][j][2]);
                cs[j][1] += __expf(acc[i][j][1]) + __expf(acc[i][j][3]);
            }

        __syncthreads();
        if (qt < 7) {
            #pragma unroll
            for (int p = 0; p < 4; p++) {
                const int idx = tid + p * 256;
                const int r = idx >> 3, c = idx & 7;
                const size_t go = ((size_t)(b * LL + (qt + 1) * 128 + r)) * DD + h * HDIM + c * 8;
                CP_ASYNC16(sb + CS_QH + r * 144 + c * 16, Qh + go);
                CP_ASYNC16(sb + CS_QL + r * 144 + c * 16, Ql + go);
            }
            CP_COMMIT();
        }
    }

    // reduce over g (lanes with same t), then over wm via smem
    float* red = (float*)(sm + CS_RED);
    #pragma unroll
    for (int j = 0; j < 4; j++)
        #pragma unroll
        for (int hh = 0; hh < 2; hh++) {
            float v = cs[j][hh];
            v += __shfl_down_sync(0xffffffffu, v, 16);
            v += __shfl_down_sync(0xffffffffu, v, 8);
            v += __shfl_down_sync(0xffffffffu, v, 4);
            if (g == 0) red[wid * 32 + j * 8 + 2 * t + hh] = v;
        }
    __syncthreads();
    if (tid < 128) {
        const int col = tid;
        const int w2 = col >> 5, cl = col & 31;
        colsum[(size_t)bh * LL + kt * 128 + col] = red[w2 * 32 + cl] + red[(w2 + 4) * 32 + cl];
    }
}

// ---------------------------------------------------------------------------
// HMMA AV: out[q,d] = sum_k exp(S_qk) * Vp[k,d]  (Vp prescaled by 1/Z)
// Grid (qt=8, bh=128), 256 thr.
// SMEM: QH 18432 | QL 18432 | KH 18432 | KL 18432 |
//       EH 34816 | EL 34816 | VPH0 17408 | VPL0 17408 | VPH1 | VPL1 = 212992 B
// ---------------------------------------------------------------------------
#define AV_QH   0
#define AV_QL   18432
#define AV_KH   36864
#define AV_KL   55296
#define AV_EH   73728
#define AV_EL   108544
#define AV_VP0  143360
#define AV_VPB  34816        // per-buffer (VPH+VPL)
#define AV_SMEM 212992

__device__ __forceinline__ void av_load_kvp(
    uint32_t sb, int tid, int b, int h, int bh, int kt, int buf,
    const __nv_bfloat16* __restrict__ Kh, const __nv_bfloat16* __restrict__ Kl,
    const uint32_t* __restrict__ Vph, const uint32_t* __restrict__ Vpl)
{
    #pragma unroll
    for (int p = 0; p < 4; p++) {
        const int idx = tid + p * 256;
        const int r = idx >> 3, c = idx & 7;
        const size_t go = ((size_t)(b * LL + kt * 128 + r)) * DD + h * HDIM + c * 8;
        CP_ASYNC16(sb + AV_KH + r * 144 + c * 16, Kh + go);
        CP_ASYNC16(sb + AV_KL + r * 144 + c * 16, Kl + go);
    }
    const uint32_t vb = sb + AV_VP0 + buf * AV_VPB;
    #pragma unroll
    for (int p = 0; p < 4; p++) {
        const int idx = tid + p * 256;          // 1024 chunks
        const int r = idx >> 4, c = idx & 15;   // r: k2-row 0..63, c: 16B chunk
        const size_t go = ((size_t)bh * 512 + kt * 64 + r) * 64 + c * 4;
        CP_ASYNC16(vb + r * 272 + c * 16, Vph + go);
        CP_ASYNC16(vb + 17408 + r * 272 + c * 16, Vpl + go);
    }
}

__global__ __launch_bounds__(256, 1) void attn_av_tc(
    const __nv_bfloat16* __restrict__ Qh, const __nv_bfloat16* __restrict__ Ql,
    const __nv_bfloat16* __restrict__ Kh, const __nv_bfloat16* __restrict__ Kl,
    const uint32_t* __restrict__ Vph, const uint32_t* __restrict__ Vpl,
    float* __restrict__ O)
{
    extern __shared__ char sm[];
    const uint32_t sb = smem_u32(sm);
    const int tid = threadIdx.x;
    const int wid = tid >> 5;
    const int lane = tid & 31;
    const int g = lane >> 2;
    const int t = lane & 3;
    const int wm = wid >> 2;
    const int wn = wid & 3;
    const int qt = blockIdx.x;
    const int bh = blockIdx.y;
    const int b = bh >> 4, h = bh & 15;

    // load Q tile (persist)
    #pragma unroll
    for (int p = 0; p < 4; p++) {
        const int idx = tid + p * 256;
        const int r = idx >> 3, c = idx & 7;
        const size_t go = ((size_t)(b * LL + qt * 128 + r)) * DD + h * HDIM + c * 8;
        CP_ASYNC16(sb + AV_QH + r * 144 + c * 16, Qh + go);
        CP_ASYNC16(sb + AV_QL + r * 144 + c * 16, Ql + go);
    }
    av_load_kvp(sb, tid, b, h, bh, 0, 0, Kh, Kl, Vph, Vpl);
    CP_COMMIT();

    float out[4][2][4];
    #pragma unroll
    for (int i = 0; i < 4; i++)
        #pragma unroll
        for (int j = 0; j < 2; j++)
            #pragma unroll
            for (int q = 0; q < 4; q++) out[i][j][q] = 0.0f;

    for (int kt = 0; kt < 8; kt++) {
        const int buf = kt & 1;
        CP_WAIT(0);
        __syncthreads();

        // ---- GEMM1: S = Q . K^T (split bf16, 3 passes) ----
        float acc[4][4][4];
        #pragma unroll
        for (int i = 0; i < 4; i++)
            #pragma unroll
            for (int j = 0; j < 4; j++)
                #pragma unroll
                for (int q = 0; q < 4; q++) acc[i][j][q] = 0.0f;

        #pragma unroll
        for (int ks = 0; ks < 4; ks++) {
            uint32_t aH[4][4], aL[4][4], bH[4][2], bL[4][2];
            #pragma unroll
            for (int i = 0; i < 4; i++) {
                const int off = (wm * 64 + i * 16 + g) * 144 + ks * 32 + t * 4;
                aH[i][0] = *(const uint32_t*)(sm + AV_QH + off);
                aH[i][1] = *(const uint32_t*)(sm + AV_QH + off + 8 * 144);
                aH[i][2] = *(const uint32_t*)(sm + AV_QH + off + 16);
                aH[i][3] = *(const uint32_t*)(sm + AV_QH + off + 8 * 144 + 16);
                aL[i][0] = *(const uint32_t*)(sm + AV_QL + off);
                aL[i][1] = *(const uint32_t*)(sm + AV_QL + off + 8 * 144);
                aL[i][2] = *(const uint32_t*)(sm + AV_QL + off + 16);
                aL[i][3] = *(const uint32_t*)(sm + AV_QL + off + 8 * 144 + 16);
            }
            #pragma unroll
            for (int j = 0; j < 4; j++) {
                const int off = (wn * 32 + j * 8 + g) * 144 + ks * 32 + t * 4;
                bH[j][0] = *(const uint32_t*)(sm + AV_KH + off);
                bH[j][1] = *(const uint32_t*)(sm + AV_KH + off + 16);
                bL[j][0] = *(const uint32_t*)(sm + AV_KL + off);
                bL[j][1] = *(const uint32_t*)(sm + AV_KL + off + 16);
            }
            #pragma unroll
            for (int i = 0; i < 4; i++)
                #pragma unroll
                for (int j = 0; j < 4; j++)
                    mma16816(acc[i][j], aH[i][0], aH[i][1], aH[i][2], aH[i][3],
                             bH[j][0], bH[j][1]);
            #pragma unroll
            for (int i = 0; i < 4; i++)
                #pragma unroll
                for (int j = 0; j < 4; j++)
                    mma16816(acc[i][j], aH[i][0], aH[i][1], aH[i][2], aH[i][3],
                             bL[j][0], bL[j][1]);
            #pragma unroll
            for (int i = 0; i < 4; i++)
                #pragma unroll
                for (int j = 0; j < 4; j++)
                    mma16816(acc[i][j], aL[i][0], aL[i][1], aL[i][2], aL[i][3],
                             bH[j][0], bH[j][1]);
        }

        // ---- exp + split-pack E to smem (pitch 272 B) ----
        #pragma unroll
        for (int i = 0; i < 4; i++) {
            const int row = wm * 64 + i * 16 + g;
            #pragma unroll
            for (int j = 0; j < 4; j++) {
                const int colb = (wn * 32 + j * 8 + 2 * t) * 2;   // byte offset in row
                float e0 = __expf(acc[i][j][0]);
                float e1 = __expf(acc[i][j][1]);
                float e2 = __expf(acc[i][j][2]);
                float e3 = __expf(acc[i][j][3]);
                __nv_bfloat16 h0 = __float2bfloat16(e0);
                __nv_bfloat16 h1 = __float2bfloat16(e1);
                __nv_bfloat16 h2 = __float2bfloat16(e2);
                __nv_bfloat16 h3 = __float2bfloat16(e3);
                *(uint32_t*)(sm + AV_EH + row * 272 + colb) = pack_bf2(e0, e1);
                *(uint32_t*)(sm + AV_EH + (row + 8) * 272 + colb) = pack_bf2(e2, e3);
                *(uint32_t*)(sm + AV_EL + row * 272 + colb) =
                    pack_bf2(e0 - __bfloat162float(h0), e1 - __bfloat162float(h1));
                *(uint32_t*)(sm + AV_EL + (row + 8) * 272 + colb) =
                    pack_bf2(e2 - __bfloat162float(h2), e3 - __bfloat162float(h3));
            }
        }
        __syncthreads();   // E visible; GEMM1 reads of K done

        if (kt < 7) {
            av_load_kvp(sb, tid, b, h, bh, kt + 1, buf ^ 1, Kh, Kl, Vph, Vpl);
            CP_COMMIT();
        }

        // ---- GEMM2: out += E . Vp (split bf16, 3 passes) ----
        const char* VH = sm + AV_VP0 + buf * AV_VPB;
        const char* VL = VH + 17408;
        #pragma unroll
        for (int ks = 0; ks < 8; ks++) {
            uint32_t aH[4][4], aL[4][4], bH[2][2], bL[2][2];
            #pragma unroll
            for (int i = 0; i < 4; i++) {
                const int off = (wm * 64 + i * 16 + g) * 272 + ks * 32 + t * 4;
                aH[i][0] = *(const uint32_t*)(sm + AV_EH + off);
                aH[i][1] = *(const uint32_t*)(sm + AV_EH + off + 8 * 272);
                aH[i][2] = *(const uint32_t*)(sm + AV_EH + off + 16);
                aH[i][3] = *(const uint32_t*)(sm + AV_EH + off + 8 * 272 + 16);
                aL[i][0] = *(const uint32_t*)(sm + AV_EL + off);
                aL[i][1] = *(const uint32_t*)(sm + AV_EL + off + 8 * 272);
                aL[i][2] = *(const uint32_t*)(sm + AV_EL + off + 16);
                aL[i][3] = *(const uint32_t*)(sm + AV_EL + off + 8 * 272 + 16);
            }
            #pragma unroll
            for (int j = 0; j < 2; j++) {
                const int off = (ks * 8 + t) * 272 + (wn * 16 + j * 8 + g) * 4;
                bH[j][0] = *(const uint32_t*)(VH + off);
                bH[j][1] = *(const uint32_t*)(VH + off + 4 * 272);
                bL[j][0] = *(const uint32_t*)(VL + off);
                bL[j][1] = *(const uint32_t*)(VL + off + 4 * 272);
            }
            #pragma unroll
            for (int i = 0; i < 4; i++)
                #pragma unroll
                for (int j = 0; j < 2; j++)
                    mma16816(out[i][j], aH[i][0], aH[i][1], aH[i][2], aH[i][3],
                             bH[j][0], bH[j][1]);
            #pragma unroll
            for (int i = 0; i < 4; i++)
                #pragma unroll
                for (int j = 0; j < 2; j++)
                    mma16816(out[i][j], aH[i][0], aH[i][1], aH[i][2], aH[i][3],
                             bL[j][0], bL[j][1]);
            #pragma unroll
            for (int i = 0; i < 4; i++)
                #pragma unroll
                for (int j = 0; j < 2; j++)
                    mma16816(out[i][j], aL[i][0], aL[i][1], aL[i][2], aL[i][3],
                             bH[j][0], bH[j][1]);
        }
        __syncthreads();   // done reading E (and Vp[buf]) before next overwrite
    }

    // ---- store out tile ----
    #pragma unroll
    for (int i = 0; i < 4; i++) {
        const int row = qt * 128 + wm * 64 + i * 16 + g;
        #pragma unroll
        for (int j = 0; j < 2; j++) {
            const int col = h * HDIM + wn * 16 + j * 8 + 2 * t;
            float* o = O + ((size_t)b * LL + row) * DD + col;
            *(float2*)o = make_float2(out[i][j][0], out[i][j][1]);
            *(float2*)(o + 8 * DD) = make_float2(out[i][j][2], out[i][j][3]);
        }
    }
}

// ---------------------------------------------------------------------------
// Launch
// ---------------------------------------------------------------------------
extern "C" void kernel_launch(void* const* d_in, const int* in_sizes, int n_in,
                              void* d_out, int out_size)
{
    (void)in_sizes; (void)n_in; (void)out_size;

    const float* x_q = (const float*)d_in[0];
    const float* x_k = (const float*)d_in[1];
    const float* x_v = (const float*)d_in[2];
    // d_in[3] = mask: unused (reference never applies it)
    const float* Wq  = (const float*)d_in[4];
    const float* bq  = (const float*)d_in[5];
    const float* Wk  = (const float*)d_in[6];
    const float* bk  = (const float*)d_in[7];
    const float* Wv  = (const float*)d_in[8];
    const float* bv  = (const float*)d_in[9];
    const float* Wo  = (const float*)d_in[10];
    const float* bo  = (const float*)d_in[11];

    float *pQ, *pK, *pV, *pA, *pZ;
    __nv_bfloat16 *pAh, *pAl, *pQh, *pQl, *pKh, *pKl;
    uint32_t *pWh, *pWl, *pVh, *pVl;
    cudaGetSymbolAddress((void**)&pQ, g_Q);
    cudaGetSymbolAddress((void**)&pK, g_K);
    cudaGetSymbolAddress((void**)&pV, g_V);
    cudaGetSymbolAddress((void**)&pA, g_attn);
    cudaGetSymbolAddress((void**)&pZ, g_colsum);
    cudaGetSymbolAddress((void**)&pAh, g_Ah);
    cudaGetSymbolAddress((void**)&pAl, g_Al);
    cudaGetSymbolAddress((void**)&pWh, g_Wph);
    cudaGetSymbolAddress((void**)&pWl, g_Wpl);
    cudaGetSymbolAddress((void**)&pQh, g_Qh);
    cudaGetSymbolAddress((void**)&pQl, g_Ql);
    cudaGetSymbolAddress((void**)&pKh, g_Kh);
    cudaGetSymbolAddress((void**)&pKl, g_Kl);
    cudaGetSymbolAddress((void**)&pVh, g_Vph);
    cudaGetSymbolAddress((void**)&pVl, g_Vpl);

    cudaFuncSetAttribute(tc_gemm_split_kernel,
                         cudaFuncAttributeMaxDynamicSharedMemorySize, GEMM_SMEM);
    cudaFuncSetAttribute(attn_colsum_tc,
                         cudaFuncAttributeMaxDynamicSharedMemorySize, CS_SMEM);
    cudaFuncSetAttribute(attn_av_tc,
                         cudaFuncAttributeMaxDynamicSharedMemorySize, AV_SMEM);

    const int n4 = MTOT * DD / 4;
    const dim3 gSplit((n4 + 255) / 256), t256(256);
    const int npack = (DD / 2) * DD;
    const dim3 gPack((npack + 255) / 256);
    const dim3 gGemm(DD / 128, MTOT / 128);

    // Projections
    split_kernel<<<gSplit, t256>>>(x_q, pAh, pAl, n4, 1.0f);
    pack_w_kernel<<<gPack, t256>>>(Wq, pWh, pWl);
    tc_gemm_split_kernel<<<gGemm, 256, GEMM_SMEM>>>(pAh, pAl, pWh, pWl, bq, pQ);
    split_kernel<<<gSplit, t256>>>(x_k, pAh, pAl, n4, 1.0f);
    pack_w_kernel<<<gPack, t256>>>(Wk, pWh, pWl);
    tc_gemm_split_kernel<<<gGemm, 256, GEMM_SMEM>>>(pAh, pAl, pWh, pWl, bk, pK);
    split_kernel<<<gSplit, t256>>>(x_v, pAh, pAl, n4, 1.0f);
    pack_w_kernel<<<gPack, t256>>>(Wv, pWh, pWl);
    tc_gemm_split_kernel<<<gGemm, 256, GEMM_SMEM>>>(pAh, pAl, pWh, pWl, bv, pV);

    // Attention operand prep: Q scaled by 1/sqrt(D)=1/32 folded into split
    split_kernel<<<gSplit, t256>>>(pQ, pQh, pQl, n4, 0.03125f);
    split_kernel<<<gSplit, t256>>>(pK, pKh, pKl, n4, 1.0f);

    // Column-softmax sums via HMMA
    attn_colsum_tc<<<dim3(8, BB * HH), 256, CS_SMEM>>>(pQh, pQl, pKh, pKl, pZ);

    // Vp = V / Z packed
    const int nvp = BB * HH * (LL / 2) * HDIM;
    build_vp_kernel<<<(nvp + 255) / 256, t256>>>(pV, pZ, pVh, pVl);

    // AV via HMMA
    attn_av_tc<<<dim3(8, BB * HH), 256, AV_SMEM>>>(pQh, pQl, pKh, pKl, pVh, pVl, pA);

    // Output projection -> d_out
    split_kernel<<<gSplit, t256>>>(pA, pAh, pAl, n4, 1.0f);
    pack_w_kernel<<<gPack, t256>>>(Wo, pWh, pWl);
    tc_gemm_split_kernel<<<gGemm, 256, GEMM_SMEM>>>(pAh, pAl, pWh, pWl, bo, (float*)d_out);
}

// round 9
// speedup vs baseline: 3.5673x; 1.2935x over previous
#include <cuda_runtime.h>
#include <cuda_bf16.h>
#include <cstdint>
#include <math.h>

// Problem constants
#define BB   8
#define LL   1024
#define DD   1024
#define HH   16
#define HDIM 64
#define MTOT (BB*LL)

// ---------------------------------------------------------------------------
// Scratch (device globals)
// ---------------------------------------------------------------------------
__device__ float g_V[(size_t)MTOT * DD];            // 32 MB (V projection, fp32)
__device__ float g_zinv[(size_t)BB * HH * LL];      // 512 KB (1/Z)
__device__ float g_Sv[(size_t)BB * HH * HDIM];      // 32 KB  (sum_k V/Z)
__device__ __nv_bfloat16 g_Ah[(size_t)MTOT * DD];   // 16 MB (act hi)
__device__ __nv_bfloat16 g_Al[(size_t)MTOT * DD];   // 16 MB (act lo)
__device__ uint32_t g_Wph[(size_t)(DD/2) * DD];     // 2 MB
__device__ uint32_t g_Wpl[(size_t)(DD/2) * DD];     // 2 MB
__device__ __nv_bfloat16 g_Qh[(size_t)MTOT * DD];   // 16 MB (Q/32, bf16)
__device__ __nv_bfloat16 g_Kh[(size_t)MTOT * DD];   // 16 MB
__device__ uint32_t g_Vph[(size_t)BB * HH * (LL/2) * HDIM];  // 16 MB (V/Z k-pair)

// ---------------------------------------------------------------------------
// Helpers
// ---------------------------------------------------------------------------
__device__ __forceinline__ void mma16816(float c[4],
    uint32_t a0, uint32_t a1, uint32_t a2, uint32_t a3,
    uint32_t b0, uint32_t b1)
{
    asm volatile(
        "mma.sync.aligned.m16n8k16.row.col.f32.bf16.bf16.f32 "
        "{%0,%1,%2,%3}, {%4,%5,%6,%7}, {%8,%9}, {%0,%1,%2,%3};"
        : "+f"(c[0]), "+f"(c[1]), "+f"(c[2]), "+f"(c[3])
        : "r"(a0), "r"(a1), "r"(a2), "r"(a3), "r"(b0), "r"(b1));
}

__device__ __forceinline__ uint32_t smem_u32(const void* p) {
    uint32_t a;
    asm("{ .reg .u64 t; cvta.to.shared.u64 t, %1; cvt.u32.u64 %0, t; }"
        : "=r"(a) : "l"(p));
    return a;
}

#define CP_ASYNC16(dst_u32, src_ptr) \
    asm volatile("cp.async.cg.shared.global [%0], [%1], 16;" \
        :: "r"(dst_u32), "l"(src_ptr) : "memory")
#define CP_COMMIT() asm volatile("cp.async.commit_group;" ::: "memory")
#define CP_WAIT(n)  asm volatile("cp.async.wait_group %0;" :: "n"(n) : "memory")

__device__ __forceinline__ uint32_t pack_bf2(float x, float y) {
    __nv_bfloat162 p = __floats2bfloat162_rn(x, y);
    return *(uint32_t*)&p;
}

// ---------------------------------------------------------------------------
// split fp32 -> (bf16 hi, bf16 lo)
// ---------------------------------------------------------------------------
__global__ __launch_bounds__(256) void split_kernel(
    const float* __restrict__ x, __nv_bfloat16* __restrict__ h,
    __nv_bfloat16* __restrict__ l, int n4)
{
    int i = blockIdx.x * blockDim.x + threadIdx.x;
    if (i >= n4) return;
    float4 v = ((const float4*)x)[i];
    __nv_bfloat16 h0 = __float2bfloat16(v.x);
    __nv_bfloat16 h1 = __float2bfloat16(v.y);
    __nv_bfloat16 h2 = __float2bfloat16(v.z);
    __nv_bfloat16 h3 = __float2bfloat16(v.w);
    __nv_bfloat162* hp = (__nv_bfloat162*)h;
    __nv_bfloat162* lp = (__nv_bfloat162*)l;
    hp[2*i]   = __halves2bfloat162(h0, h1);
    hp[2*i+1] = __halves2bfloat162(h2, h3);
    lp[2*i]   = __halves2bfloat162(
        __float2bfloat16(v.x - __bfloat162float(h0)),
        __float2bfloat16(v.y - __bfloat162float(h1)));
    lp[2*i+1] = __halves2bfloat162(
        __float2bfloat16(v.z - __bfloat162float(h2)),
        __float2bfloat16(v.w - __bfloat162float(h3)));
}

// ---------------------------------------------------------------------------
// pack W [K,N] fp32 -> k-pair bf16x2 [k2][n] (hi/lo)
// ---------------------------------------------------------------------------
__global__ __launch_bounds__(256) void pack_w_kernel(
    const float* __restrict__ W, uint32_t* __restrict__ Ph,
    uint32_t* __restrict__ Pl)
{
    int i = blockIdx.x * blockDim.x + threadIdx.x;
    if (i >= (DD/2) * DD) return;
    int k2 = i >> 10, n = i & (DD - 1);
    float w0 = W[(size_t)(2*k2)     * DD + n];
    float w1 = W[(size_t)(2*k2 + 1) * DD + n];
    __nv_bfloat16 h0 = __float2bfloat16(w0);
    __nv_bfloat16 h1 = __float2bfloat16(w1);
    Ph[i] = pack_bf2(w0, w1);
    Pl[i] = pack_bf2(w0 - __bfloat162float(h0), w1 - __bfloat162float(h1));
}

// ---------------------------------------------------------------------------
// build Vp (hi only): Vp[bh][k2][d] = bf16x2{ V[2k2,d]*zi0, V[2k2+1,d]*zi1 }
// ---------------------------------------------------------------------------
__global__ __launch_bounds__(256) void build_vp_kernel(
    const float* __restrict__ V, const float* __restrict__ Zi,
    uint32_t* __restrict__ Ph)
{
    int i = blockIdx.x * blockDim.x + threadIdx.x;
    const int total = BB * HH * (LL/2) * HDIM;
    if (i >= total) return;
    int bh = i >> 15;
    int r  = (i >> 6) & 511;
    int d  = i & 63;
    int b = bh >> 4, h = bh & 15;
    float zi0 = Zi[(size_t)bh * LL + 2*r];
    float zi1 = Zi[(size_t)bh * LL + 2*r + 1];
    float v0 = V[((size_t)b * LL + 2*r)     * DD + h * HDIM + d] * zi0;
    float v1 = V[((size_t)b * LL + 2*r + 1) * DD + h * HDIM + d] * zi1;
    Ph[i] = pack_bf2(v0, v1);
}

// ---------------------------------------------------------------------------
// Sv[bh][d] = sum_k V[b,k,h,d] * zinv[bh,k]   (fp32 exact part of AV)
// ---------------------------------------------------------------------------
__global__ __launch_bounds__(256) void compute_sv_kernel(
    const float* __restrict__ V, const float* __restrict__ Zi,
    float* __restrict__ Sv)
{
    __shared__ float red[256];
    const int bh = blockIdx.x;
    const int b = bh >> 4, h = bh & 15;
    const int tid = threadIdx.x;
    const int d = tid & 63;
    const int slice = tid >> 6;        // 0..3, each 256 k
    float s = 0.0f;
    const int k0 = slice * 256;
    for (int k = k0; k < k0 + 256; k++) {
        s += V[((size_t)b * LL + k) * DD + h * HDIM + d] * Zi[(size_t)bh * LL + k];
    }
    red[tid] = s;
    __syncthreads();
    if (tid < 64)
        Sv[(size_t)bh * HDIM + d] = red[d] + red[64 + d] + red[128 + d] + red[192 + d];
}

// ---------------------------------------------------------------------------
// Split-bf16 HMMA projection GEMM. mode 0: fp32 C = A@W + bias.
// mode 1: bf16 Hout = (A@W + bias) * oscale  (hi rounding only)
// ---------------------------------------------------------------------------
#define SM_AH   0
#define SM_AL   18432
#define SM_BH   36864
#define SM_BL   53760
#define SM_BUF  70656
#define GEMM_SMEM (2 * SM_BUF)

__device__ __forceinline__ void gemm_load_tiles(
    char* sm, uint32_t smem_base, int buf, int tid, int m0, int n0, int kt,
    const __nv_bfloat16* __restrict__ Ah, const __nv_bfloat16* __restrict__ Al,
    const uint32_t* __restrict__ Bh, const uint32_t* __restrict__ Bl)
{
    const uint32_t sb = smem_base + buf * SM_BUF;
    #pragma unroll
    for (int p = 0; p < 4; p++) {
        const int idx = tid + p * 256;
        const int r = idx >> 3, c = idx & 7;
        const size_t g = (size_t)(m0 + r) * DD + kt * 64 + c * 8;
        const uint32_t d = r * 144 + c * 16;
        CP_ASYNC16(sb + SM_AH + d, Ah + g);
        CP_ASYNC16(sb + SM_AL + d, Al + g);
    }
    #pragma unroll
    for (int p = 0; p < 4; p++) {
        const int idx = tid + p * 256;
        const int r = idx >> 5, c = idx & 31;
        const size_t g = (size_t)(kt * 32 + r) * DD + n0 + c * 4;
        const uint32_t d = r * 528 + c * 16;
        CP_ASYNC16(sb + SM_BH + d, Bh + g);
        CP_ASYNC16(sb + SM_BL + d, Bl + g);
    }
}

__global__ __launch_bounds__(256, 1) void tc_gemm_split_kernel(
    const __nv_bfloat16* __restrict__ Ah, const __nv_bfloat16* __restrict__ Al,
    const uint32_t* __restrict__ Bh, const uint32_t* __restrict__ Bl,
    const float* __restrict__ bias, float* __restrict__ C,
    __nv_bfloat16* __restrict__ Hout, float oscale, int mode)
{
    extern __shared__ char sm[];
    const uint32_t smem_base = smem_u32(sm);
    const int tid = threadIdx.x;
    const int wid = tid >> 5;
    const int lane = tid & 31;
    const int g = lane >> 2;
    const int t = lane & 3;
    const int wm = wid >> 2;
    const int wn = wid & 3;
    const int n0 = blockIdx.x * 128;
    const int m0 = blockIdx.y * 128;

    float c[4][4][4];
    #pragma unroll
    for (int i = 0; i < 4; i++)
        #pragma unroll
        for (int j = 0; j < 4; j++)
            #pragma unroll
            for (int q = 0; q < 4; q++) c[i][j][q] = 0.0f;

    gemm_load_tiles(sm, smem_base, 0, tid, m0, n0, 0, Ah, Al, Bh, Bl);
    CP_COMMIT();

    for (int kt = 0; kt < 16; kt++) {
        const int buf = kt & 1;
        if (kt < 15) {
            gemm_load_tiles(sm, smem_base, buf ^ 1, tid, m0, n0, kt + 1, Ah, Al, Bh, Bl);
            CP_COMMIT();
            CP_WAIT(1);
        } else {
            CP_WAIT(0);
        }
        __syncthreads();

        const char* Abh = sm + buf * SM_BUF + SM_AH;
        const char* Abl = sm + buf * SM_BUF + SM_AL;
        const char* Bbh = sm + buf * SM_BUF + SM_BH;
        const char* Bbl = sm + buf * SM_BUF + SM_BL;

        #pragma unroll
        for (int ks = 0; ks < 4; ks++) {
            uint32_t aH[4][4], aL[4][4], bH[4][2], bL[4][2];
            #pragma unroll
            for (int i = 0; i < 4; i++) {
                const int off = (wm * 64 + i * 16 + g) * 144 + ks * 32 + t * 4;
                aH[i][0] = *(const uint32_t*)(Abh + off);
                aH[i][1] = *(const uint32_t*)(Abh + off + 8 * 144);
                aH[i][2] = *(const uint32_t*)(Abh + off + 16);
                aH[i][3] = *(const uint32_t*)(Abh + off + 8 * 144 + 16);
                aL[i][0] = *(const uint32_t*)(Abl + off);
                aL[i][1] = *(const uint32_t*)(Abl + off + 8 * 144);
                aL[i][2] = *(const uint32_t*)(Abl + off + 16);
                aL[i][3] = *(const uint32_t*)(Abl + off + 8 * 144 + 16);
            }
            #pragma unroll
            for (int j = 0; j < 4; j++) {
                const int off = (ks * 8 + t) * 528 + (wn * 32 + j * 8 + g) * 4;
                bH[j][0] = *(const uint32_t*)(Bbh + off);
                bH[j][1] = *(const uint32_t*)(Bbh + off + 4 * 528);
                bL[j][0] = *(const uint32_t*)(Bbl + off);
                bL[j][1] = *(const uint32_t*)(Bbl + off + 4 * 528);
            }
            #pragma unroll
            for (int i = 0; i < 4; i++)
                #pragma unroll
                for (int j = 0; j < 4; j++)
                    mma16816(c[i][j], aH[i][0], aH[i][1], aH[i][2], aH[i][3],
                             bH[j][0], bH[j][1]);
            #pragma unroll
            for (int i = 0; i < 4; i++)
                #pragma unroll
                for (int j = 0; j < 4; j++)
                    mma16816(c[i][j], aH[i][0], aH[i][1], aH[i][2], aH[i][3],
                             bL[j][0], bL[j][1]);
            #pragma unroll
            for (int i = 0; i < 4; i++)
                #pragma unroll
                for (int j = 0; j < 4; j++)
                    mma16816(c[i][j], aL[i][0], aL[i][1], aL[i][2], aL[i][3],
                             bH[j][0], bH[j][1]);
        }
        __syncthreads();
    }

    #pragma unroll
    for (int j = 0; j < 4; j++) {
        const int col = n0 + wn * 32 + j * 8 + 2 * t;
        const float2 bv = *(const float2*)(bias + col);
        #pragma unroll
        for (int i = 0; i < 4; i++) {
            const int row = m0 + wm * 64 + i * 16 + g;
            float v0 = c[i][j][0] + bv.x, v1 = c[i][j][1] + bv.y;
            float v2 = c[i][j][2] + bv.x, v3 = c[i][j][3] + bv.y;
            if (mode == 0) {
                float* o = C + (size_t)row * DD + col;
                *(float2*)o = make_float2(v0, v1);
                *(float2*)(o + 8 * DD) = make_float2(v2, v3);
            } else {
                *(uint32_t*)(Hout + (size_t)row * DD + col) =
                    pack_bf2(v0 * oscale, v1 * oscale);
                *(uint32_t*)(Hout + (size_t)(row + 8) * DD + col) =
                    pack_bf2(v2 * oscale, v3 * oscale);
            }
        }
    }
}

// ---------------------------------------------------------------------------
// HMMA colsum (single-pass bf16): zinv[bh,k] = 1 / sum_q exp(S_qk)
// Grid (kt=8, bh=128), 256 thr. SMEM: KH 18432 | QH 18432 | RED 1024 = 37888
// ---------------------------------------------------------------------------
#define CS_KH  0
#define CS_QH  18432
#define CS_RED 36864
#define CS_SMEM 37888

__global__ __launch_bounds__(256, 2) void attn_colsum_tc(
    const __nv_bfloat16* __restrict__ Qh, const __nv_bfloat16* __restrict__ Kh,
    float* __restrict__ zinv)
{
    extern __shared__ char sm[];
    const uint32_t sb = smem_u32(sm);
    const int tid = threadIdx.x;
    const int wid = tid >> 5;
    const int lane = tid & 31;
    const int g = lane >> 2;
    const int t = lane & 3;
    const int wm = wid >> 2;
    const int wn = wid & 3;
    const int kt = blockIdx.x;
    const int bh = blockIdx.y;
    const int b = bh >> 4, h = bh & 15;

    #pragma unroll
    for (int p = 0; p < 4; p++) {
        const int idx = tid + p * 256;
        const int r = idx >> 3, c = idx & 7;
        const size_t go = ((size_t)(b * LL + kt * 128 + r)) * DD + h * HDIM + c * 8;
        CP_ASYNC16(sb + CS_KH + r * 144 + c * 16, Kh + go);
    }
    #pragma unroll
    for (int p = 0; p < 4; p++) {
        const int idx = tid + p * 256;
        const int r = idx >> 3, c = idx & 7;
        const size_t go = ((size_t)(b * LL + r)) * DD + h * HDIM + c * 8;
        CP_ASYNC16(sb + CS_QH + r * 144 + c * 16, Qh + go);
    }
    CP_COMMIT();

    float cs[4][2];
    #pragma unroll
    for (int j = 0; j < 4; j++) { cs[j][0] = 0.0f; cs[j][1] = 0.0f; }

    for (int qt = 0; qt < 8; qt++) {
        CP_WAIT(0);
        __syncthreads();

        float acc[4][4][4];
        #pragma unroll
        for (int i = 0; i < 4; i++)
            #pragma unroll
            for (int j = 0; j < 4; j++)
                #pragma unroll
                for (int q = 0; q < 4; q++) acc[i][j][q] = 0.0f;

        #pragma unroll
        for (int ks = 0; ks < 4; ks++) {
            uint32_t aH[4][4], bH[4][2];
            #pragma unroll
            for (int i = 0; i < 4; i++) {
                const int off = (wm * 64 + i * 16 + g) * 144 + ks * 32 + t * 4;
                aH[i][0] = *(const uint32_t*)(sm + CS_QH + off);
                aH[i][1] = *(const uint32_t*)(sm + CS_QH + off + 8 * 144);
                aH[i][2] = *(const uint32_t*)(sm + CS_QH + off + 16);
                aH[i][3] = *(const uint32_t*)(sm + CS_QH + off + 8 * 144 + 16);
            }
            #pragma unroll
            for (int j = 0; j < 4; j++) {
                const int off = (wn * 32 + j * 8 + g) * 144 + ks * 32 + t * 4;
                bH[j][0] = *(const uint32_t*)(sm + CS_KH + off);
                bH[j][1] = *(const uint32_t*)(sm + CS_KH + off + 16);
            }
            #pragma unroll
            for (int i = 0; i < 4; i++)
                #pragma unroll
                for (int j = 0; j < 4; j++)
                    mma16816(acc[i][j], aH[i][0], aH[i][1], aH[i][2], aH[i][3],
                             bH[j][0], bH[j][1]);
        }

        #pragma unroll
        for (int i = 0; i < 4; i++)
            #pragma unroll
            for (int j = 0; j < 4; j++) {
                cs[j][0] += __expf(acc[i][j][0]) + __expf(acc[i][j][2]);
                cs[j][1] += __expf(acc[i][j][1]) + __expf(acc[i][j][3]);
            }

        __syncthreads();
        if (qt < 7) {
            #pragma unroll
            for (int p = 0; p < 4; p++) {
                const int idx = tid + p * 256;
                const int r = idx >> 3, c = idx & 7;
                const size_t go = ((size_t)(b * LL + (qt + 1) * 128 + r)) * DD + h * HDIM + c * 8;
                CP_ASYNC16(sb + CS_QH + r * 144 + c * 16, Qh + go);
            }
            CP_COMMIT();
        }
    }

    float* red = (float*)(sm + CS_RED);
    #pragma unroll
    for (int j = 0; j < 4; j++)
        #pragma unroll
        for (int hh = 0; hh < 2; hh++) {
            float v = cs[j][hh];
            v += __shfl_down_sync(0xffffffffu, v, 16);
            v += __shfl_down_sync(0xffffffffu, v, 8);
            v += __shfl_down_sync(0xffffffffu, v, 4);
            if (g == 0) red[wid * 32 + j * 8 + 2 * t + hh] = v;
        }
    __syncthreads();
    if (tid < 128) {
        const int col = tid;
        const int w2 = col >> 5, cl = col & 31;
        zinv[(size_t)bh * LL + kt * 128 + col] =
            1.0f / (red[w2 * 32 + cl] + red[(w2 + 4) * 32 + cl]);
    }
}

// ---------------------------------------------------------------------------
// HMMA AV (E = 1 + e decomposition):
// out[q,d] = Sv[d] + sum_k e_qk * Vp_h[k,d],  e = exp(S)-1, Vp = V/Z
// GEMM1 single-pass bf16, GEMM2 single-pass (e_bf16 x Vp_hi).
// Writes attention output as split bf16 hi/lo (for final projection).
// Grid (qt=8, bh=128), 256 thr.
// SMEM: QH 18432 | KH 18432 | E 34816 | VP 2x17408 = 106496
// ---------------------------------------------------------------------------
#define AV_QH   0
#define AV_KH   18432
#define AV_E    36864
#define AV_VP0  71680
#define AV_VPB  17408
#define AV_SMEM 106496

__device__ __forceinline__ void av_load_kvp(
    uint32_t sb, int tid, int b, int h, int bh, int kt, int buf,
    const __nv_bfloat16* __restrict__ Kh, const uint32_t* __restrict__ Vph)
{
    #pragma unroll
    for (int p = 0; p < 4; p++) {
        const int idx = tid + p * 256;
        const int r = idx >> 3, c = idx & 7;
        const size_t go = ((size_t)(b * LL + kt * 128 + r)) * DD + h * HDIM + c * 8;
        CP_ASYNC16(sb + AV_KH + r * 144 + c * 16, Kh + go);
    }
    const uint32_t vb = sb + AV_VP0 + buf * AV_VPB;
    #pragma unroll
    for (int p = 0; p < 4; p++) {
        const int idx = tid + p * 256;
        const int r = idx >> 4, c = idx & 15;
        const size_t go = ((size_t)bh * 512 + kt * 64 + r) * 64 + c * 4;
        CP_ASYNC16(vb + r * 272 + c * 16, Vph + go);
    }
}

__global__ __launch_bounds__(256, 1) void attn_av_tc(
    const __nv_bfloat16* __restrict__ Qh, const __nv_bfloat16* __restrict__ Kh,
    const uint32_t* __restrict__ Vph, const float* __restrict__ Sv,
    __nv_bfloat16* __restrict__ Oh, __nv_bfloat16* __restrict__ Ol)
{
    extern __shared__ char sm[];
    const uint32_t sb = smem_u32(sm);
    const int tid = threadIdx.x;
    const int wid = tid >> 5;
    const int lane = tid & 31;
    const int g = lane >> 2;
    const int t = lane & 3;
    const int wm = wid >> 2;
    const int wn = wid & 3;
    const int qt = blockIdx.x;
    const int bh = blockIdx.y;
    const int b = bh >> 4, h = bh & 15;

    #pragma unroll
    for (int p = 0; p < 4; p++) {
        const int idx = tid + p * 256;
        const int r = idx >> 3, c = idx & 7;
        const size_t go = ((size_t)(b * LL + qt * 128 + r)) * DD + h * HDIM + c * 8;
        CP_ASYNC16(sb + AV_QH + r * 144 + c * 16, Qh + go);
    }
    av_load_kvp(sb, tid, b, h, bh, 0, 0, Kh, Vph);
    CP_COMMIT();

    float out[4][2][4];
    #pragma unroll
    for (int i = 0; i < 4; i++)
        #pragma unroll
        for (int j = 0; j < 2; j++)
            #pragma unroll
            for (int q = 0; q < 4; q++) out[i][j][q] = 0.0f;

    for (int kt = 0; kt < 8; kt++) {
        const int buf = kt & 1;
        CP_WAIT(0);
        __syncthreads();

        // ---- GEMM1: S = Q . K^T (single-pass bf16) ----
        float acc[4][4][4];
        #pragma unroll
        for (int i = 0; i < 4; i++)
            #pragma unroll
            for (int j = 0; j < 4; j++)
                #pragma unroll
                for (int q = 0; q < 4; q++) acc[i][j][q] = 0.0f;

        #pragma unroll
        for (int ks = 0; ks < 4; ks++) {
            uint32_t aH[4][4], bH[4][2];
            #pragma unroll
            for (int i = 0; i < 4; i++) {
                const int off = (wm * 64 + i * 16 + g) * 144 + ks * 32 + t * 4;
                aH[i][0] = *(const uint32_t*)(sm + AV_QH + off);
                aH[i][1] = *(const uint32_t*)(sm + AV_QH + off + 8 * 144);
                aH[i][2] = *(const uint32_t*)(sm + AV_QH + off + 16);
                aH[i][3] = *(const uint32_t*)(sm + AV_QH + off + 8 * 144 + 16);
            }
            #pragma unroll
            for (int j = 0; j < 4; j++) {
                const int off = (wn * 32 + j * 8 + g) * 144 + ks * 32 + t * 4;
                bH[j][0] = *(const uint32_t*)(sm + AV_KH + off);
                bH[j][1] = *(const uint32_t*)(sm + AV_KH + off + 16);
            }
            #pragma unroll
            for (int i = 0; i < 4; i++)
                #pragma unroll
                for (int j = 0; j < 4; j++)
                    mma16816(acc[i][j], aH[i][0], aH[i][1], aH[i][2], aH[i][3],
                             bH[j][0], bH[j][1]);
        }

        // ---- e = exp(S) - 1, packed bf16 to smem (pitch 272) ----
        #pragma unroll
        for (int i = 0; i < 4; i++) {
            const int row = wm * 64 + i * 16 + g;
            #pragma unroll
            for (int j = 0; j < 4; j++) {
                const int colb = (wn * 32 + j * 8 + 2 * t) * 2;
                float e0 = __expf(acc[i][j][0]) - 1.0f;
                float e1 = __expf(acc[i][j][1]) - 1.0f;
                float e2 = __expf(acc[i][j][2]) - 1.0f;
                float e3 = __expf(acc[i][j][3]) - 1.0f;
                *(uint32_t*)(sm + AV_E + row * 272 + colb) = pack_bf2(e0, e1);
                *(uint32_t*)(sm + AV_E + (row + 8) * 272 + colb) = pack_bf2(e2, e3);
            }
        }
        __syncthreads();

        if (kt < 7) {
            av_load_kvp(sb, tid, b, h, bh, kt + 1, buf ^ 1, Kh, Vph);
            CP_COMMIT();
        }

        // ---- GEMM2: out += e . Vp (single-pass) ----
        const char* VH = sm + AV_VP0 + buf * AV_VPB;
        #pragma unroll
        for (int ks = 0; ks < 8; ks++) {
            uint32_t aE[4][4], bV[2][2];
            #pragma unroll
            for (int i = 0; i < 4; i++) {
                const int off = (wm * 64 + i * 16 + g) * 272 + ks * 32 + t * 4;
                aE[i][0] = *(const uint32_t*)(sm + AV_E + off);
                aE[i][1] = *(const uint32_t*)(sm + AV_E + off + 8 * 272);
                aE[i][2] = *(const uint32_t*)(sm + AV_E + off + 16);
                aE[i][3] = *(const uint32_t*)(sm + AV_E + off + 8 * 272 + 16);
            }
            #pragma unroll
            for (int j = 0; j < 2; j++) {
                const int off = (ks * 8 + t) * 272 + (wn * 16 + j * 8 + g) * 4;
                bV[j][0] = *(const uint32_t*)(VH + off);
                bV[j][1] = *(const uint32_t*)(VH + off + 4 * 272);
            }
            #pragma unroll
            for (int i = 0; i < 4; i++)
                #pragma unroll
                for (int j = 0; j < 2; j++)
                    mma16816(out[i][j], aE[i][0], aE[i][1], aE[i][2], aE[i][3],
                             bV[j][0], bV[j][1]);
        }
        __syncthreads();
    }

    // ---- add Sv, write split bf16 attention output ----
    #pragma unroll
    for (int i = 0; i < 4; i++) {
        const int row = qt * 128 + wm * 64 + i * 16 + g;
        #pragma unroll
        for (int j = 0; j < 2; j++) {
            const int dcol = wn * 16 + j * 8 + 2 * t;
            const float sv0 = Sv[(size_t)bh * HDIM + dcol];
            const float sv1 = Sv[(size_t)bh * HDIM + dcol + 1];
            const size_t o0 = ((size_t)b * LL + row) * DD + h * HDIM + dcol;
            const size_t o1 = ((size_t)b * LL + row + 8) * DD + h * HDIM + dcol;
            float v0 = out[i][j][0] + sv0, v1 = out[i][j][1] + sv1;
            float v2 = out[i][j][2] + sv0, v3 = out[i][j][3] + sv1;
            __nv_bfloat16 h0 = __float2bfloat16(v0);
            __nv_bfloat16 h1 = __float2bfloat16(v1);
            __nv_bfloat16 h2 = __float2bfloat16(v2);
            __nv_bfloat16 h3 = __float2bfloat16(v3);
            *(uint32_t*)(Oh + o0) = pack_bf2(v0, v1);
            *(uint32_t*)(Oh + o1) = pack_bf2(v2, v3);
            *(uint32_t*)(Ol + o0) =
                pack_bf2(v0 - __bfloat162float(h0), v1 - __bfloat162float(h1));
            *(uint32_t*)(Ol + o1) =
                pack_bf2(v2 - __bfloat162float(h2), v3 - __bfloat162float(h3));
        }
    }
}

// ---------------------------------------------------------------------------
// Launch
// ---------------------------------------------------------------------------
extern "C" void kernel_launch(void* const* d_in, const int* in_sizes, int n_in,
                              void* d_out, int out_size)
{
    (void)in_sizes; (void)n_in; (void)out_size;

    const float* x_q = (const float*)d_in[0];
    const float* x_k = (const float*)d_in[1];
    const float* x_v = (const float*)d_in[2];
    // d_in[3] = mask: unused (reference never applies it)
    const float* Wq  = (const float*)d_in[4];
    const float* bq  = (const float*)d_in[5];
    const float* Wk  = (const float*)d_in[6];
    const float* bk  = (const float*)d_in[7];
    const float* Wv  = (const float*)d_in[8];
    const float* bv  = (const float*)d_in[9];
    const float* Wo  = (const float*)d_in[10];
    const float* bo  = (const float*)d_in[11];

    float *pV, *pZi, *pSv;
    __nv_bfloat16 *pAh, *pAl, *pQh, *pKh;
    uint32_t *pWh, *pWl, *pVh;
    cudaGetSymbolAddress((void**)&pV, g_V);
    cudaGetSymbolAddress((void**)&pZi, g_zinv);
    cudaGetSymbolAddress((void**)&pSv, g_Sv);
    cudaGetSymbolAddress((void**)&pAh, g_Ah);
    cudaGetSymbolAddress((void**)&pAl, g_Al);
    cudaGetSymbolAddress((void**)&pWh, g_Wph);
    cudaGetSymbolAddress((void**)&pWl, g_Wpl);
    cudaGetSymbolAddress((void**)&pQh, g_Qh);
    cudaGetSymbolAddress((void**)&pKh, g_Kh);
    cudaGetSymbolAddress((void**)&pVh, g_Vph);

    cudaFuncSetAttribute(tc_gemm_split_kernel,
                         cudaFuncAttributeMaxDynamicSharedMemorySize, GEMM_SMEM);
    cudaFuncSetAttribute(attn_colsum_tc,
                         cudaFuncAttributeMaxDynamicSharedMemorySize, CS_SMEM);
    cudaFuncSetAttribute(attn_av_tc,
                         cudaFuncAttributeMaxDynamicSharedMemorySize, AV_SMEM);

    const int n4 = MTOT * DD / 4;
    const dim3 gSplit((n4 + 255) / 256), t256(256);
    const int npack = (DD / 2) * DD;
    const dim3 gPack((npack + 255) / 256);
    const dim3 gGemm(DD / 128, MTOT / 128);

    // Q projection -> Qh (scaled by 1/sqrt(D) = 1/32)
    split_kernel<<<gSplit, t256>>>(x_q, pAh, pAl, n4);
    pack_w_kernel<<<gPack, t256>>>(Wq, pWh, pWl);
    tc_gemm_split_kernel<<<gGemm, 256, GEMM_SMEM>>>(
        pAh, pAl, pWh, pWl, bq, nullptr, pQh, 0.03125f, 1);
    // K projection -> Kh
    split_kernel<<<gSplit, t256>>>(x_k, pAh, pAl, n4);
    pack_w_kernel<<<gPack, t256>>>(Wk, pWh, pWl);
    tc_gemm_split_kernel<<<gGemm, 256, GEMM_SMEM>>>(
        pAh, pAl, pWh, pWl, bk, nullptr, pKh, 1.0f, 1);
    // V projection -> fp32 V
    split_kernel<<<gSplit, t256>>>(x_v, pAh, pAl, n4);
    pack_w_kernel<<<gPack, t256>>>(Wv, pWh, pWl);
    tc_gemm_split_kernel<<<gGemm, 256, GEMM_SMEM>>>(
        pAh, pAl, pWh, pWl, bv, pV, nullptr, 1.0f, 0);

    // zinv = 1 / column-softmax sums
    attn_colsum_tc<<<dim3(8, BB * HH), 256, CS_SMEM>>>(pQh, pKh, pZi);

    // Vp (hi) and Sv
    const int nvp = BB * HH * (LL / 2) * HDIM;
    build_vp_kernel<<<(nvp + 255) / 256, t256>>>(pV, pZi, pVh);
    compute_sv_kernel<<<BB * HH, 256>>>(pV, pZi, pSv);

    // AV -> split attention output in (Ah, Al)
    attn_av_tc<<<dim3(8, BB * HH), 256, AV_SMEM>>>(pQh, pKh, pVh, pSv, pAh, pAl);

    // Output projection -> d_out
    pack_w_kernel<<<gPack, t256>>>(Wo, pWh, pWl);
    tc_gemm_split_kernel<<<gGemm, 256, GEMM_SMEM>>>(
        pAh, pAl, pWh, pWl, bo, (float*)d_out, nullptr, 1.0f, 0);
}

// round 10
// speedup vs baseline: 4.6144x; 1.2935x over previous
#include <cuda_runtime.h>
#include <cuda_bf16.h>
#include <cstdint>
#include <math.h>

// Problem constants
#define BB   8
#define LL   1024
#define DD   1024
#define HH   16
#define HDIM 64
#define MTOT (BB*LL)

// ---------------------------------------------------------------------------
// Scratch (device globals)
// ---------------------------------------------------------------------------
__device__ float g_V[(size_t)MTOT * DD];            // 32 MB (V projection, fp32)
__device__ float g_zinv[(size_t)BB * HH * LL];      // 512 KB (1/Z)
__device__ float g_sz[(size_t)BB * HH];             // sum_k zinv
__device__ float g_sx[(size_t)BB * HH * DD];        // 512 KB (sum_k x_v * zinv)
__device__ float g_Sv[(size_t)BB * HH * HDIM];      // 32 KB  (exact sum_k V/Z)
__device__ __nv_bfloat16 g_Ah[(size_t)MTOT * DD];   // 16 MB (act hi)
__device__ __nv_bfloat16 g_Al[(size_t)MTOT * DD];   // 16 MB (act lo)
__device__ uint32_t g_Wph[(size_t)(DD/2) * DD];     // 2 MB
__device__ uint32_t g_Wpl[(size_t)(DD/2) * DD];     // 2 MB
__device__ __nv_bfloat16 g_Qh[(size_t)MTOT * DD];   // 16 MB (Q/32, bf16)
__device__ __nv_bfloat16 g_Kh[(size_t)MTOT * DD];   // 16 MB
__device__ uint32_t g_Vph[(size_t)BB * HH * (LL/2) * HDIM];  // 16 MB (V/Z k-pair)

// ---------------------------------------------------------------------------
// Helpers
// ---------------------------------------------------------------------------
__device__ __forceinline__ void mma16816(float c[4],
    uint32_t a0, uint32_t a1, uint32_t a2, uint32_t a3,
    uint32_t b0, uint32_t b1)
{
    asm volatile(
        "mma.sync.aligned.m16n8k16.row.col.f32.bf16.bf16.f32 "
        "{%0,%1,%2,%3}, {%4,%5,%6,%7}, {%8,%9}, {%0,%1,%2,%3};"
        : "+f"(c[0]), "+f"(c[1]), "+f"(c[2]), "+f"(c[3])
        : "r"(a0), "r"(a1), "r"(a2), "r"(a3), "r"(b0), "r"(b1));
}

__device__ __forceinline__ uint32_t smem_u32(const void* p) {
    uint32_t a;
    asm("{ .reg .u64 t; cvta.to.shared.u64 t, %1; cvt.u32.u64 %0, t; }"
        : "=r"(a) : "l"(p));
    return a;
}

#define CP_ASYNC16(dst_u32, src_ptr) \
    asm volatile("cp.async.cg.shared.global [%0], [%1], 16;" \
        :: "r"(dst_u32), "l"(src_ptr) : "memory")
#define CP_COMMIT() asm volatile("cp.async.commit_group;" ::: "memory")
#define CP_WAIT(n)  asm volatile("cp.async.wait_group %0;" :: "n"(n) : "memory")

__device__ __forceinline__ uint32_t pack_bf2(float x, float y) {
    __nv_bfloat162 p = __floats2bfloat162_rn(x, y);
    return *(uint32_t*)&p;
}

// ---------------------------------------------------------------------------
// fp32 -> bf16 (hi only)
// ---------------------------------------------------------------------------
__global__ __launch_bounds__(256) void tobf16_kernel(
    const float* __restrict__ x, __nv_bfloat16* __restrict__ h, int n4)
{
    int i = blockIdx.x * blockDim.x + threadIdx.x;
    if (i >= n4) return;
    float4 v = ((const float4*)x)[i];
    __nv_bfloat162* hp = (__nv_bfloat162*)h;
    hp[2*i]   = __floats2bfloat162_rn(v.x, v.y);
    hp[2*i+1] = __floats2bfloat162_rn(v.z, v.w);
}

// ---------------------------------------------------------------------------
// pack W [K,N] fp32 -> k-pair bf16x2 [k2][n]: hi/lo, or hi-only
// ---------------------------------------------------------------------------
__global__ __launch_bounds__(256) void pack_w_kernel(
    const float* __restrict__ W, uint32_t* __restrict__ Ph,
    uint32_t* __restrict__ Pl)
{
    int i = blockIdx.x * blockDim.x + threadIdx.x;
    if (i >= (DD/2) * DD) return;
    int k2 = i >> 10, n = i & (DD - 1);
    float w0 = W[(size_t)(2*k2)     * DD + n];
    float w1 = W[(size_t)(2*k2 + 1) * DD + n];
    __nv_bfloat16 h0 = __float2bfloat16(w0);
    __nv_bfloat16 h1 = __float2bfloat16(w1);
    Ph[i] = pack_bf2(w0, w1);
    Pl[i] = pack_bf2(w0 - __bfloat162float(h0), w1 - __bfloat162float(h1));
}

__global__ __launch_bounds__(256) void pack_wh_kernel(
    const float* __restrict__ W, uint32_t* __restrict__ Ph)
{
    int i = blockIdx.x * blockDim.x + threadIdx.x;
    if (i >= (DD/2) * DD) return;
    int k2 = i >> 10, n = i & (DD - 1);
    Ph[i] = pack_bf2(W[(size_t)(2*k2) * DD + n], W[(size_t)(2*k2 + 1) * DD + n]);
}

// ---------------------------------------------------------------------------
// build Vp (hi only): Vp[bh][k2][d] = bf16x2{ V[2k2,d]*zi0, V[2k2+1,d]*zi1 }
// ---------------------------------------------------------------------------
__global__ __launch_bounds__(256) void build_vp_kernel(
    const float* __restrict__ V, const float* __restrict__ Zi,
    uint32_t* __restrict__ Ph)
{
    int i = blockIdx.x * blockDim.x + threadIdx.x;
    const int total = BB * HH * (LL/2) * HDIM;
    if (i >= total) return;
    int bh = i >> 15;
    int r  = (i >> 6) & 511;
    int d  = i & 63;
    int b = bh >> 4, h = bh & 15;
    float zi0 = Zi[(size_t)bh * LL + 2*r];
    float zi1 = Zi[(size_t)bh * LL + 2*r + 1];
    float v0 = V[((size_t)b * LL + 2*r)     * DD + h * HDIM + d] * zi0;
    float v1 = V[((size_t)b * LL + 2*r + 1) * DD + h * HDIM + d] * zi1;
    Ph[i] = pack_bf2(v0, v1);
}

// ---------------------------------------------------------------------------
// sz[bh] = sum_k zinv[bh,k]
// ---------------------------------------------------------------------------
__global__ __launch_bounds__(256) void sumz_kernel(
    const float* __restrict__ Zi, float* __restrict__ Sz)
{
    __shared__ float red[256];
    const int bh = blockIdx.x;
    const int tid = threadIdx.x;
    float s = 0.0f;
    #pragma unroll
    for (int p = 0; p < 4; p++) s += Zi[(size_t)bh * LL + tid + p * 256];
    red[tid] = s;
    __syncthreads();
    for (int w = 128; w > 0; w >>= 1) {
        if (tid < w) red[tid] += red[tid + w];
        __syncthreads();
    }
    if (tid == 0) Sz[bh] = red[0];
}

// ---------------------------------------------------------------------------
// s_x[bh][d'] = sum_k x_v[b,k,d'] * zinv[bh,k]   (exact fp32)
// grid (8 b, 16 dchunk64), block 256 = 64 d x 4 k-slice.
// dyn smem: szi[16][1024] fp32 = 65536 B (red overlays first 16 KB after use)
// ---------------------------------------------------------------------------
__global__ __launch_bounds__(256) void sx_kernel(
    const float* __restrict__ xv, const float* __restrict__ Zi,
    float* __restrict__ Sx)
{
    extern __shared__ float szi[];   // [16][1024]
    const int b = blockIdx.x;
    const int dc = blockIdx.y;       // 0..15
    const int tid = threadIdx.x;
    const int d = tid & 63;
    const int s = tid >> 6;          // k-slice 0..3

    // stage zinv rows for this batch: 16 h x 1024 k
    for (int i = tid; i < 16 * 1024; i += 256)
        szi[i] = Zi[(size_t)(b * 16) * LL + i];
    __syncthreads();

    float acc[16];
    #pragma unroll
    for (int h = 0; h < 16; h++) acc[h] = 0.0f;

    const int dglob = dc * 64 + d;
    const int k0 = s * 256;
    for (int k = k0; k < k0 + 256; k++) {
        float x = xv[((size_t)b * LL + k) * DD + dglob];
        #pragma unroll
        for (int h = 0; h < 16; h++)
            acc[h] = fmaf(x, szi[h * 1024 + k], acc[h]);
    }
    __syncthreads();
    // reduce 4 slices via smem (overlay szi)
    float* red = szi;   // [4][16][64]
    #pragma unroll
    for (int h = 0; h < 16; h++)
        red[(s * 16 + h) * 64 + d] = acc[h];
    __syncthreads();
    // 1024 outputs (16 h x 64 d), 256 threads -> 4 each
    for (int i = tid; i < 16 * 64; i += 256) {
        int h = i >> 6, dd = i & 63;
        float v = red[(0 * 16 + h) * 64 + dd] + red[(1 * 16 + h) * 64 + dd]
                + red[(2 * 16 + h) * 64 + dd] + red[(3 * 16 + h) * 64 + dd];
        Sx[(size_t)(b * 16 + h) * DD + dc * 64 + dd] = v;
    }
}

// ---------------------------------------------------------------------------
// Sv[bh][d] = sum_{d'} s_x[bh][d'] * Wv[d'][h*64+d] + bv[h*64+d]*sz[bh]
// grid (128 bh), block 256 = 64 d x 4 k-slice
// ---------------------------------------------------------------------------
__global__ __launch_bounds__(256) void sv_kernel(
    const float* __restrict__ Sx, const float* __restrict__ Wv,
    const float* __restrict__ bv, const float* __restrict__ Sz,
    float* __restrict__ Sv)
{
    __shared__ float sxr[1024];
    __shared__ float red[4 * 64];
    const int bh = blockIdx.x;
    const int h = bh & 15;
    const int tid = threadIdx.x;
    const int d = tid & 63;
    const int s = tid >> 6;

    for (int i = tid; i < 1024; i += 256)
        sxr[i] = Sx[(size_t)bh * DD + i];
    __syncthreads();

    float acc = 0.0f;
    const int k0 = s * 256;
    const int col = h * HDIM + d;
    for (int k = k0; k < k0 + 256; k++)
        acc = fmaf(sxr[k], Wv[(size_t)k * DD + col], acc);
    red[s * 64 + d] = acc;
    __syncthreads();
    if (tid < 64)
        Sv[(size_t)bh * HDIM + d] =
            red[d] + red[64 + d] + red[128 + d] + red[192 + d] + bv[col] * Sz[bh];
}

// ---------------------------------------------------------------------------
// Single-pass bf16 HMMA GEMM (for Q/K/V projections).
// mode 0: fp32 C = A@W + bias.  mode 1: bf16 Hout = (A@W + bias)*oscale.
// SMEM per buffer: A 18432 + B 16896 = 35328; x2 = 70656 -> 2 CTAs/SM.
// ---------------------------------------------------------------------------
#define F_AH   0
#define F_BH   18432
#define F_BUF  35328
#define F_SMEM (2 * F_BUF)

__device__ __forceinline__ void gemm1p_load(
    uint32_t sb0, int buf, int tid, int m0, int n0, int kt,
    const __nv_bfloat16* __restrict__ Ah, const uint32_t* __restrict__ Bh)
{
    const uint32_t sb = sb0 + buf * F_BUF;
    #pragma unroll
    for (int p = 0; p < 4; p++) {
        const int idx = tid + p * 256;
        const int r = idx >> 3, c = idx & 7;
        const size_t g = (size_t)(m0 + r) * DD + kt * 64 + c * 8;
        CP_ASYNC16(sb + F_AH + r * 144 + c * 16, Ah + g);
    }
    #pragma unroll
    for (int p = 0; p < 4; p++) {
        const int idx = tid + p * 256;
        const int r = idx >> 5, c = idx & 31;
        const size_t g = (size_t)(kt * 32 + r) * DD + n0 + c * 4;
        CP_ASYNC16(sb + F_BH + r * 528 + c * 16, Bh + g);
    }
}

__global__ __launch_bounds__(256, 2) void tc_gemm_1p_kernel(
    const __nv_bfloat16* __restrict__ Ah, const uint32_t* __restrict__ Bh,
    const float* __restrict__ bias, float* __restrict__ C,
    __nv_bfloat16* __restrict__ Hout, float oscale, int mode)
{
    extern __shared__ char sm[];
    const uint32_t smem_base = smem_u32(sm);
    const int tid = threadIdx.x;
    const int wid = tid >> 5;
    const int lane = tid & 31;
    const int g = lane >> 2;
    const int t = lane & 3;
    const int wm = wid >> 2;
    const int wn = wid & 3;
    const int n0 = blockIdx.x * 128;
    const int m0 = blockIdx.y * 128;

    float c[4][4][4];
    #pragma unroll
    for (int i = 0; i < 4; i++)
        #pragma unroll
        for (int j = 0; j < 4; j++)
            #pragma unroll
            for (int q = 0; q < 4; q++) c[i][j][q] = 0.0f;

    gemm1p_load(smem_base, 0, tid, m0, n0, 0, Ah, Bh);
    CP_COMMIT();

    for (int kt = 0; kt < 16; kt++) {
        const int buf = kt & 1;
        if (kt < 15) {
            gemm1p_load(smem_base, buf ^ 1, tid, m0, n0, kt + 1, Ah, Bh);
            CP_COMMIT();
            CP_WAIT(1);
        } else {
            CP_WAIT(0);
        }
        __syncthreads();

        const char* Ab = sm + buf * F_BUF + F_AH;
        const char* Bb = sm + buf * F_BUF + F_BH;

        #pragma unroll
        for (int ks = 0; ks < 4; ks++) {
            uint32_t aH[4][4], bH[4][2];
            #pragma unroll
            for (int i = 0; i < 4; i++) {
                const int off = (wm * 64 + i * 16 + g) * 144 + ks * 32 + t * 4;
                aH[i][0] = *(const uint32_t*)(Ab + off);
                aH[i][1] = *(const uint32_t*)(Ab + off + 8 * 144);
                aH[i][2] = *(const uint32_t*)(Ab + off + 16);
                aH[i][3] = *(const uint32_t*)(Ab + off + 8 * 144 + 16);
            }
            #pragma unroll
            for (int j = 0; j < 4; j++) {
                const int off = (ks * 8 + t) * 528 + (wn * 32 + j * 8 + g) * 4;
                bH[j][0] = *(const uint32_t*)(Bb + off);
                bH[j][1] = *(const uint32_t*)(Bb + off + 4 * 528);
            }
            #pragma unroll
            for (int i = 0; i < 4; i++)
                #pragma unroll
                for (int j = 0; j < 4; j++)
                    mma16816(c[i][j], aH[i][0], aH[i][1], aH[i][2], aH[i][3],
                             bH[j][0], bH[j][1]);
        }
        __syncthreads();
    }

    #pragma unroll
    for (int j = 0; j < 4; j++) {
        const int col = n0 + wn * 32 + j * 8 + 2 * t;
        const float2 bv = *(const float2*)(bias + col);
        #pragma unroll
        for (int i = 0; i < 4; i++) {
            const int row = m0 + wm * 64 + i * 16 + g;
            float v0 = c[i][j][0] + bv.x, v1 = c[i][j][1] + bv.y;
            float v2 = c[i][j][2] + bv.x, v3 = c[i][j][3] + bv.y;
            if (mode == 0) {
                float* o = C + (size_t)row * DD + col;
                *(float2*)o = make_float2(v0, v1);
                *(float2*)(o + 8 * DD) = make_float2(v2, v3);
            } else {
                *(uint32_t*)(Hout + (size_t)row * DD + col) =
                    pack_bf2(v0 * oscale, v1 * oscale);
                *(uint32_t*)(Hout + (size_t)(row + 8) * DD + col) =
                    pack_bf2(v2 * oscale, v3 * oscale);
            }
        }
    }
}

// ---------------------------------------------------------------------------
// 3-pass split-bf16 HMMA GEMM (output projection only)
// ---------------------------------------------------------------------------
#define SM_AH   0
#define SM_AL   18432
#define SM_BH   36864
#define SM_BL   53760
#define SM_BUF  70656
#define GEMM_SMEM (2 * SM_BUF)

__device__ __forceinline__ void gemm_load_tiles(
    char* sm, uint32_t smem_base, int buf, int tid, int m0, int n0, int kt,
    const __nv_bfloat16* __restrict__ Ah, const __nv_bfloat16* __restrict__ Al,
    const uint32_t* __restrict__ Bh, const uint32_t* __restrict__ Bl)
{
    const uint32_t sb = smem_base + buf * SM_BUF;
    #pragma unroll
    for (int p = 0; p < 4; p++) {
        const int idx = tid + p * 256;
        const int r = idx >> 3, c = idx & 7;
        const size_t g = (size_t)(m0 + r) * DD + kt * 64 + c * 8;
        const uint32_t d = r * 144 + c * 16;
        CP_ASYNC16(sb + SM_AH + d, Ah + g);
        CP_ASYNC16(sb + SM_AL + d, Al + g);
    }
    #pragma unroll
    for (int p = 0; p < 4; p++) {
        const int idx = tid + p * 256;
        const int r = idx >> 5, c = idx & 31;
        const size_t g = (size_t)(kt * 32 + r) * DD + n0 + c * 4;
        const uint32_t d = r * 528 + c * 16;
        CP_ASYNC16(sb + SM_BH + d, Bh + g);
        CP_ASYNC16(sb + SM_BL + d, Bl + g);
    }
}

__global__ __launch_bounds__(256, 1) void tc_gemm_split_kernel(
    const __nv_bfloat16* __restrict__ Ah, const __nv_bfloat16* __restrict__ Al,
    const uint32_t* __restrict__ Bh, const uint32_t* __restrict__ Bl,
    const float* __restrict__ bias, float* __restrict__ C)
{
    extern __shared__ char sm[];
    const uint32_t smem_base = smem_u32(sm);
    const int tid = threadIdx.x;
    const int wid = tid >> 5;
    const int lane = tid & 31;
    const int g = lane >> 2;
    const int t = lane & 3;
    const int wm = wid >> 2;
    const int wn = wid & 3;
    const int n0 = blockIdx.x * 128;
    const int m0 = blockIdx.y * 128;

    float c[4][4][4];
    #pragma unroll
    for (int i = 0; i < 4; i++)
        #pragma unroll
        for (int j = 0; j < 4; j++)
            #pragma unroll
            for (int q = 0; q < 4; q++) c[i][j][q] = 0.0f;

    gemm_load_tiles(sm, smem_base, 0, tid, m0, n0, 0, Ah, Al, Bh, Bl);
    CP_COMMIT();

    for (int kt = 0; kt < 16; kt++) {
        const int buf = kt & 1;
        if (kt < 15) {
            gemm_load_tiles(sm, smem_base, buf ^ 1, tid, m0, n0, kt + 1, Ah, Al, Bh, Bl);
            CP_COMMIT();
            CP_WAIT(1);
        } else {
            CP_WAIT(0);
        }
        __syncthreads();

        const char* Abh = sm + buf * SM_BUF + SM_AH;
        const char* Abl = sm + buf * SM_BUF + SM_AL;
        const char* Bbh = sm + buf * SM_BUF + SM_BH;
        const char* Bbl = sm + buf * SM_BUF + SM_BL;

        #pragma unroll
        for (int ks = 0; ks < 4; ks++) {
            uint32_t aH[4][4], aL[4][4], bH[4][2], bL[4][2];
            #pragma unroll
            for (int i = 0; i < 4; i++) {
                const int off = (wm * 64 + i * 16 + g) * 144 + ks * 32 + t * 4;
                aH[i][0] = *(const uint32_t*)(Abh + off);
                aH[i][1] = *(const uint32_t*)(Abh + off + 8 * 144);
                aH[i][2] = *(const uint32_t*)(Abh + off + 16);
                aH[i][3] = *(const uint32_t*)(Abh + off + 8 * 144 + 16);
                aL[i][0] = *(const uint32_t*)(Abl + off);
                aL[i][1] = *(const uint32_t*)(Abl + off + 8 * 144);
                aL[i][2] = *(const uint32_t*)(Abl + off + 16);
                aL[i][3] = *(const uint32_t*)(Abl + off + 8 * 144 + 16);
            }
            #pragma unroll
            for (int j = 0; j < 4; j++) {
                const int off = (ks * 8 + t) * 528 + (wn * 32 + j * 8 + g) * 4;
                bH[j][0] = *(const uint32_t*)(Bbh + off);
                bH[j][1] = *(const uint32_t*)(Bbh + off + 4 * 528);
                bL[j][0] = *(const uint32_t*)(Bbl + off);
                bL[j][1] = *(const uint32_t*)(Bbl + off + 4 * 528);
            }
            #pragma unroll
            for (int i = 0; i < 4; i++)
                #pragma unroll
                for (int j = 0; j < 4; j++)
                    mma16816(c[i][j], aH[i][0], aH[i][1], aH[i][2], aH[i][3],
                             bH[j][0], bH[j][1]);
            #pragma unroll
            for (int i = 0; i < 4; i++)
                #pragma unroll
                for (int j = 0; j < 4; j++)
                    mma16816(c[i][j], aH[i][0], aH[i][1], aH[i][2], aH[i][3],
                             bL[j][0], bL[j][1]);
            #pragma unroll
            for (int i = 0; i < 4; i++)
                #pragma unroll
                for (int j = 0; j < 4; j++)
                    mma16816(c[i][j], aL[i][0], aL[i][1], aL[i][2], aL[i][3],
                             bH[j][0], bH[j][1]);
        }
        __syncthreads();
    }

    #pragma unroll
    for (int j = 0; j < 4; j++) {
        const int col = n0 + wn * 32 + j * 8 + 2 * t;
        const float2 bv = *(const float2*)(bias + col);
        #pragma unroll
        for (int i = 0; i < 4; i++) {
            const int row = m0 + wm * 64 + i * 16 + g;
            float* o = C + (size_t)row * DD + col;
            *(float2*)o = make_float2(c[i][j][0] + bv.x, c[i][j][1] + bv.y);
            *(float2*)(o + 8 * DD) = make_float2(c[i][j][2] + bv.x, c[i][j][3] + bv.y);
        }
    }
}

// ---------------------------------------------------------------------------
// HMMA colsum (single-pass bf16): zinv[bh,k] = 1 / sum_q exp(S_qk)
// ---------------------------------------------------------------------------
#define CS_KH  0
#define CS_QH  18432
#define CS_RED 36864
#define CS_SMEM 37888

__global__ __launch_bounds__(256, 2) void attn_colsum_tc(
    const __nv_bfloat16* __restrict__ Qh, const __nv_bfloat16* __restrict__ Kh,
    float* __restrict__ zinv)
{
    extern __shared__ char sm[];
    const uint32_t sb = smem_u32(sm);
    const int tid = threadIdx.x;
    const int wid = tid >> 5;
    const int lane = tid & 31;
    const int g = lane >> 2;
    const int t = lane & 3;
    const int wm = wid >> 2;
    const int wn = wid & 3;
    const int kt = blockIdx.x;
    const int bh = blockIdx.y;
    const int b = bh >> 4, h = bh & 15;

    #pragma unroll
    for (int p = 0; p < 4; p++) {
        const int idx = tid + p * 256;
        const int r = idx >> 3, c = idx & 7;
        const size_t go = ((size_t)(b * LL + kt * 128 + r)) * DD + h * HDIM + c * 8;
        CP_ASYNC16(sb + CS_KH + r * 144 + c * 16, Kh + go);
    }
    #pragma unroll
    for (int p = 0; p < 4; p++) {
        const int idx = tid + p * 256;
        const int r = idx >> 3, c = idx & 7;
        const size_t go = ((size_t)(b * LL + r)) * DD + h * HDIM + c * 8;
        CP_ASYNC16(sb + CS_QH + r * 144 + c * 16, Qh + go);
    }
    CP_COMMIT();

    float cs[4][2];
    #pragma unroll
    for (int j = 0; j < 4; j++) { cs[j][0] = 0.0f; cs[j][1] = 0.0f; }

    for (int qt = 0; qt < 8; qt++) {
        CP_WAIT(0);
        __syncthreads();

        float acc[4][4][4];
        #pragma unroll
        for (int i = 0; i < 4; i++)
            #pragma unroll
            for (int j = 0; j < 4; j++)
                #pragma unroll
                for (int q = 0; q < 4; q++) acc[i][j][q] = 0.0f;

        #pragma unroll
        for (int ks = 0; ks < 4; ks++) {
            uint32_t aH[4][4], bH[4][2];
            #pragma unroll
            for (int i = 0; i < 4; i++) {
                const int off = (wm * 64 + i * 16 + g) * 144 + ks * 32 + t * 4;
                aH[i][0] = *(const uint32_t*)(sm + CS_QH + off);
                aH[i][1] = *(const uint32_t*)(sm + CS_QH + off + 8 * 144);
                aH[i][2] = *(const uint32_t*)(sm + CS_QH + off + 16);
                aH[i][3] = *(const uint32_t*)(sm + CS_QH + off + 8 * 144 + 16);
            }
            #pragma unroll
            for (int j = 0; j < 4; j++) {
                const int off = (wn * 32 + j * 8 + g) * 144 + ks * 32 + t * 4;
                bH[j][0] = *(const uint32_t*)(sm + CS_KH + off);
                bH[j][1] = *(const uint32_t*)(sm + CS_KH + off + 16);
            }
            #pragma unroll
            for (int i = 0; i < 4; i++)
                #pragma unroll
                for (int j = 0; j < 4; j++)
                    mma16816(acc[i][j], aH[i][0], aH[i][1], aH[i][2], aH[i][3],
                             bH[j][0], bH[j][1]);
        }

        #pragma unroll
        for (int i = 0; i < 4; i++)
            #pragma unroll
            for (int j = 0; j < 4; j++) {
                cs[j][0] += __expf(acc[i][j][0]) + __expf(acc[i][j][2]);
                cs[j][1] += __expf(acc[i][j][1]) + __expf(acc[i][j][3]);
            }

        __syncthreads();
        if (qt < 7) {
            #pragma unroll
            for (int p = 0; p < 4; p++) {
                const int idx = tid + p * 256;
                const int r = idx >> 3, c = idx & 7;
                const size_t go = ((size_t)(b * LL + (qt + 1) * 128 + r)) * DD + h * HDIM + c * 8;
                CP_ASYNC16(sb + CS_QH + r * 144 + c * 16, Qh + go);
            }
            CP_COMMIT();
        }
    }

    float* red = (float*)(sm + CS_RED);
    #pragma unroll
    for (int j = 0; j < 4; j++)
        #pragma unroll
        for (int hh = 0; hh < 2; hh++) {
            float v = cs[j][hh];
            v += __shfl_down_sync(0xffffffffu, v, 16);
            v += __shfl_down_sync(0xffffffffu, v, 8);
            v += __shfl_down_sync(0xffffffffu, v, 4);
            if (g == 0) red[wid * 32 + j * 8 + 2 * t + hh] = v;
        }
    __syncthreads();
    if (tid < 128) {
        const int col = tid;
        const int w2 = col >> 5, cl = col & 31;
        zinv[(size_t)bh * LL + kt * 128 + col] =
            1.0f / (red[w2 * 32 + cl] + red[(w2 + 4) * 32 + cl]);
    }
}

// ---------------------------------------------------------------------------
// HMMA AV (E = 1 + e): out = Sv + sum_k e * Vp; writes split bf16 output
// ---------------------------------------------------------------------------
#define AV_QH   0
#define AV_KH   18432
#define AV_E    36864
#define AV_VP0  71680
#define AV_VPB  17408
#define AV_SMEM 106496

__device__ __forceinline__ void av_load_kvp(
    uint32_t sb, int tid, int b, int h, int bh, int kt, int buf,
    const __nv_bfloat16* __restrict__ Kh, const uint32_t* __restrict__ Vph)
{
    #pragma unroll
    for (int p = 0; p < 4; p++) {
        const int idx = tid + p * 256;
        const int r = idx >> 3, c = idx & 7;
        const size_t go = ((size_t)(b * LL + kt * 128 + r)) * DD + h * HDIM + c * 8;
        CP_ASYNC16(sb + AV_KH + r * 144 + c * 16, Kh + go);
    }
    const uint32_t vb = sb + AV_VP0 + buf * AV_VPB;
    #pragma unroll
    for (int p = 0; p < 4; p++) {
        const int idx = tid + p * 256;
        const int r = idx >> 4, c = idx & 15;
        const size_t go = ((size_t)bh * 512 + kt * 64 + r) * 64 + c * 4;
        CP_ASYNC16(vb + r * 272 + c * 16, Vph + go);
    }
}

__global__ __launch_bounds__(256, 1) void attn_av_tc(
    const __nv_bfloat16* __restrict__ Qh, const __nv_bfloat16* __restrict__ Kh,
    const uint32_t* __restrict__ Vph, const float* __restrict__ Sv,
    __nv_bfloat16* __restrict__ Oh, __nv_bfloat16* __restrict__ Ol)
{
    extern __shared__ char sm[];
    const uint32_t sb = smem_u32(sm);
    const int tid = threadIdx.x;
    const int wid = tid >> 5;
    const int lane = tid & 31;
    const int g = lane >> 2;
    const int t = lane & 3;
    const int wm = wid >> 2;
    const int wn = wid & 3;
    const int qt = blockIdx.x;
    const int bh = blockIdx.y;
    const int b = bh >> 4, h = bh & 15;

    #pragma unroll
    for (int p = 0; p < 4; p++) {
        const int idx = tid + p * 256;
        const int r = idx >> 3, c = idx & 7;
        const size_t go = ((size_t)(b * LL + qt * 128 + r)) * DD + h * HDIM + c * 8;
        CP_ASYNC16(sb + AV_QH + r * 144 + c * 16, Qh + go);
    }
    av_load_kvp(sb, tid, b, h, bh, 0, 0, Kh, Vph);
    CP_COMMIT();

    float out[4][2][4];
    #pragma unroll
    for (int i = 0; i < 4; i++)
        #pragma unroll
        for (int j = 0; j < 2; j++)
            #pragma unroll
            for (int q = 0; q < 4; q++) out[i][j][q] = 0.0f;

    for (int kt = 0; kt < 8; kt++) {
        const int buf = kt & 1;
        CP_WAIT(0);
        __syncthreads();

        float acc[4][4][4];
        #pragma unroll
        for (int i = 0; i < 4; i++)
            #pragma unroll
            for (int j = 0; j < 4; j++)
                #pragma unroll
                for (int q = 0; q < 4; q++) acc[i][j][q] = 0.0f;

        #pragma unroll
        for (int ks = 0; ks < 4; ks++) {
            uint32_t aH[4][4], bH[4][2];
            #pragma unroll
            for (int i = 0; i < 4; i++) {
                const int off = (wm * 64 + i * 16 + g) * 144 + ks * 32 + t * 4;
                aH[i][0] = *(const uint32_t*)(sm + AV_QH + off);
                aH[i][1] = *(const uint32_t*)(sm + AV_QH + off + 8 * 144);
                aH[i][2] = *(const uint32_t*)(sm + AV_QH + off + 16);
                aH[i][3] = *(const uint32_t*)(sm + AV_QH + off + 8 * 144 + 16);
            }
            #pragma unroll
            for (int j = 0; j < 4; j++) {
                const int off = (wn * 32 + j * 8 + g) * 144 + ks * 32 + t * 4;
                bH[j][0] = *(const uint32_t*)(sm + AV_KH + off);
                bH[j][1] = *(const uint32_t*)(sm + AV_KH + off + 16);
            }
            #pragma unroll
            for (int i = 0; i < 4; i++)
                #pragma unroll
                for (int j = 0; j < 4; j++)
                    mma16816(acc[i][j], aH[i][0], aH[i][1], aH[i][2], aH[i][3],
                             bH[j][0], bH[j][1]);
        }

        #pragma unroll
        for (int i = 0; i < 4; i++) {
            const int row = wm * 64 + i * 16 + g;
            #pragma unroll
            for (int j = 0; j < 4; j++) {
                const int colb = (wn * 32 + j * 8 + 2 * t) * 2;
                float e0 = __expf(acc[i][j][0]) - 1.0f;
                float e1 = __expf(acc[i][j][1]) - 1.0f;
                float e2 = __expf(acc[i][j][2]) - 1.0f;
                float e3 = __expf(acc[i][j][3]) - 1.0f;
                *(uint32_t*)(sm + AV_E + row * 272 + colb) = pack_bf2(e0, e1);
                *(uint32_t*)(sm + AV_E + (row + 8) * 272 + colb) = pack_bf2(e2, e3);
            }
        }
        __syncthreads();

        if (kt < 7) {
            av_load_kvp(sb, tid, b, h, bh, kt + 1, buf ^ 1, Kh, Vph);
            CP_COMMIT();
        }

        const char* VH = sm + AV_VP0 + buf * AV_VPB;
        #pragma unroll
        for (int ks = 0; ks < 8; ks++) {
            uint32_t aE[4][4], bV[2][2];
            #pragma unroll
            for (int i = 0; i < 4; i++) {
                const int off = (wm * 64 + i * 16 + g) * 272 + ks * 32 + t * 4;
                aE[i][0] = *(const uint32_t*)(sm + AV_E + off);
                aE[i][1] = *(const uint32_t*)(sm + AV_E + off + 8 * 272);
                aE[i][2] = *(const uint32_t*)(sm + AV_E + off + 16);
                aE[i][3] = *(const uint32_t*)(sm + AV_E + off + 8 * 272 + 16);
            }
            #pragma unroll
            for (int j = 0; j < 2; j++) {
                const int off = (ks * 8 + t) * 272 + (wn * 16 + j * 8 + g) * 4;
                bV[j][0] = *(const uint32_t*)(VH + off);
                bV[j][1] = *(const uint32_t*)(VH + off + 4 * 272);
            }
            #pragma unroll
            for (int i = 0; i < 4; i++)
                #pragma unroll
                for (int j = 0; j < 2; j++)
                    mma16816(out[i][j], aE[i][0], aE[i][1], aE[i][2], aE[i][3],
                             bV[j][0], bV[j][1]);
        }
        __syncthreads();
    }

    #pragma unroll
    for (int i = 0; i < 4; i++) {
        const int row = qt * 128 + wm * 64 + i * 16 + g;
        #pragma unroll
        for (int j = 0; j < 2; j++) {
            const int dcol = wn * 16 + j * 8 + 2 * t;
            const float sv0 = Sv[(size_t)bh * HDIM + dcol];
            const float sv1 = Sv[(size_t)bh * HDIM + dcol + 1];
            const size_t o0 = ((size_t)b * LL + row) * DD + h * HDIM + dcol;
            const size_t o1 = ((size_t)b * LL + row + 8) * DD + h * HDIM + dcol;
            float v0 = out[i][j][0] + sv0, v1 = out[i][j][1] + sv1;
            float v2 = out[i][j][2] + sv0, v3 = out[i][j][3] + sv1;
            __nv_bfloat16 h0 = __float2bfloat16(v0);
            __nv_bfloat16 h1 = __float2bfloat16(v1);
            __nv_bfloat16 h2 = __float2bfloat16(v2);
            __nv_bfloat16 h3 = __float2bfloat16(v3);
            *(uint32_t*)(Oh + o0) = pack_bf2(v0, v1);
            *(uint32_t*)(Oh + o1) = pack_bf2(v2, v3);
            *(uint32_t*)(Ol + o0) =
                pack_bf2(v0 - __bfloat162float(h0), v1 - __bfloat162float(h1));
            *(uint32_t*)(Ol + o1) =
                pack_bf2(v2 - __bfloat162float(h2), v3 - __bfloat162float(h3));
        }
    }
}

// ---------------------------------------------------------------------------
// Launch
// ---------------------------------------------------------------------------
extern "C" void kernel_launch(void* const* d_in, const int* in_sizes, int n_in,
                              void* d_out, int out_size)
{
    (void)in_sizes; (void)n_in; (void)out_size;

    const float* x_q = (const float*)d_in[0];
    const float* x_k = (const float*)d_in[1];
    const float* x_v = (const float*)d_in[2];
    // d_in[3] = mask: unused (reference never applies it)
    const float* Wq  = (const float*)d_in[4];
    const float* bq  = (const float*)d_in[5];
    const float* Wk  = (const float*)d_in[6];
    const float* bk  = (const float*)d_in[7];
    const float* Wv  = (const float*)d_in[8];
    const float* bv  = (const float*)d_in[9];
    const float* Wo  = (const float*)d_in[10];
    const float* bo  = (const float*)d_in[11];

    float *pV, *pZi, *pSz, *pSx, *pSv;
    __nv_bfloat16 *pAh, *pAl, *pQh, *pKh;
    uint32_t *pWh, *pWl, *pVh;
    cudaGetSymbolAddress((void**)&pV, g_V);
    cudaGetSymbolAddress((void**)&pZi, g_zinv);
    cudaGetSymbolAddress((void**)&pSz, g_sz);
    cudaGetSymbolAddress((void**)&pSx, g_sx);
    cudaGetSymbolAddress((void**)&pSv, g_Sv);
    cudaGetSymbolAddress((void**)&pAh, g_Ah);
    cudaGetSymbolAddress((void**)&pAl, g_Al);
    cudaGetSymbolAddress((void**)&pWh, g_Wph);
    cudaGetSymbolAddress((void**)&pWl, g_Wpl);
    cudaGetSymbolAddress((void**)&pQh, g_Qh);
    cudaGetSymbolAddress((void**)&pKh, g_Kh);
    cudaGetSymbolAddress((void**)&pVh, g_Vph);

    cudaFuncSetAttribute(tc_gemm_1p_kernel,
                         cudaFuncAttributeMaxDynamicSharedMemorySize, F_SMEM);
    cudaFuncSetAttribute(tc_gemm_split_kernel,
                         cudaFuncAttributeMaxDynamicSharedMemorySize, GEMM_SMEM);
    cudaFuncSetAttribute(attn_colsum_tc,
                         cudaFuncAttributeMaxDynamicSharedMemorySize, CS_SMEM);
    cudaFuncSetAttribute(attn_av_tc,
                         cudaFuncAttributeMaxDynamicSharedMemorySize, AV_SMEM);
    cudaFuncSetAttribute(sx_kernel,
                         cudaFuncAttributeMaxDynamicSharedMemorySize, 65536);

    const int n4 = MTOT * DD / 4;
    const dim3 gSplit((n4 + 255) / 256), t256(256);
    const int npack = (DD / 2) * DD;
    const dim3 gPack((npack + 255) / 256);
    const dim3 gGemm(DD / 128, MTOT / 128);

    // Q projection (1-pass) -> Qh scaled by 1/32
    tobf16_kernel<<<gSplit, t256>>>(x_q, pAh, n4);
    pack_wh_kernel<<<gPack, t256>>>(Wq, pWh);
    tc_gemm_1p_kernel<<<gGemm, 256, F_SMEM>>>(
        pAh, pWh, bq, nullptr, pQh, 0.03125f, 1);
    // K projection (1-pass) -> Kh
    tobf16_kernel<<<gSplit, t256>>>(x_k, pAh, n4);
    pack_wh_kernel<<<gPack, t256>>>(Wk, pWh);
    tc_gemm_1p_kernel<<<gGemm, 256, F_SMEM>>>(
        pAh, pWh, bk, nullptr, pKh, 1.0f, 1);
    // V projection (1-pass) -> fp32 V
    tobf16_kernel<<<gSplit, t256>>>(x_v, pAh, n4);
    pack_wh_kernel<<<gPack, t256>>>(Wv, pWh);
    tc_gemm_1p_kernel<<<gGemm, 256, F_SMEM>>>(
        pAh, pWh, bv, pV, nullptr, 1.0f, 0);

    // zinv = 1 / column-softmax sums
    attn_colsum_tc<<<dim3(8, BB * HH), 256, CS_SMEM>>>(pQh, pKh, pZi);

    // Exact Sv via commuted identity: Sv = (sum_k x_v zi) @ Wv + bv * sum(zi)
    sumz_kernel<<<BB * HH, 256>>>(pZi, pSz);
    sx_kernel<<<dim3(BB, 16), 256, 65536>>>(x_v, pZi, pSx);
    sv_kernel<<<BB * HH, 256>>>(pSx, Wv, bv, pSz, pSv);

    // Vp (hi) from V
    const int nvp = BB * HH * (LL / 2) * HDIM;
    build_vp_kernel<<<(nvp + 255) / 256, t256>>>(pV, pZi, pVh);

    // AV -> split attention output in (Ah, Al)
    attn_av_tc<<<dim3(8, BB * HH), 256, AV_SMEM>>>(pQh, pKh, pVh, pSv, pAh, pAl);

    // Output projection (3-pass) -> d_out
    pack_w_kernel<<<gPack, t256>>>(Wo, pWh, pWl);
    tc_gemm_split_kernel<<<gGemm, 256, GEMM_SMEM>>>(
        pAh, pAl, pWh, pWl, bo, (float*)d_out);
}

// round 11
// speedup vs baseline: 5.3807x; 1.1661x over previous
#include <cuda_runtime.h>
#include <cuda_fp16.h>
#include <cstdint>
#include <math.h>

// Problem constants
#define BB   8
#define LL   1024
#define DD   1024
#define HH   16
#define HDIM 64
#define MTOT (BB*LL)

// ---------------------------------------------------------------------------
// Scratch (device globals)
// ---------------------------------------------------------------------------
__device__ float g_V[(size_t)MTOT * DD];            // 32 MB (V projection, fp32)
__device__ float g_zinv[(size_t)BB * HH * LL];      // 512 KB (1/Z)
__device__ float g_sz[(size_t)BB * HH];             // sum_k zinv
__device__ float g_sx[(size_t)BB * HH * DD];        // 512 KB (sum_k x_v * zinv)
__device__ float g_Sv[(size_t)BB * HH * HDIM];      // 32 KB  (exact sum_k V/Z)
__device__ __half g_Ah[(size_t)MTOT * DD];          // 16 MB (x fp16 / attn out fp16)
__device__ uint32_t g_Wph[(size_t)(DD/2) * DD];     // 2 MB  (W k-pair fp16x2)
__device__ __half g_Qh[(size_t)MTOT * DD];          // 16 MB (Q/32, fp16)
__device__ __half g_Kh[(size_t)MTOT * DD];          // 16 MB
__device__ uint32_t g_Vph[(size_t)BB * HH * (LL/2) * HDIM];  // 16 MB (1024*V/Z k-pair)

// ---------------------------------------------------------------------------
// Helpers
// ---------------------------------------------------------------------------
__device__ __forceinline__ void mma16816(float c[4],
    uint32_t a0, uint32_t a1, uint32_t a2, uint32_t a3,
    uint32_t b0, uint32_t b1)
{
    asm volatile(
        "mma.sync.aligned.m16n8k16.row.col.f32.f16.f16.f32 "
        "{%0,%1,%2,%3}, {%4,%5,%6,%7}, {%8,%9}, {%0,%1,%2,%3};"
        : "+f"(c[0]), "+f"(c[1]), "+f"(c[2]), "+f"(c[3])
        : "r"(a0), "r"(a1), "r"(a2), "r"(a3), "r"(b0), "r"(b1));
}

__device__ __forceinline__ uint32_t smem_u32(const void* p) {
    uint32_t a;
    asm("{ .reg .u64 t; cvta.to.shared.u64 t, %1; cvt.u32.u64 %0, t; }"
        : "=r"(a) : "l"(p));
    return a;
}

#define CP_ASYNC16(dst_u32, src_ptr) \
    asm volatile("cp.async.cg.shared.global [%0], [%1], 16;" \
        :: "r"(dst_u32), "l"(src_ptr) : "memory")
#define CP_COMMIT() asm volatile("cp.async.commit_group;" ::: "memory")
#define CP_WAIT(n)  asm volatile("cp.async.wait_group %0;" :: "n"(n) : "memory")

__device__ __forceinline__ uint32_t pack_h2(float x, float y) {
    __half2 p = __floats2half2_rn(x, y);   // .x = x (low half)
    return *(uint32_t*)&p;
}

// ---------------------------------------------------------------------------
// fp32 -> fp16
// ---------------------------------------------------------------------------
__global__ __launch_bounds__(256) void tof16_kernel(
    const float* __restrict__ x, __half* __restrict__ h, int n4)
{
    int i = blockIdx.x * blockDim.x + threadIdx.x;
    if (i >= n4) return;
    float4 v = ((const float4*)x)[i];
    __half2* hp = (__half2*)h;
    hp[2*i]   = __floats2half2_rn(v.x, v.y);
    hp[2*i+1] = __floats2half2_rn(v.z, v.w);
}

// ---------------------------------------------------------------------------
// pack W [K,N] fp32 -> k-pair fp16x2 [k2][n]
// ---------------------------------------------------------------------------
__global__ __launch_bounds__(256) void pack_wh_kernel(
    const float* __restrict__ W, uint32_t* __restrict__ Ph)
{
    int i = blockIdx.x * blockDim.x + threadIdx.x;
    if (i >= (DD/2) * DD) return;
    int k2 = i >> 10, n = i & (DD - 1);
    Ph[i] = pack_h2(W[(size_t)(2*k2) * DD + n], W[(size_t)(2*k2 + 1) * DD + n]);
}

// ---------------------------------------------------------------------------
// build Vp: Vp[bh][k2][d] = fp16x2{ 1024*V[2k2,d]*zi0, 1024*V[2k2+1,d]*zi1 }
// ---------------------------------------------------------------------------
__global__ __launch_bounds__(256) void build_vp_kernel(
    const float* __restrict__ V, const float* __restrict__ Zi,
    uint32_t* __restrict__ Ph)
{
    int i = blockIdx.x * blockDim.x + threadIdx.x;
    const int total = BB * HH * (LL/2) * HDIM;
    if (i >= total) return;
    int bh = i >> 15;
    int r  = (i >> 6) & 511;
    int d  = i & 63;
    int b = bh >> 4, h = bh & 15;
    float zi0 = Zi[(size_t)bh * LL + 2*r] * 1024.0f;
    float zi1 = Zi[(size_t)bh * LL + 2*r + 1] * 1024.0f;
    float v0 = V[((size_t)b * LL + 2*r)     * DD + h * HDIM + d] * zi0;
    float v1 = V[((size_t)b * LL + 2*r + 1) * DD + h * HDIM + d] * zi1;
    Ph[i] = pack_h2(v0, v1);
}

// ---------------------------------------------------------------------------
// sz[bh] = sum_k zinv[bh,k]
// ---------------------------------------------------------------------------
__global__ __launch_bounds__(256) void sumz_kernel(
    const float* __restrict__ Zi, float* __restrict__ Sz)
{
    __shared__ float red[256];
    const int bh = blockIdx.x;
    const int tid = threadIdx.x;
    float s = 0.0f;
    #pragma unroll
    for (int p = 0; p < 4; p++) s += Zi[(size_t)bh * LL + tid + p * 256];
    red[tid] = s;
    __syncthreads();
    for (int w = 128; w > 0; w >>= 1) {
        if (tid < w) red[tid] += red[tid + w];
        __syncthreads();
    }
    if (tid == 0) Sz[bh] = red[0];
}

// ---------------------------------------------------------------------------
// s_x[bh][d'] = sum_k x_v[b,k,d'] * zinv[bh,k]   (exact fp32)
// ---------------------------------------------------------------------------
__global__ __launch_bounds__(256) void sx_kernel(
    const float* __restrict__ xv, const float* __restrict__ Zi,
    float* __restrict__ Sx)
{
    extern __shared__ float szi[];   // [16][1024]
    const int b = blockIdx.x;
    const int dc = blockIdx.y;       // 0..15
    const int tid = threadIdx.x;
    const int d = tid & 63;
    const int s = tid >> 6;          // k-slice 0..3

    for (int i = tid; i < 16 * 1024; i += 256)
        szi[i] = Zi[(size_t)(b * 16) * LL + i];
    __syncthreads();

    float acc[16];
    #pragma unroll
    for (int h = 0; h < 16; h++) acc[h] = 0.0f;

    const int dglob = dc * 64 + d;
    const int k0 = s * 256;
    for (int k = k0; k < k0 + 256; k++) {
        float x = xv[((size_t)b * LL + k) * DD + dglob];
        #pragma unroll
        for (int h = 0; h < 16; h++)
            acc[h] = fmaf(x, szi[h * 1024 + k], acc[h]);
    }
    __syncthreads();
    float* red = szi;   // [4][16][64]
    #pragma unroll
    for (int h = 0; h < 16; h++)
        red[(s * 16 + h) * 64 + d] = acc[h];
    __syncthreads();
    for (int i = tid; i < 16 * 64; i += 256) {
        int h = i >> 6, dd = i & 63;
        float v = red[(0 * 16 + h) * 64 + dd] + red[(1 * 16 + h) * 64 + dd]
                + red[(2 * 16 + h) * 64 + dd] + red[(3 * 16 + h) * 64 + dd];
        Sx[(size_t)(b * 16 + h) * DD + dc * 64 + dd] = v;
    }
}

// ---------------------------------------------------------------------------
// Sv[bh][d] = sum_{d'} s_x[bh][d'] * Wv[d'][h*64+d] + bv[h*64+d]*sz[bh]
// ---------------------------------------------------------------------------
__global__ __launch_bounds__(256) void sv_kernel(
    const float* __restrict__ Sx, const float* __restrict__ Wv,
    const float* __restrict__ bv, const float* __restrict__ Sz,
    float* __restrict__ Sv)
{
    __shared__ float sxr[1024];
    __shared__ float red[4 * 64];
    const int bh = blockIdx.x;
    const int h = bh & 15;
    const int tid = threadIdx.x;
    const int d = tid & 63;
    const int s = tid >> 6;

    for (int i = tid; i < 1024; i += 256)
        sxr[i] = Sx[(size_t)bh * DD + i];
    __syncthreads();

    float acc = 0.0f;
    const int k0 = s * 256;
    const int col = h * HDIM + d;
    for (int k = k0; k < k0 + 256; k++)
        acc = fmaf(sxr[k], Wv[(size_t)k * DD + col], acc);
    red[s * 64 + d] = acc;
    __syncthreads();
    if (tid < 64)
        Sv[(size_t)bh * HDIM + d] =
            red[d] + red[64 + d] + red[128 + d] + red[192 + d] + bv[col] * Sz[bh];
}

// ---------------------------------------------------------------------------
// Single-pass fp16 HMMA GEMM (all 4 projections).
// mode 0: fp32 C = A@W + bias.  mode 1: fp16 Hout = (A@W + bias)*oscale.
// SMEM per buffer: A 18432 + B 16896 = 35328; x2 = 70656 -> 2 CTAs/SM.
// ---------------------------------------------------------------------------
#define F_AH   0
#define F_BH   18432
#define F_BUF  35328
#define F_SMEM (2 * F_BUF)

__device__ __forceinline__ void gemm1p_load(
    uint32_t sb0, int buf, int tid, int m0, int n0, int kt,
    const __half* __restrict__ Ah, const uint32_t* __restrict__ Bh)
{
    const uint32_t sb = sb0 + buf * F_BUF;
    #pragma unroll
    for (int p = 0; p < 4; p++) {
        const int idx = tid + p * 256;
        const int r = idx >> 3, c = idx & 7;
        const size_t g = (size_t)(m0 + r) * DD + kt * 64 + c * 8;
        CP_ASYNC16(sb + F_AH + r * 144 + c * 16, Ah + g);
    }
    #pragma unroll
    for (int p = 0; p < 4; p++) {
        const int idx = tid + p * 256;
        const int r = idx >> 5, c = idx & 31;
        const size_t g = (size_t)(kt * 32 + r) * DD + n0 + c * 4;
        CP_ASYNC16(sb + F_BH + r * 528 + c * 16, Bh + g);
    }
}

__global__ __launch_bounds__(256, 2) void tc_gemm_1p_kernel(
    const __half* __restrict__ Ah, const uint32_t* __restrict__ Bh,
    const float* __restrict__ bias, float* __restrict__ C,
    __half* __restrict__ Hout, float oscale, int mode)
{
    extern __shared__ char sm[];
    const uint32_t smem_base = smem_u32(sm);
    const int tid = threadIdx.x;
    const int wid = tid >> 5;
    const int lane = tid & 31;
    const int g = lane >> 2;
    const int t = lane & 3;
    const int wm = wid >> 2;
    const int wn = wid & 3;
    const int n0 = blockIdx.x * 128;
    const int m0 = blockIdx.y * 128;

    float c[4][4][4];
    #pragma unroll
    for (int i = 0; i < 4; i++)
        #pragma unroll
        for (int j = 0; j < 4; j++)
            #pragma unroll
            for (int q = 0; q < 4; q++) c[i][j][q] = 0.0f;

    gemm1p_load(smem_base, 0, tid, m0, n0, 0, Ah, Bh);
    CP_COMMIT();

    for (int kt = 0; kt < 16; kt++) {
        const int buf = kt & 1;
        if (kt < 15) {
            gemm1p_load(smem_base, buf ^ 1, tid, m0, n0, kt + 1, Ah, Bh);
            CP_COMMIT();
            CP_WAIT(1);
        } else {
            CP_WAIT(0);
        }
        __syncthreads();

        const char* Ab = sm + buf * F_BUF + F_AH;
        const char* Bb = sm + buf * F_BUF + F_BH;

        #pragma unroll
        for (int ks = 0; ks < 4; ks++) {
            uint32_t aH[4][4], bH[4][2];
            #pragma unroll
            for (int i = 0; i < 4; i++) {
                const int off = (wm * 64 + i * 16 + g) * 144 + ks * 32 + t * 4;
                aH[i][0] = *(const uint32_t*)(Ab + off);
                aH[i][1] = *(const uint32_t*)(Ab + off + 8 * 144);
                aH[i][2] = *(const uint32_t*)(Ab + off + 16);
                aH[i][3] = *(const uint32_t*)(Ab + off + 8 * 144 + 16);
            }
            #pragma unroll
            for (int j = 0; j < 4; j++) {
                const int off = (ks * 8 + t) * 528 + (wn * 32 + j * 8 + g) * 4;
                bH[j][0] = *(const uint32_t*)(Bb + off);
                bH[j][1] = *(const uint32_t*)(Bb + off + 4 * 528);
            }
            #pragma unroll
            for (int i = 0; i < 4; i++)
                #pragma unroll
                for (int j = 0; j < 4; j++)
                    mma16816(c[i][j], aH[i][0], aH[i][1], aH[i][2], aH[i][3],
                             bH[j][0], bH[j][1]);
        }
        __syncthreads();
    }

    #pragma unroll
    for (int j = 0; j < 4; j++) {
        const int col = n0 + wn * 32 + j * 8 + 2 * t;
        const float2 bv = *(const float2*)(bias + col);
        #pragma unroll
        for (int i = 0; i < 4; i++) {
            const int row = m0 + wm * 64 + i * 16 + g;
            float v0 = c[i][j][0] + bv.x, v1 = c[i][j][1] + bv.y;
            float v2 = c[i][j][2] + bv.x, v3 = c[i][j][3] + bv.y;
            if (mode == 0) {
                float* o = C + (size_t)row * DD + col;
                *(float2*)o = make_float2(v0, v1);
                *(float2*)(o + 8 * DD) = make_float2(v2, v3);
            } else {
                *(uint32_t*)(Hout + (size_t)row * DD + col) =
                    pack_h2(v0 * oscale, v1 * oscale);
                *(uint32_t*)(Hout + (size_t)(row + 8) * DD + col) =
                    pack_h2(v2 * oscale, v3 * oscale);
            }
        }
    }
}

// ---------------------------------------------------------------------------
// HMMA colsum (fp16): zinv[bh,k] = 1 / sum_q exp(S_qk)
// ---------------------------------------------------------------------------
#define CS_KH  0
#define CS_QH  18432
#define CS_RED 36864
#define CS_SMEM 37888

__global__ __launch_bounds__(256, 2) void attn_colsum_tc(
    const __half* __restrict__ Qh, const __half* __restrict__ Kh,
    float* __restrict__ zinv)
{
    extern __shared__ char sm[];
    const uint32_t sb = smem_u32(sm);
    const int tid = threadIdx.x;
    const int wid = tid >> 5;
    const int lane = tid & 31;
    const int g = lane >> 2;
    const int t = lane & 3;
    const int wm = wid >> 2;
    const int wn = wid & 3;
    const int kt = blockIdx.x;
    const int bh = blockIdx.y;
    const int b = bh >> 4, h = bh & 15;

    #pragma unroll
    for (int p = 0; p < 4; p++) {
        const int idx = tid + p * 256;
        const int r = idx >> 3, c = idx & 7;
        const size_t go = ((size_t)(b * LL + kt * 128 + r)) * DD + h * HDIM + c * 8;
        CP_ASYNC16(sb + CS_KH + r * 144 + c * 16, Kh + go);
    }
    #pragma unroll
    for (int p = 0; p < 4; p++) {
        const int idx = tid + p * 256;
        const int r = idx >> 3, c = idx & 7;
        const size_t go = ((size_t)(b * LL + r)) * DD + h * HDIM + c * 8;
        CP_ASYNC16(sb + CS_QH + r * 144 + c * 16, Qh + go);
    }
    CP_COMMIT();

    float cs[4][2];
    #pragma unroll
    for (int j = 0; j < 4; j++) { cs[j][0] = 0.0f; cs[j][1] = 0.0f; }

    for (int qt = 0; qt < 8; qt++) {
        CP_WAIT(0);
        __syncthreads();

        float acc[4][4][4];
        #pragma unroll
        for (int i = 0; i < 4; i++)
            #pragma unroll
            for (int j = 0; j < 4; j++)
                #pragma unroll
                for (int q = 0; q < 4; q++) acc[i][j][q] = 0.0f;

        #pragma unroll
        for (int ks = 0; ks < 4; ks++) {
            uint32_t aH[4][4], bH[4][2];
            #pragma unroll
            for (int i = 0; i < 4; i++) {
                const int off = (wm * 64 + i * 16 + g) * 144 + ks * 32 + t * 4;
                aH[i][0] = *(const uint32_t*)(sm + CS_QH + off);
                aH[i][1] = *(const uint32_t*)(sm + CS_QH + off + 8 * 144);
                aH[i][2] = *(const uint32_t*)(sm + CS_QH + off + 16);
                aH[i][3] = *(const uint32_t*)(sm + CS_QH + off + 8 * 144 + 16);
            }
            #pragma unroll
            for (int j = 0; j < 4; j++) {
                const int off = (wn * 32 + j * 8 + g) * 144 + ks * 32 + t * 4;
                bH[j][0] = *(const uint32_t*)(sm + CS_KH + off);
                bH[j][1] = *(const uint32_t*)(sm + CS_KH + off + 16);
            }
            #pragma unroll
            for (int i = 0; i < 4; i++)
                #pragma unroll
                for (int j = 0; j < 4; j++)
                    mma16816(acc[i][j], aH[i][0], aH[i][1], aH[i][2], aH[i][3],
                             bH[j][0], bH[j][1]);
        }

        #pragma unroll
        for (int i = 0; i < 4; i++)
            #pragma unroll
            for (int j = 0; j < 4; j++) {
                cs[j][0] += __expf(acc[i][j][0]) + __expf(acc[i][j][2]);
                cs[j][1] += __expf(acc[i][j][1]) + __expf(acc[i][j][3]);
            }

        __syncthreads();
        if (qt < 7) {
            #pragma unroll
            for (int p = 0; p < 4; p++) {
                const int idx = tid + p * 256;
                const int r = idx >> 3, c = idx & 7;
                const size_t go = ((size_t)(b * LL + (qt + 1) * 128 + r)) * DD + h * HDIM + c * 8;
                CP_ASYNC16(sb + CS_QH + r * 144 + c * 16, Qh + go);
            }
            CP_COMMIT();
        }
    }

    float* red = (float*)(sm + CS_RED);
    #pragma unroll
    for (int j = 0; j < 4; j++)
        #pragma unroll
        for (int hh = 0; hh < 2; hh++) {
            float v = cs[j][hh];
            v += __shfl_down_sync(0xffffffffu, v, 16);
            v += __shfl_down_sync(0xffffffffu, v, 8);
            v += __shfl_down_sync(0xffffffffu, v, 4);
            if (g == 0) red[wid * 32 + j * 8 + 2 * t + hh] = v;
        }
    __syncthreads();
    if (tid < 128) {
        const int col = tid;
        const int w2 = col >> 5, cl = col & 31;
        zinv[(size_t)bh * LL + kt * 128 + col] =
            1.0f / (red[w2 * 32 + cl] + red[(w2 + 4) * 32 + cl]);
    }
}

// ---------------------------------------------------------------------------
// HMMA AV (E = 1 + e): out = Sv + (1/1024) * sum_k e * (1024*Vp)
// Writes fp16 attention output.
// ---------------------------------------------------------------------------
#define AV_QH   0
#define AV_KH   18432
#define AV_E    36864
#define AV_VP0  71680
#define AV_VPB  17408
#define AV_SMEM 106496

__device__ __forceinline__ void av_load_kvp(
    uint32_t sb, int tid, int b, int h, int bh, int kt, int buf,
    const __half* __restrict__ Kh, const uint32_t* __restrict__ Vph)
{
    #pragma unroll
    for (int p = 0; p < 4; p++) {
        const int idx = tid + p * 256;
        const int r = idx >> 3, c = idx & 7;
        const size_t go = ((size_t)(b * LL + kt * 128 + r)) * DD + h * HDIM + c * 8;
        CP_ASYNC16(sb + AV_KH + r * 144 + c * 16, Kh + go);
    }
    const uint32_t vb = sb + AV_VP0 + buf * AV_VPB;
    #pragma unroll
    for (int p = 0; p < 4; p++) {
        const int idx = tid + p * 256;
        const int r = idx >> 4, c = idx & 15;
        const size_t go = ((size_t)bh * 512 + kt * 64 + r) * 64 + c * 4;
        CP_ASYNC16(vb + r * 272 + c * 16, Vph + go);
    }
}

__global__ __launch_bounds__(256, 1) void attn_av_tc(
    const __half* __restrict__ Qh, const __half* __restrict__ Kh,
    const uint32_t* __restrict__ Vph, const float* __restrict__ Sv,
    __half* __restrict__ Oh)
{
    extern __shared__ char sm[];
    const uint32_t sb = smem_u32(sm);
    const int tid = threadIdx.x;
    const int wid = tid >> 5;
    const int lane = tid & 31;
    const int g = lane >> 2;
    const int t = lane & 3;
    const int wm = wid >> 2;
    const int wn = wid & 3;
    const int qt = blockIdx.x;
    const int bh = blockIdx.y;
    const int b = bh >> 4, h = bh & 15;

    #pragma unroll
    for (int p = 0; p < 4; p++) {
        const int idx = tid + p * 256;
        const int r = idx >> 3, c = idx & 7;
        const size_t go = ((size_t)(b * LL + qt * 128 + r)) * DD + h * HDIM + c * 8;
        CP_ASYNC16(sb + AV_QH + r * 144 + c * 16, Qh + go);
    }
    av_load_kvp(sb, tid, b, h, bh, 0, 0, Kh, Vph);
    CP_COMMIT();

    float out[4][2][4];
    #pragma unroll
    for (int i = 0; i < 4; i++)
        #pragma unroll
        for (int j = 0; j < 2; j++)
            #pragma unroll
            for (int q = 0; q < 4; q++) out[i][j][q] = 0.0f;

    for (int kt = 0; kt < 8; kt++) {
        const int buf = kt & 1;
        CP_WAIT(0);
        __syncthreads();

        float acc[4][4][4];
        #pragma unroll
        for (int i = 0; i < 4; i++)
            #pragma unroll
            for (int j = 0; j < 4; j++)
                #pragma unroll
                for (int q = 0; q < 4; q++) acc[i][j][q] = 0.0f;

        #pragma unroll
        for (int ks = 0; ks < 4; ks++) {
            uint32_t aH[4][4], bH[4][2];
            #pragma unroll
            for (int i = 0; i < 4; i++) {
                const int off = (wm * 64 + i * 16 + g) * 144 + ks * 32 + t * 4;
                aH[i][0] = *(const uint32_t*)(sm + AV_QH + off);
                aH[i][1] = *(const uint32_t*)(sm + AV_QH + off + 8 * 144);
                aH[i][2] = *(const uint32_t*)(sm + AV_QH + off + 16);
                aH[i][3] = *(const uint32_t*)(sm + AV_QH + off + 8 * 144 + 16);
            }
            #pragma unroll
            for (int j = 0; j < 4; j++) {
                const int off = (wn * 32 + j * 8 + g) * 144 + ks * 32 + t * 4;
                bH[j][0] = *(const uint32_t*)(sm + AV_KH + off);
                bH[j][1] = *(const uint32_t*)(sm + AV_KH + off + 16);
            }
            #pragma unroll
            for (int i = 0; i < 4; i++)
                #pragma unroll
                for (int j = 0; j < 4; j++)
                    mma16816(acc[i][j], aH[i][0], aH[i][1], aH[i][2], aH[i][3],
                             bH[j][0], bH[j][1]);
        }

        #pragma unroll
        for (int i = 0; i < 4; i++) {
            const int row = wm * 64 + i * 16 + g;
            #pragma unroll
            for (int j = 0; j < 4; j++) {
                const int colb = (wn * 32 + j * 8 + 2 * t) * 2;
                float e0 = __expf(acc[i][j][0]) - 1.0f;
                float e1 = __expf(acc[i][j][1]) - 1.0f;
                float e2 = __expf(acc[i][j][2]) - 1.0f;
                float e3 = __expf(acc[i][j][3]) - 1.0f;
                *(uint32_t*)(sm + AV_E + row * 272 + colb) = pack_h2(e0, e1);
                *(uint32_t*)(sm + AV_E + (row + 8) * 272 + colb) = pack_h2(e2, e3);
            }
        }
        __syncthreads();

        if (kt < 7) {
            av_load_kvp(sb, tid, b, h, bh, kt + 1, buf ^ 1, Kh, Vph);
            CP_COMMIT();
        }

        const char* VH = sm + AV_VP0 + buf * AV_VPB;
        #pragma unroll
        for (int ks = 0; ks < 8; ks++) {
            uint32_t aE[4][4], bV[2][2];
            #pragma unroll
            for (int i = 0; i < 4; i++) {
                const int off = (wm * 64 + i * 16 + g) * 272 + ks * 32 + t * 4;
                aE[i][0] = *(const uint32_t*)(sm + AV_E + off);
                aE[i][1] = *(const uint32_t*)(sm + AV_E + off + 8 * 272);
                aE[i][2] = *(const uint32_t*)(sm + AV_E + off + 16);
                aE[i][3] = *(const uint32_t*)(sm + AV_E + off + 8 * 272 + 16);
            }
            #pragma unroll
            for (int j = 0; j < 2; j++) {
                const int off = (ks * 8 + t) * 272 + (wn * 16 + j * 8 + g) * 4;
                bV[j][0] = *(const uint32_t*)(VH + off);
                bV[j][1] = *(const uint32_t*)(VH + off + 4 * 272);
            }
            #pragma unroll
            for (int i = 0; i < 4; i++)
                #pragma unroll
                for (int j = 0; j < 2; j++)
                    mma16816(out[i][j], aE[i][0], aE[i][1], aE[i][2], aE[i][3],
                             bV[j][0], bV[j][1]);
        }
        __syncthreads();
    }

    const float s = 1.0f / 1024.0f;
    #pragma unroll
    for (int i = 0; i < 4; i++) {
        const int row = qt * 128 + wm * 64 + i * 16 + g;
        #pragma unroll
        for (int j = 0; j < 2; j++) {
            const int dcol = wn * 16 + j * 8 + 2 * t;
            const float sv0 = Sv[(size_t)bh * HDIM + dcol];
            const float sv1 = Sv[(size_t)bh * HDIM + dcol + 1];
            const size_t o0 = ((size_t)b * LL + row) * DD + h * HDIM + dcol;
            const size_t o1 = ((size_t)b * LL + row + 8) * DD + h * HDIM + dcol;
            *(uint32_t*)(Oh + o0) =
                pack_h2(out[i][j][0] * s + sv0, out[i][j][1] * s + sv1);
            *(uint32_t*)(Oh + o1) =
                pack_h2(out[i][j][2] * s + sv0, out[i][j][3] * s + sv1);
        }
    }
}

// ---------------------------------------------------------------------------
// Launch
// ---------------------------------------------------------------------------
extern "C" void kernel_launch(void* const* d_in, const int* in_sizes, int n_in,
                              void* d_out, int out_size)
{
    (void)in_sizes; (void)n_in; (void)out_size;

    const float* x_q = (const float*)d_in[0];
    const float* x_k = (const float*)d_in[1];
    const float* x_v = (const float*)d_in[2];
    // d_in[3] = mask: unused (reference never applies it)
    const float* Wq  = (const float*)d_in[4];
    const float* bq  = (const float*)d_in[5];
    const float* Wk  = (const float*)d_in[6];
    const float* bk  = (const float*)d_in[7];
    const float* Wv  = (const float*)d_in[8];
    const float* bv  = (const float*)d_in[9];
    const float* Wo  = (const float*)d_in[10];
    const float* bo  = (const float*)d_in[11];

    float *pV, *pZi, *pSz, *pSx, *pSv;
    __half *pAh, *pQh, *pKh;
    uint32_t *pWh, *pVh;
    cudaGetSymbolAddress((void**)&pV, g_V);
    cudaGetSymbolAddress((void**)&pZi, g_zinv);
    cudaGetSymbolAddress((void**)&pSz, g_sz);
    cudaGetSymbolAddress((void**)&pSx, g_sx);
    cudaGetSymbolAddress((void**)&pSv, g_Sv);
    cudaGetSymbolAddress((void**)&pAh, g_Ah);
    cudaGetSymbolAddress((void**)&pWh, g_Wph);
    cudaGetSymbolAddress((void**)&pQh, g_Qh);
    cudaGetSymbolAddress((void**)&pKh, g_Kh);
    cudaGetSymbolAddress((void**)&pVh, g_Vph);

    cudaFuncSetAttribute(tc_gemm_1p_kernel,
                         cudaFuncAttributeMaxDynamicSharedMemorySize, F_SMEM);
    cudaFuncSetAttribute(attn_colsum_tc,
                         cudaFuncAttributeMaxDynamicSharedMemorySize, CS_SMEM);
    cudaFuncSetAttribute(attn_av_tc,
                         cudaFuncAttributeMaxDynamicSharedMemorySize, AV_SMEM);
    cudaFuncSetAttribute(sx_kernel,
                         cudaFuncAttributeMaxDynamicSharedMemorySize, 65536);

    const int n4 = MTOT * DD / 4;
    const dim3 gSplit((n4 + 255) / 256), t256(256);
    const int npack = (DD / 2) * DD;
    const dim3 gPack((npack + 255) / 256);
    const dim3 gGemm(DD / 128, MTOT / 128);

    // Q projection (1-pass fp16) -> Qh scaled by 1/32
    tof16_kernel<<<gSplit, t256>>>(x_q, pAh, n4);
    pack_wh_kernel<<<gPack, t256>>>(Wq, pWh);
    tc_gemm_1p_kernel<<<gGemm, 256, F_SMEM>>>(
        pAh, pWh, bq, nullptr, pQh, 0.03125f, 1);
    // K projection (1-pass fp16) -> Kh
    tof16_kernel<<<gSplit, t256>>>(x_k, pAh, n4);
    pack_wh_kernel<<<gPack, t256>>>(Wk, pWh);
    tc_gemm_1p_kernel<<<gGemm, 256, F_SMEM>>>(
        pAh, pWh, bk, nullptr, pKh, 1.0f, 1);
    // V projection (1-pass fp16) -> fp32 V
    tof16_kernel<<<gSplit, t256>>>(x_v, pAh, n4);
    pack_wh_kernel<<<gPack, t256>>>(Wv, pWh);
    tc_gemm_1p_kernel<<<gGemm, 256, F_SMEM>>>(
        pAh, pWh, bv, pV, nullptr, 1.0f, 0);

    // zinv = 1 / column-softmax sums
    attn_colsum_tc<<<dim3(8, BB * HH), 256, CS_SMEM>>>(pQh, pKh, pZi);

    // Exact Sv via commuted identity: Sv = (sum_k x_v zi) @ Wv + bv * sum(zi)
    sumz_kernel<<<BB * HH, 256>>>(pZi, pSz);
    sx_kernel<<<dim3(BB, 16), 256, 65536>>>(x_v, pZi, pSx);
    sv_kernel<<<BB * HH, 256>>>(pSx, Wv, bv, pSz, pSv);

    // Vp (1024*V/Z) fp16 k-pair packed
    const int nvp = BB * HH * (LL / 2) * HDIM;
    build_vp_kernel<<<(nvp + 255) / 256, t256>>>(pV, pZi, pVh);

    // AV -> fp16 attention output in g_Ah
    attn_av_tc<<<dim3(8, BB * HH), 256, AV_SMEM>>>(pQh, pKh, pVh, pSv, pAh);

    // Output projection (1-pass fp16) -> d_out
    pack_wh_kernel<<<gPack, t256>>>(Wo, pWh);
    tc_gemm_1p_kernel<<<gGemm, 256, F_SMEM>>>(
        pAh, pWh, bo, (float*)d_out, nullptr, 1.0f, 0);
}

// round 12
// speedup vs baseline: 5.4517x; 1.0132x over previous
#include <cuda_runtime.h>
#include <cuda_fp16.h>
#include <cstdint>
#include <math.h>

// Problem constants
#define BB   8
#define LL   1024
#define DD   1024
#define HH   16
#define HDIM 64
#define MTOT (BB*LL)

// ---------------------------------------------------------------------------
// Scratch (device globals)
// ---------------------------------------------------------------------------
__device__ float g_zinv[(size_t)BB * HH * LL];      // 512 KB (1/Z)
__device__ float g_sz[(size_t)BB * HH];             // sum_k zinv
__device__ float g_sx[(size_t)BB * HH * DD];        // 512 KB (sum_k x_v * zinv)
__device__ float g_Sv[(size_t)BB * HH * HDIM];      // 32 KB  (exact sum_k V/Z)
__device__ __half g_Ah[(size_t)MTOT * DD];          // 16 MB (x_q fp16 / attn out)
__device__ __half g_Xk[(size_t)MTOT * DD];          // 16 MB (x_k fp16)
__device__ __half g_Xv[(size_t)MTOT * DD];          // 16 MB (x_v fp16)
__device__ uint32_t g_Wp[(size_t)4 * (DD/2) * DD];  // 8 MB (4 W's k-pair fp16x2)
__device__ __half g_Qh[(size_t)MTOT * DD];          // 16 MB (Q/32, fp16)
__device__ __half g_Kh[(size_t)MTOT * DD];          // 16 MB
__device__ uint32_t g_Vph[(size_t)BB * HH * (LL/2) * HDIM];  // 16 MB (1024*V/Z k-pair)

// ---------------------------------------------------------------------------
// Helpers
// ---------------------------------------------------------------------------
__device__ __forceinline__ void mma16816(float c[4],
    uint32_t a0, uint32_t a1, uint32_t a2, uint32_t a3,
    uint32_t b0, uint32_t b1)
{
    asm volatile(
        "mma.sync.aligned.m16n8k16.row.col.f32.f16.f16.f32 "
        "{%0,%1,%2,%3}, {%4,%5,%6,%7}, {%8,%9}, {%0,%1,%2,%3};"
        : "+f"(c[0]), "+f"(c[1]), "+f"(c[2]), "+f"(c[3])
        : "r"(a0), "r"(a1), "r"(a2), "r"(a3), "r"(b0), "r"(b1));
}

__device__ __forceinline__ uint32_t smem_u32(const void* p) {
    uint32_t a;
    asm("{ .reg .u64 t; cvta.to.shared.u64 t, %1; cvt.u32.u64 %0, t; }"
        : "=r"(a) : "l"(p));
    return a;
}

#define CP_ASYNC16(dst_u32, src_ptr) \
    asm volatile("cp.async.cg.shared.global [%0], [%1], 16;" \
        :: "r"(dst_u32), "l"(src_ptr) : "memory")
#define CP_COMMIT() asm volatile("cp.async.commit_group;" ::: "memory")
#define CP_WAIT(n)  asm volatile("cp.async.wait_group %0;" :: "n"(n) : "memory")

__device__ __forceinline__ uint32_t pack_h2(float x, float y) {
    __half2 p = __floats2half2_rn(x, y);   // .x = x (low half)
    return *(uint32_t*)&p;
}

// ---------------------------------------------------------------------------
// fp32 -> fp16, batched over 3 inputs (blockIdx.y selects)
// ---------------------------------------------------------------------------
__global__ __launch_bounds__(256) void tof16_batch(
    const float* __restrict__ x0, const float* __restrict__ x1,
    const float* __restrict__ x2,
    __half* __restrict__ h0, __half* __restrict__ h1, __half* __restrict__ h2,
    int n4)
{
    int i = blockIdx.x * blockDim.x + threadIdx.x;
    if (i >= n4) return;
    const float* x;
    __half* h;
    if (blockIdx.y == 0)      { x = x0; h = h0; }
    else if (blockIdx.y == 1) { x = x1; h = h1; }
    else                      { x = x2; h = h2; }
    float4 v = ((const float4*)x)[i];
    __half2* hp = (__half2*)h;
    hp[2*i]   = __floats2half2_rn(v.x, v.y);
    hp[2*i+1] = __floats2half2_rn(v.z, v.w);
}

// ---------------------------------------------------------------------------
// pack 4 W's [K,N] fp32 -> k-pair fp16x2 [k2][n] (blockIdx.y selects)
// ---------------------------------------------------------------------------
__global__ __launch_bounds__(256) void pack_w_batch(
    const float* __restrict__ W0, const float* __restrict__ W1,
    const float* __restrict__ W2, const float* __restrict__ W3,
    uint32_t* __restrict__ P)
{
    int i = blockIdx.x * blockDim.x + threadIdx.x;
    if (i >= (DD/2) * DD) return;
    const float* W;
    if (blockIdx.y == 0)      W = W0;
    else if (blockIdx.y == 1) W = W1;
    else if (blockIdx.y == 2) W = W2;
    else                      W = W3;
    uint32_t* Ph = P + (size_t)blockIdx.y * (DD/2) * DD;
    int k2 = i >> 10, n = i & (DD - 1);
    Ph[i] = pack_h2(W[(size_t)(2*k2) * DD + n], W[(size_t)(2*k2 + 1) * DD + n]);
}

// ---------------------------------------------------------------------------
// sz[bh] = sum_k zinv[bh,k]
// ---------------------------------------------------------------------------
__global__ __launch_bounds__(256) void sumz_kernel(
    const float* __restrict__ Zi, float* __restrict__ Sz)
{
    __shared__ float red[256];
    const int bh = blockIdx.x;
    const int tid = threadIdx.x;
    float s = 0.0f;
    #pragma unroll
    for (int p = 0; p < 4; p++) s += Zi[(size_t)bh * LL + tid + p * 256];
    red[tid] = s;
    __syncthreads();
    for (int w = 128; w > 0; w >>= 1) {
        if (tid < w) red[tid] += red[tid + w];
        __syncthreads();
    }
    if (tid == 0) Sz[bh] = red[0];
}

// ---------------------------------------------------------------------------
// s_x[bh][d'] = sum_k x_v[b,k,d'] * zinv[bh,k]   (exact fp32)
// ---------------------------------------------------------------------------
__global__ __launch_bounds__(256) void sx_kernel(
    const float* __restrict__ xv, const float* __restrict__ Zi,
    float* __restrict__ Sx)
{
    extern __shared__ float szi[];   // [16][1024]
    const int b = blockIdx.x;
    const int dc = blockIdx.y;       // 0..15
    const int tid = threadIdx.x;
    const int d = tid & 63;
    const int s = tid >> 6;          // k-slice 0..3

    for (int i = tid; i < 16 * 1024; i += 256)
        szi[i] = Zi[(size_t)(b * 16) * LL + i];
    __syncthreads();

    float acc[16];
    #pragma unroll
    for (int h = 0; h < 16; h++) acc[h] = 0.0f;

    const int dglob = dc * 64 + d;
    const int k0 = s * 256;
    for (int k = k0; k < k0 + 256; k++) {
        float x = xv[((size_t)b * LL + k) * DD + dglob];
        #pragma unroll
        for (int h = 0; h < 16; h++)
            acc[h] = fmaf(x, szi[h * 1024 + k], acc[h]);
    }
    __syncthreads();
    float* red = szi;   // [4][16][64]
    #pragma unroll
    for (int h = 0; h < 16; h++)
        red[(s * 16 + h) * 64 + d] = acc[h];
    __syncthreads();
    for (int i = tid; i < 16 * 64; i += 256) {
        int h = i >> 6, dd = i & 63;
        float v = red[(0 * 16 + h) * 64 + dd] + red[(1 * 16 + h) * 64 + dd]
                + red[(2 * 16 + h) * 64 + dd] + red[(3 * 16 + h) * 64 + dd];
        Sx[(size_t)(b * 16 + h) * DD + dc * 64 + dd] = v;
    }
}

// ---------------------------------------------------------------------------
// Sv[bh][d] = sum_{d'} s_x[bh][d'] * Wv[d'][h*64+d] + bv[h*64+d]*sz[bh]
// ---------------------------------------------------------------------------
__global__ __launch_bounds__(256) void sv_kernel(
    const float* __restrict__ Sx, const float* __restrict__ Wv,
    const float* __restrict__ bv, const float* __restrict__ Sz,
    float* __restrict__ Sv)
{
    __shared__ float sxr[1024];
    __shared__ float red[4 * 64];
    const int bh = blockIdx.x;
    const int h = bh & 15;
    const int tid = threadIdx.x;
    const int d = tid & 63;
    const int s = tid >> 6;

    for (int i = tid; i < 1024; i += 256)
        sxr[i] = Sx[(size_t)bh * DD + i];
    __syncthreads();

    float acc = 0.0f;
    const int k0 = s * 256;
    const int col = h * HDIM + d;
    for (int k = k0; k < k0 + 256; k++)
        acc = fmaf(sxr[k], Wv[(size_t)k * DD + col], acc);
    red[s * 64 + d] = acc;
    __syncthreads();
    if (tid < 64)
        Sv[(size_t)bh * HDIM + d] =
            red[d] + red[64 + d] + red[128 + d] + red[192 + d] + bv[col] * Sz[bh];
}

// ---------------------------------------------------------------------------
// Single-pass fp16 HMMA GEMM.
// mode 0: fp32 C = A@W + bias
// mode 1: fp16 Hout = (A@W + bias) * oscale
// mode 2: Vp pack: Vout[bh][k2][d] = fp16x2{ 1024*zi*(A@W+bias) } k-pairs
// SMEM per buffer: A 18432 + B 16896 = 35328; x2 = 70656 -> 2 CTAs/SM.
// ---------------------------------------------------------------------------
#define F_AH   0
#define F_BH   18432
#define F_BUF  35328
#define F_SMEM (2 * F_BUF)

__device__ __forceinline__ void gemm1p_load(
    uint32_t sb0, int buf, int tid, int m0, int n0, int kt,
    const __half* __restrict__ Ah, const uint32_t* __restrict__ Bh)
{
    const uint32_t sb = sb0 + buf * F_BUF;
    #pragma unroll
    for (int p = 0; p < 4; p++) {
        const int idx = tid + p * 256;
        const int r = idx >> 3, c = idx & 7;
        const size_t g = (size_t)(m0 + r) * DD + kt * 64 + c * 8;
        CP_ASYNC16(sb + F_AH + r * 144 + c * 16, Ah + g);
    }
    #pragma unroll
    for (int p = 0; p < 4; p++) {
        const int idx = tid + p * 256;
        const int r = idx >> 5, c = idx & 31;
        const size_t g = (size_t)(kt * 32 + r) * DD + n0 + c * 4;
        CP_ASYNC16(sb + F_BH + r * 528 + c * 16, Bh + g);
    }
}

__global__ __launch_bounds__(256, 2) void tc_gemm_1p_kernel(
    const __half* __restrict__ Ah, const uint32_t* __restrict__ Bh,
    const float* __restrict__ bias, float* __restrict__ C,
    __half* __restrict__ Hout, const float* __restrict__ Zi,
    uint32_t* __restrict__ Vout, float oscale, int mode)
{
    extern __shared__ char sm[];
    const uint32_t smem_base = smem_u32(sm);
    const int tid = threadIdx.x;
    const int wid = tid >> 5;
    const int lane = tid & 31;
    const int g = lane >> 2;
    const int t = lane & 3;
    const int wm = wid >> 2;
    const int wn = wid & 3;
    const int n0 = blockIdx.x * 128;
    const int m0 = blockIdx.y * 128;

    float c[4][4][4];
    #pragma unroll
    for (int i = 0; i < 4; i++)
        #pragma unroll
        for (int j = 0; j < 4; j++)
            #pragma unroll
            for (int q = 0; q < 4; q++) c[i][j][q] = 0.0f;

    gemm1p_load(smem_base, 0, tid, m0, n0, 0, Ah, Bh);
    CP_COMMIT();

    for (int kt = 0; kt < 16; kt++) {
        const int buf = kt & 1;
        if (kt < 15) {
            gemm1p_load(smem_base, buf ^ 1, tid, m0, n0, kt + 1, Ah, Bh);
            CP_COMMIT();
            CP_WAIT(1);
        } else {
            CP_WAIT(0);
        }
        __syncthreads();

        const char* Ab = sm + buf * F_BUF + F_AH;
        const char* Bb = sm + buf * F_BUF + F_BH;

        #pragma unroll
        for (int ks = 0; ks < 4; ks++) {
            uint32_t aH[4][4], bH[4][2];
            #pragma unroll
            for (int i = 0; i < 4; i++) {
                const int off = (wm * 64 + i * 16 + g) * 144 + ks * 32 + t * 4;
                aH[i][0] = *(const uint32_t*)(Ab + off);
                aH[i][1] = *(const uint32_t*)(Ab + off + 8 * 144);
                aH[i][2] = *(const uint32_t*)(Ab + off + 16);
                aH[i][3] = *(const uint32_t*)(Ab + off + 8 * 144 + 16);
            }
            #pragma unroll
            for (int j = 0; j < 4; j++) {
                const int off = (ks * 8 + t) * 528 + (wn * 32 + j * 8 + g) * 4;
                bH[j][0] = *(const uint32_t*)(Bb + off);
                bH[j][1] = *(const uint32_t*)(Bb + off + 4 * 528);
            }
            #pragma unroll
            for (int i = 0; i < 4; i++)
                #pragma unroll
                for (int j = 0; j < 4; j++)
                    mma16816(c[i][j], aH[i][0], aH[i][1], aH[i][2], aH[i][3],
                             bH[j][0], bH[j][1]);
        }
        __syncthreads();
    }

    if (mode == 2) {
        // Stage fp32 (C + bias) tile in smem, then repack as zinv-scaled
        // fp16 k-pairs into Vp layout. stage pitch = 132 floats (528 B).
        float* stage = (float*)sm;                 // 128 x 132 fp32 = 67584 B
        float* ziS   = (float*)(sm + 67584);       // [2][128] fp32
        #pragma unroll
        for (int j = 0; j < 4; j++) {
            const int cl = wn * 32 + j * 8 + 2 * t;
            const float2 bv = *(const float2*)(bias + n0 + cl);
            #pragma unroll
            for (int i = 0; i < 4; i++) {
                const int rl = wm * 64 + i * 16 + g;
                stage[rl * 132 + cl]       = c[i][j][0] + bv.x;
                stage[rl * 132 + cl + 1]   = c[i][j][1] + bv.y;
                stage[(rl + 8) * 132 + cl]     = c[i][j][2] + bv.x;
                stage[(rl + 8) * 132 + cl + 1] = c[i][j][3] + bv.y;
            }
        }
        const int b = m0 >> 10;
        const int l0 = m0 & 1023;
        const int h0 = n0 >> 6;        // first of 2 heads in this col block
        {
            const int hh = tid >> 7, l = tid & 127;
            ziS[tid] = Zi[(size_t)(b * 16 + h0 + hh) * LL + l0 + l] * 1024.0f;
        }
        __syncthreads();
        const int k20 = l0 >> 1;
        #pragma unroll
        for (int p = 0; p < 32; p++) {
            const int i = tid + p * 256;          // 0..8191
            const int hh = i >> 12;
            const int k2r = (i >> 6) & 63;
            const int d = i & 63;
            float v0 = stage[(2 * k2r) * 132 + hh * 64 + d] * ziS[hh * 128 + 2 * k2r];
            float v1 = stage[(2 * k2r + 1) * 132 + hh * 64 + d] * ziS[hh * 128 + 2 * k2r + 1];
            Vout[((size_t)(b * 16 + h0 + hh) * 512 + k20 + k2r) * 64 + d] =
                pack_h2(v0, v1);
        }
        return;
    }

    #pragma unroll
    for (int j = 0; j < 4; j++) {
        const int col = n0 + wn * 32 + j * 8 + 2 * t;
        const float2 bv = *(const float2*)(bias + col);
        #pragma unroll
        for (int i = 0; i < 4; i++) {
            const int row = m0 + wm * 64 + i * 16 + g;
            float v0 = c[i][j][0] + bv.x, v1 = c[i][j][1] + bv.y;
            float v2 = c[i][j][2] + bv.x, v3 = c[i][j][3] + bv.y;
            if (mode == 0) {
                float* o = C + (size_t)row * DD + col;
                *(float2*)o = make_float2(v0, v1);
                *(float2*)(o + 8 * DD) = make_float2(v2, v3);
            } else {
                *(uint32_t*)(Hout + (size_t)row * DD + col) =
                    pack_h2(v0 * oscale, v1 * oscale);
                *(uint32_t*)(Hout + (size_t)(row + 8) * DD + col) =
                    pack_h2(v2 * oscale, v3 * oscale);
            }
        }
    }
}

// ---------------------------------------------------------------------------
// HMMA colsum (fp16): zinv[bh,k] = 1 / sum_q exp(S_qk)
// ---------------------------------------------------------------------------
#define CS_KH  0
#define CS_QH  18432
#define CS_RED 36864
#define CS_SMEM 37888

__global__ __launch_bounds__(256, 2) void attn_colsum_tc(
    const __half* __restrict__ Qh, const __half* __restrict__ Kh,
    float* __restrict__ zinv)
{
    extern __shared__ char sm[];
    const uint32_t sb = smem_u32(sm);
    const int tid = threadIdx.x;
    const int wid = tid >> 5;
    const int lane = tid & 31;
    const int g = lane >> 2;
    const int t = lane & 3;
    const int wm = wid >> 2;
    const int wn = wid & 3;
    const int kt = blockIdx.x;
    const int bh = blockIdx.y;
    const int b = bh >> 4, h = bh & 15;

    #pragma unroll
    for (int p = 0; p < 4; p++) {
        const int idx = tid + p * 256;
        const int r = idx >> 3, c = idx & 7;
        const size_t go = ((size_t)(b * LL + kt * 128 + r)) * DD + h * HDIM + c * 8;
        CP_ASYNC16(sb + CS_KH + r * 144 + c * 16, Kh + go);
    }
    #pragma unroll
    for (int p = 0; p < 4; p++) {
        const int idx = tid + p * 256;
        const int r = idx >> 3, c = idx & 7;
        const size_t go = ((size_t)(b * LL + r)) * DD + h * HDIM + c * 8;
        CP_ASYNC16(sb + CS_QH + r * 144 + c * 16, Qh + go);
    }
    CP_COMMIT();

    float cs[4][2];
    #pragma unroll
    for (int j = 0; j < 4; j++) { cs[j][0] = 0.0f; cs[j][1] = 0.0f; }

    for (int qt = 0; qt < 8; qt++) {
        CP_WAIT(0);
        __syncthreads();

        float acc[4][4][4];
        #pragma unroll
        for (int i = 0; i < 4; i++)
            #pragma unroll
            for (int j = 0; j < 4; j++)
                #pragma unroll
                for (int q = 0; q < 4; q++) acc[i][j][q] = 0.0f;

        #pragma unroll
        for (int ks = 0; ks < 4; ks++) {
            uint32_t aH[4][4], bH[4][2];
            #pragma unroll
            for (int i = 0; i < 4; i++) {
                const int off = (wm * 64 + i * 16 + g) * 144 + ks * 32 + t * 4;
                aH[i][0] = *(const uint32_t*)(sm + CS_QH + off);
                aH[i][1] = *(const uint32_t*)(sm + CS_QH + off + 8 * 144);
                aH[i][2] = *(const uint32_t*)(sm + CS_QH + off + 16);
                aH[i][3] = *(const uint32_t*)(sm + CS_QH + off + 8 * 144 + 16);
            }
            #pragma unroll
            for (int j = 0; j < 4; j++) {
                const int off = (wn * 32 + j * 8 + g) * 144 + ks * 32 + t * 4;
                bH[j][0] = *(const uint32_t*)(sm + CS_KH + off);
                bH[j][1] = *(const uint32_t*)(sm + CS_KH + off + 16);
            }
            #pragma unroll
            for (int i = 0; i < 4; i++)
                #pragma unroll
                for (int j = 0; j < 4; j++)
                    mma16816(acc[i][j], aH[i][0], aH[i][1], aH[i][2], aH[i][3],
                             bH[j][0], bH[j][1]);
        }

        #pragma unroll
        for (int i = 0; i < 4; i++)
            #pragma unroll
            for (int j = 0; j < 4; j++) {
                cs[j][0] += __expf(acc[i][j][0]) + __expf(acc[i][j][2]);
                cs[j][1] += __expf(acc[i][j][1]) + __expf(acc[i][j][3]);
            }

        __syncthreads();
        if (qt < 7) {
            #pragma unroll
            for (int p = 0; p < 4; p++) {
                const int idx = tid + p * 256;
                const int r = idx >> 3, c = idx & 7;
                const size_t go = ((size_t)(b * LL + (qt + 1) * 128 + r)) * DD + h * HDIM + c * 8;
                CP_ASYNC16(sb + CS_QH + r * 144 + c * 16, Qh + go);
            }
            CP_COMMIT();
        }
    }

    float* red = (float*)(sm + CS_RED);
    #pragma unroll
    for (int j = 0; j < 4; j++)
        #pragma unroll
        for (int hh = 0; hh < 2; hh++) {
            float v = cs[j][hh];
            v += __shfl_down_sync(0xffffffffu, v, 16);
            v += __shfl_down_sync(0xffffffffu, v, 8);
            v += __shfl_down_sync(0xffffffffu, v, 4);
            if (g == 0) red[wid * 32 + j * 8 + 2 * t + hh] = v;
        }
    __syncthreads();
    if (tid < 128) {
        const int col = tid;
        const int w2 = col >> 5, cl = col & 31;
        zinv[(size_t)bh * LL + kt * 128 + col] =
            1.0f / (red[w2 * 32 + cl] + red[(w2 + 4) * 32 + cl]);
    }
}

// ---------------------------------------------------------------------------
// HMMA AV (E = 1 + e): out = Sv + (1/1024) * sum_k e * (1024*Vp)
// 64-row q tiles, occupancy 2. Grid (16, 128), 256 thr.
// SMEM: QH 9216 | KH 18432 | E 17408 | VP 2x17408 = 79872
// ---------------------------------------------------------------------------
#define AV_QH   0
#define AV_KH   9216
#define AV_E    27648
#define AV_VP0  45056
#define AV_VPB  17408
#define AV_SMEM 79872

__device__ __forceinline__ void av_load_kvp(
    uint32_t sb, int tid, int b, int h, int bh, int kt, int buf,
    const __half* __restrict__ Kh, const uint32_t* __restrict__ Vph)
{
    #pragma unroll
    for (int p = 0; p < 4; p++) {
        const int idx = tid + p * 256;
        const int r = idx >> 3, c = idx & 7;
        const size_t go = ((size_t)(b * LL + kt * 128 + r)) * DD + h * HDIM + c * 8;
        CP_ASYNC16(sb + AV_KH + r * 144 + c * 16, Kh + go);
    }
    const uint32_t vb = sb + AV_VP0 + buf * AV_VPB;
    #pragma unroll
    for (int p = 0; p < 4; p++) {
        const int idx = tid + p * 256;
        const int r = idx >> 4, c = idx & 15;
        const size_t go = ((size_t)bh * 512 + kt * 64 + r) * 64 + c * 4;
        CP_ASYNC16(vb + r * 272 + c * 16, Vph + go);
    }
}

__global__ __launch_bounds__(256, 2) void attn_av_tc(
    const __half* __restrict__ Qh, const __half* __restrict__ Kh,
    const uint32_t* __restrict__ Vph, const float* __restrict__ Sv,
    __half* __restrict__ Oh)
{
    extern __shared__ char sm[];
    const uint32_t sb = smem_u32(sm);
    const int tid = threadIdx.x;
    const int wid = tid >> 5;
    const int lane = tid & 31;
    const int g = lane >> 2;
    const int t = lane & 3;
    const int wm = wid >> 2;       // 0..1: 32-row slab
    const int wn = wid & 3;        // 0..3: 32-col (S) / 16-col (out) slab
    const int qt = blockIdx.x;     // 0..15, 64-row q tiles
    const int bh = blockIdx.y;
    const int b = bh >> 4, h = bh & 15;

    // load Q tile 64x64 fp16 (512 chunks)
    #pragma unroll
    for (int p = 0; p < 2; p++) {
        const int idx = tid + p * 256;
        const int r = idx >> 3, c = idx & 7;
        const size_t go = ((size_t)(b * LL + qt * 64 + r)) * DD + h * HDIM + c * 8;
        CP_ASYNC16(sb + AV_QH + r * 144 + c * 16, Qh + go);
    }
    av_load_kvp(sb, tid, b, h, bh, 0, 0, Kh, Vph);
    CP_COMMIT();

    float out[2][2][4];
    #pragma unroll
    for (int i = 0; i < 2; i++)
        #pragma unroll
        for (int j = 0; j < 2; j++)
            #pragma unroll
            for (int q = 0; q < 4; q++) out[i][j][q] = 0.0f;

    for (int kt = 0; kt < 8; kt++) {
        const int buf = kt & 1;
        CP_WAIT(0);
        __syncthreads();

        // ---- GEMM1: S (64x128) = Q . K^T ----
        float acc[2][4][4];
        #pragma unroll
        for (int i = 0; i < 2; i++)
            #pragma unroll
            for (int j = 0; j < 4; j++)
                #pragma unroll
                for (int q = 0; q < 4; q++) acc[i][j][q] = 0.0f;

        #pragma unroll
        for (int ks = 0; ks < 4; ks++) {
            uint32_t aH[2][4], bH[4][2];
            #pragma unroll
            for (int i = 0; i < 2; i++) {
                const int off = (wm * 32 + i * 16 + g) * 144 + ks * 32 + t * 4;
                aH[i][0] = *(const uint32_t*)(sm + AV_QH + off);
                aH[i][1] = *(const uint32_t*)(sm + AV_QH + off + 8 * 144);
                aH[i][2] = *(const uint32_t*)(sm + AV_QH + off + 16);
                aH[i][3] = *(const uint32_t*)(sm + AV_QH + off + 8 * 144 + 16);
            }
            #pragma unroll
            for (int j = 0; j < 4; j++) {
                const int off = (wn * 32 + j * 8 + g) * 144 + ks * 32 + t * 4;
                bH[j][0] = *(const uint32_t*)(sm + AV_KH + off);
                bH[j][1] = *(const uint32_t*)(sm + AV_KH + off + 16);
            }
            #pragma unroll
            for (int i = 0; i < 2; i++)
                #pragma unroll
                for (int j = 0; j < 4; j++)
                    mma16816(acc[i][j], aH[i][0], aH[i][1], aH[i][2], aH[i][3],
                             bH[j][0], bH[j][1]);
        }

        // ---- e = exp(S) - 1 -> smem (pitch 272) ----
        #pragma unroll
        for (int i = 0; i < 2; i++) {
            const int row = wm * 32 + i * 16 + g;
            #pragma unroll
            for (int j = 0; j < 4; j++) {
                const int colb = (wn * 32 + j * 8 + 2 * t) * 2;
                float e0 = __expf(acc[i][j][0]) - 1.0f;
                float e1 = __expf(acc[i][j][1]) - 1.0f;
                float e2 = __expf(acc[i][j][2]) - 1.0f;
                float e3 = __expf(acc[i][j][3]) - 1.0f;
                *(uint32_t*)(sm + AV_E + row * 272 + colb) = pack_h2(e0, e1);
                *(uint32_t*)(sm + AV_E + (row + 8) * 272 + colb) = pack_h2(e2, e3);
            }
        }
        __syncthreads();

        if (kt < 7) {
            av_load_kvp(sb, tid, b, h, bh, kt + 1, buf ^ 1, Kh, Vph);
            CP_COMMIT();
        }

        // ---- GEMM2: out (64x64) += e . Vp ----
        const char* VH = sm + AV_VP0 + buf * AV_VPB;
        #pragma unroll
        for (int ks = 0; ks < 8; ks++) {
            uint32_t aE[2][4], bV[2][2];
            #pragma unroll
            for (int i = 0; i < 2; i++) {
                const int off = (wm * 32 + i * 16 + g) * 272 + ks * 32 + t * 4;
                aE[i][0] = *(const uint32_t*)(sm + AV_E + off);
                aE[i][1] = *(const uint32_t*)(sm + AV_E + off + 8 * 272);
                aE[i][2] = *(const uint32_t*)(sm + AV_E + off + 16);
                aE[i][3] = *(const uint32_t*)(sm + AV_E + off + 8 * 272 + 16);
            }
            #pragma unroll
            for (int j = 0; j < 2; j++) {
                const int off = (ks * 8 + t) * 272 + (wn * 16 + j * 8 + g) * 4;
                bV[j][0] = *(const uint32_t*)(VH + off);
                bV[j][1] = *(const uint32_t*)(VH + off + 4 * 272);
            }
            #pragma unroll
            for (int i = 0; i < 2; i++)
                #pragma unroll
                for (int j = 0; j < 2; j++)
                    mma16816(out[i][j], aE[i][0], aE[i][1], aE[i][2], aE[i][3],
                             bV[j][0], bV[j][1]);
        }
        __syncthreads();
    }

    const float s = 1.0f / 1024.0f;
    #pragma unroll
    for (int i = 0; i < 2; i++) {
        const int row = qt * 64 + wm * 32 + i * 16 + g;
        #pragma unroll
        for (int j = 0; j < 2; j++) {
            const int dcol = wn * 16 + j * 8 + 2 * t;
            const float sv0 = Sv[(size_t)bh * HDIM + dcol];
            const float sv1 = Sv[(size_t)bh * HDIM + dcol + 1];
            const size_t o0 = ((size_t)b * LL + row) * DD + h * HDIM + dcol;
            const size_t o1 = ((size_t)b * LL + row + 8) * DD + h * HDIM + dcol;
            *(uint32_t*)(Oh + o0) =
                pack_h2(out[i][j][0] * s + sv0, out[i][j][1] * s + sv1);
            *(uint32_t*)(Oh + o1) =
                pack_h2(out[i][j][2] * s + sv0, out[i][j][3] * s + sv1);
        }
    }
}

// ---------------------------------------------------------------------------
// Launch
// ---------------------------------------------------------------------------
extern "C" void kernel_launch(void* const* d_in, const int* in_sizes, int n_in,
                              void* d_out, int out_size)
{
    (void)in_sizes; (void)n_in; (void)out_size;

    const float* x_q = (const float*)d_in[0];
    const float* x_k = (const float*)d_in[1];
    const float* x_v = (const float*)d_in[2];
    // d_in[3] = mask: unused (reference never applies it)
    const float* Wq  = (const float*)d_in[4];
    const float* bq  = (const float*)d_in[5];
    const float* Wk  = (const float*)d_in[6];
    const float* bk  = (const float*)d_in[7];
    const float* Wv  = (const float*)d_in[8];
    const float* bv  = (const float*)d_in[9];
    const float* Wo  = (const float*)d_in[10];
    const float* bo  = (const float*)d_in[11];

    float *pZi, *pSz, *pSx, *pSv;
    __half *pAh, *pXk, *pXv, *pQh, *pKh;
    uint32_t *pWp, *pVh;
    cudaGetSymbolAddress((void**)&pZi, g_zinv);
    cudaGetSymbolAddress((void**)&pSz, g_sz);
    cudaGetSymbolAddress((void**)&pSx, g_sx);
    cudaGetSymbolAddress((void**)&pSv, g_Sv);
    cudaGetSymbolAddress((void**)&pAh, g_Ah);
    cudaGetSymbolAddress((void**)&pXk, g_Xk);
    cudaGetSymbolAddress((void**)&pXv, g_Xv);
    cudaGetSymbolAddress((void**)&pWp, g_Wp);
    cudaGetSymbolAddress((void**)&pQh, g_Qh);
    cudaGetSymbolAddress((void**)&pKh, g_Kh);
    cudaGetSymbolAddress((void**)&pVh, g_Vph);

    cudaFuncSetAttribute(tc_gemm_1p_kernel,
                         cudaFuncAttributeMaxDynamicSharedMemorySize, F_SMEM);
    cudaFuncSetAttribute(attn_colsum_tc,
                         cudaFuncAttributeMaxDynamicSharedMemorySize, CS_SMEM);
    cudaFuncSetAttribute(attn_av_tc,
                         cudaFuncAttributeMaxDynamicSharedMemorySize, AV_SMEM);
    cudaFuncSetAttribute(sx_kernel,
                         cudaFuncAttributeMaxDynamicSharedMemorySize, 65536);

    const int n4 = MTOT * DD / 4;
    const dim3 t256(256);
    const int npack = (DD / 2) * DD;
    const dim3 gGemm(DD / 128, MTOT / 128);
    const size_t WPS = (size_t)(DD / 2) * DD;   // per-W pack stride (u32)

    // All fp32->fp16 conversions and W packs, batched
    tof16_batch<<<dim3((n4 + 255) / 256, 3), t256>>>(
        x_q, x_k, x_v, pAh, pXk, pXv, n4);
    pack_w_batch<<<dim3((npack + 255) / 256, 4), t256>>>(Wq, Wk, Wv, Wo, pWp);

    // Q projection -> Qh scaled by 1/32; K projection -> Kh
    tc_gemm_1p_kernel<<<gGemm, 256, F_SMEM>>>(
        pAh, pWp, bq, nullptr, pQh, nullptr, nullptr, 0.03125f, 1);
    tc_gemm_1p_kernel<<<gGemm, 256, F_SMEM>>>(
        pXk, pWp + WPS, bk, nullptr, pKh, nullptr, nullptr, 1.0f, 1);

    // zinv = 1 / column-softmax sums (needs only Qh, Kh)
    attn_colsum_tc<<<dim3(8, BB * HH), 256, CS_SMEM>>>(pQh, pKh, pZi);

    // Exact Sv via commuted identity: Sv = (sum_k x_v zi) @ Wv + bv * sum(zi)
    sumz_kernel<<<BB * HH, 256>>>(pZi, pSz);
    sx_kernel<<<dim3(BB, 16), 256, 65536>>>(x_v, pZi, pSx);
    sv_kernel<<<BB * HH, 256>>>(pSx, Wv, bv, pSz, pSv);

    // V projection fused with Vp pack (mode 2): writes 1024*V/Z k-pairs
    tc_gemm_1p_kernel<<<gGemm, 256, F_SMEM>>>(
        pXv, pWp + 2 * WPS, bv, nullptr, nullptr, pZi, pVh, 1.0f, 2);

    // AV -> fp16 attention output in g_Ah
    attn_av_tc<<<dim3(16, BB * HH), 256, AV_SMEM>>>(pQh, pKh, pVh, pSv, pAh);

    // Output projection (mode 0) -> d_out
    tc_gemm_1p_kernel<<<gGemm, 256, F_SMEM>>>(
        pAh, pWp + 3 * WPS, bo, (float*)d_out, nullptr, nullptr, nullptr, 1.0f, 0);
}

// round 13
// speedup vs baseline: 5.7713x; 1.0586x over previous
#include <cuda_runtime.h>
#include <cuda_fp16.h>
#include <cstdint>
#include <math.h>

// Problem constants
#define BB   8
#define LL   1024
#define DD   1024
#define HH   16
#define HDIM 64
#define MTOT (BB*LL)
#define WPS  ((size_t)(DD/2) * DD)

// ---------------------------------------------------------------------------
// Scratch (device globals)
// ---------------------------------------------------------------------------
__device__ float g_zinv[(size_t)BB * HH * LL];      // 512 KB (1/Z)
__device__ float g_sz[(size_t)BB * HH];             // sum_k zinv
__device__ float g_sx[(size_t)BB * HH * DD];        // 512 KB (sum_k x_v * zinv)
__device__ float g_Sv[(size_t)BB * HH * HDIM];      // 32 KB  (exact sum_k V/Z)
__device__ __half g_Ah[(size_t)MTOT * DD];          // 16 MB (x_q fp16 / attn out)
__device__ __half g_Xk[(size_t)MTOT * DD];          // 16 MB (x_k fp16)
__device__ __half g_Xv[(size_t)MTOT * DD];          // 16 MB (x_v fp16)
__device__ uint32_t g_Wp[(size_t)4 * (DD/2) * DD];  // 8 MB (4 W's k-pair fp16x2)
__device__ __half g_Qh[(size_t)MTOT * DD];          // 16 MB (Q/32, fp16)
__device__ __half g_Kh[(size_t)MTOT * DD];          // 16 MB
__device__ uint32_t g_Vph[(size_t)BB * HH * (LL/2) * HDIM];  // 16 MB (1024*V/Z k-pair)

// ---------------------------------------------------------------------------
// Helpers
// ---------------------------------------------------------------------------
__device__ __forceinline__ void mma16816(float c[4],
    uint32_t a0, uint32_t a1, uint32_t a2, uint32_t a3,
    uint32_t b0, uint32_t b1)
{
    asm volatile(
        "mma.sync.aligned.m16n8k16.row.col.f32.f16.f16.f32 "
        "{%0,%1,%2,%3}, {%4,%5,%6,%7}, {%8,%9}, {%0,%1,%2,%3};"
        : "+f"(c[0]), "+f"(c[1]), "+f"(c[2]), "+f"(c[3])
        : "r"(a0), "r"(a1), "r"(a2), "r"(a3), "r"(b0), "r"(b1));
}

__device__ __forceinline__ void ldsm4(uint32_t r[4], uint32_t addr)
{
    asm volatile(
        "ldmatrix.sync.aligned.m8n8.x4.shared.b16 {%0,%1,%2,%3}, [%4];"
        : "=r"(r[0]), "=r"(r[1]), "=r"(r[2]), "=r"(r[3]) : "r"(addr));
}

__device__ __forceinline__ uint32_t smem_u32(const void* p) {
    uint32_t a;
    asm("{ .reg .u64 t; cvta.to.shared.u64 t, %1; cvt.u32.u64 %0, t; }"
        : "=r"(a) : "l"(p));
    return a;
}

#define CP_ASYNC16(dst_u32, src_ptr) \
    asm volatile("cp.async.cg.shared.global [%0], [%1], 16;" \
        :: "r"(dst_u32), "l"(src_ptr) : "memory")
#define CP_COMMIT() asm volatile("cp.async.commit_group;" ::: "memory")
#define CP_WAIT(n)  asm volatile("cp.async.wait_group %0;" :: "n"(n) : "memory")

__device__ __forceinline__ uint32_t pack_h2(float x, float y) {
    __half2 p = __floats2half2_rn(x, y);   // .x = x (low half)
    return *(uint32_t*)&p;
}

// ---------------------------------------------------------------------------
// fp32 -> fp16, batched over 3 inputs (blockIdx.y selects)
// ---------------------------------------------------------------------------
__global__ __launch_bounds__(256) void tof16_batch(
    const float* __restrict__ x0, const float* __restrict__ x1,
    const float* __restrict__ x2,
    __half* __restrict__ h0, __half* __restrict__ h1, __half* __restrict__ h2,
    int n4)
{
    int i = blockIdx.x * blockDim.x + threadIdx.x;
    if (i >= n4) return;
    const float* x;
    __half* h;
    if (blockIdx.y == 0)      { x = x0; h = h0; }
    else if (blockIdx.y == 1) { x = x1; h = h1; }
    else                      { x = x2; h = h2; }
    float4 v = ((const float4*)x)[i];
    __half2* hp = (__half2*)h;
    hp[2*i]   = __floats2half2_rn(v.x, v.y);
    hp[2*i+1] = __floats2half2_rn(v.z, v.w);
}

// ---------------------------------------------------------------------------
// pack 4 W's [K,N] fp32 -> k-pair fp16x2 [k2][n] (blockIdx.y selects)
// ---------------------------------------------------------------------------
__global__ __launch_bounds__(256) void pack_w_batch(
    const float* __restrict__ W0, const float* __restrict__ W1,
    const float* __restrict__ W2, const float* __restrict__ W3,
    uint32_t* __restrict__ P)
{
    int i = blockIdx.x * blockDim.x + threadIdx.x;
    if (i >= (DD/2) * DD) return;
    const float* W;
    if (blockIdx.y == 0)      W = W0;
    else if (blockIdx.y == 1) W = W1;
    else if (blockIdx.y == 2) W = W2;
    else                      W = W3;
    uint32_t* Ph = P + (size_t)blockIdx.y * WPS;
    int k2 = i >> 10, n = i & (DD - 1);
    Ph[i] = pack_h2(W[(size_t)(2*k2) * DD + n], W[(size_t)(2*k2 + 1) * DD + n]);
}

// ---------------------------------------------------------------------------
// sz[bh] = sum_k zinv[bh,k]
// ---------------------------------------------------------------------------
__global__ __launch_bounds__(256) void sumz_kernel(
    const float* __restrict__ Zi, float* __restrict__ Sz)
{
    __shared__ float red[256];
    const int bh = blockIdx.x;
    const int tid = threadIdx.x;
    float s = 0.0f;
    #pragma unroll
    for (int p = 0; p < 4; p++) s += Zi[(size_t)bh * LL + tid + p * 256];
    red[tid] = s;
    __syncthreads();
    for (int w = 128; w > 0; w >>= 1) {
        if (tid < w) red[tid] += red[tid + w];
        __syncthreads();
    }
    if (tid == 0) Sz[bh] = red[0];
}

// ---------------------------------------------------------------------------
// s_x[bh][d'] = sum_k x_v[b,k,d'] * zinv[bh,k]   (exact fp32)
// ---------------------------------------------------------------------------
__global__ __launch_bounds__(256) void sx_kernel(
    const float* __restrict__ xv, const float* __restrict__ Zi,
    float* __restrict__ Sx)
{
    extern __shared__ float szi[];   // [16][1024]
    const int b = blockIdx.x;
    const int dc = blockIdx.y;       // 0..15
    const int tid = threadIdx.x;
    const int d = tid & 63;
    const int s = tid >> 6;          // k-slice 0..3

    for (int i = tid; i < 16 * 1024; i += 256)
        szi[i] = Zi[(size_t)(b * 16) * LL + i];
    __syncthreads();

    float acc[16];
    #pragma unroll
    for (int h = 0; h < 16; h++) acc[h] = 0.0f;

    const int dglob = dc * 64 + d;
    const int k0 = s * 256;
    for (int k = k0; k < k0 + 256; k++) {
        float x = xv[((size_t)b * LL + k) * DD + dglob];
        #pragma unroll
        for (int h = 0; h < 16; h++)
            acc[h] = fmaf(x, szi[h * 1024 + k], acc[h]);
    }
    __syncthreads();
    float* red = szi;   // [4][16][64]
    #pragma unroll
    for (int h = 0; h < 16; h++)
        red[(s * 16 + h) * 64 + d] = acc[h];
    __syncthreads();
    for (int i = tid; i < 16 * 64; i += 256) {
        int h = i >> 6, dd = i & 63;
        float v = red[(0 * 16 + h) * 64 + dd] + red[(1 * 16 + h) * 64 + dd]
                + red[(2 * 16 + h) * 64 + dd] + red[(3 * 16 + h) * 64 + dd];
        Sx[(size_t)(b * 16 + h) * DD + dc * 64 + dd] = v;
    }
}

// ---------------------------------------------------------------------------
// Sv[bh][d] = sum_{d'} s_x[bh][d'] * Wv[d'][h*64+d] + bv[h*64+d]*sz[bh]
// ---------------------------------------------------------------------------
__global__ __launch_bounds__(256) void sv_kernel(
    const float* __restrict__ Sx, const float* __restrict__ Wv,
    const float* __restrict__ bv, const float* __restrict__ Sz,
    float* __restrict__ Sv)
{
    __shared__ float sxr[1024];
    __shared__ float red[4 * 64];
    const int bh = blockIdx.x;
    const int h = bh & 15;
    const int tid = threadIdx.x;
    const int d = tid & 63;
    const int s = tid >> 6;

    for (int i = tid; i < 1024; i += 256)
        sxr[i] = Sx[(size_t)bh * DD + i];
    __syncthreads();

    float acc = 0.0f;
    const int k0 = s * 256;
    const int col = h * HDIM + d;
    for (int k = k0; k < k0 + 256; k++)
        acc = fmaf(sxr[k], Wv[(size_t)k * DD + col], acc);
    red[s * 64 + d] = acc;
    __syncthreads();
    if (tid < 64)
        Sv[(size_t)bh * HDIM + d] =
            red[d] + red[64 + d] + red[128 + d] + red[192 + d] + bv[col] * Sz[bh];
}

// ---------------------------------------------------------------------------
// Single-pass fp16 HMMA GEMM (A frags via ldmatrix).
// mode 0: fp32 C = A@W + bias
// mode 1: fp16 Hout = (A@W + bias) * oscale  (gridDim.z may be 2: second set)
// mode 2: Vp pack: Vout[bh][k2][d] = fp16x2{ 1024*zi*(A@W+bias) } k-pairs
// SMEM per buffer: A 18432 + B 16896 = 35328; x2 = 70656 -> 2 CTAs/SM.
// ---------------------------------------------------------------------------
#define F_AH   0
#define F_BH   18432
#define F_BUF  35328
#define F_SMEM (2 * F_BUF)

__device__ __forceinline__ void gemm1p_load(
    uint32_t sb0, int buf, int tid, int m0, int n0, int kt,
    const __half* __restrict__ Ah, const uint32_t* __restrict__ Bh)
{
    const uint32_t sb = sb0 + buf * F_BUF;
    #pragma unroll
    for (int p = 0; p < 4; p++) {
        const int idx = tid + p * 256;
        const int r = idx >> 3, c = idx & 7;
        const size_t g = (size_t)(m0 + r) * DD + kt * 64 + c * 8;
        CP_ASYNC16(sb + F_AH + r * 144 + c * 16, Ah + g);
    }
    #pragma unroll
    for (int p = 0; p < 4; p++) {
        const int idx = tid + p * 256;
        const int r = idx >> 5, c = idx & 31;
        const size_t g = (size_t)(kt * 32 + r) * DD + n0 + c * 4;
        CP_ASYNC16(sb + F_BH + r * 528 + c * 16, Bh + g);
    }
}

__global__ __launch_bounds__(256, 2) void tc_gemm_1p_kernel(
    const __half* __restrict__ Ah_, const uint32_t* __restrict__ Bh_,
    const float* __restrict__ bias_, float* __restrict__ C,
    __half* __restrict__ Hout_, const float* __restrict__ Zi,
    uint32_t* __restrict__ Vout, float oscale_, int mode,
    const __half* __restrict__ Ah2, const float* __restrict__ bias2,
    __half* __restrict__ Hout2, float oscale2)
{
    const __half* Ah = Ah_;
    const uint32_t* Bh = Bh_;
    const float* bias = bias_;
    __half* Hout = Hout_;
    float oscale = oscale_;
    if (blockIdx.z == 1) {
        Ah = Ah2; Bh = Bh_ + WPS; bias = bias2; Hout = Hout2; oscale = oscale2;
    }

    extern __shared__ char sm[];
    const uint32_t smem_base = smem_u32(sm);
    const int tid = threadIdx.x;
    const int wid = tid >> 5;
    const int lane = tid & 31;
    const int g = lane >> 2;
    const int t = lane & 3;
    const int wm = wid >> 2;
    const int wn = wid & 3;
    const int n0 = blockIdx.x * 128;
    const int m0 = blockIdx.y * 128;

    // per-lane ldmatrix base for A fragments
    const uint32_t aFrag = smem_base + F_AH
        + (wm * 64 + (lane & 15)) * 144 + (lane >> 4) * 16;

    float c[4][4][4];
    #pragma unroll
    for (int i = 0; i < 4; i++)
        #pragma unroll
        for (int j = 0; j < 4; j++)
            #pragma unroll
            for (int q = 0; q < 4; q++) c[i][j][q] = 0.0f;

    gemm1p_load(smem_base, 0, tid, m0, n0, 0, Ah, Bh);
    CP_COMMIT();

    for (int kt = 0; kt < 16; kt++) {
        const int buf = kt & 1;
        if (kt < 15) {
            gemm1p_load(smem_base, buf ^ 1, tid, m0, n0, kt + 1, Ah, Bh);
            CP_COMMIT();
            CP_WAIT(1);
        } else {
            CP_WAIT(0);
        }
        __syncthreads();

        const uint32_t aB = aFrag + buf * F_BUF;
        const char* Bb = sm + buf * F_BUF + F_BH;

        #pragma unroll
        for (int ks = 0; ks < 4; ks++) {
            uint32_t aH[4][4], bH[4][2];
            #pragma unroll
            for (int i = 0; i < 4; i++)
                ldsm4(aH[i], aB + i * (16 * 144) + ks * 32);
            #pragma unroll
            for (int j = 0; j < 4; j++) {
                const int off = (ks * 8 + t) * 528 + (wn * 32 + j * 8 + g) * 4;
                bH[j][0] = *(const uint32_t*)(Bb + off);
                bH[j][1] = *(const uint32_t*)(Bb + off + 4 * 528);
            }
            #pragma unroll
            for (int i = 0; i < 4; i++)
                #pragma unroll
                for (int j = 0; j < 4; j++)
                    mma16816(c[i][j], aH[i][0], aH[i][1], aH[i][2], aH[i][3],
                             bH[j][0], bH[j][1]);
        }
        __syncthreads();
    }

    if (mode == 2) {
        // Stage fp32 (C + bias) tile in smem, then repack as zinv-scaled
        // fp16 k-pairs into Vp layout. stage pitch = 132 floats (528 B).
        float* stage = (float*)sm;                 // 128 x 132 fp32 = 67584 B
        float* ziS   = (float*)(sm + 67584);       // [2][128] fp32
        #pragma unroll
        for (int j = 0; j < 4; j++) {
            const int cl = wn * 32 + j * 8 + 2 * t;
            const float2 bv = *(const float2*)(bias + n0 + cl);
            #pragma unroll
            for (int i = 0; i < 4; i++) {
                const int rl = wm * 64 + i * 16 + g;
                stage[rl * 132 + cl]       = c[i][j][0] + bv.x;
                stage[rl * 132 + cl + 1]   = c[i][j][1] + bv.y;
                stage[(rl + 8) * 132 + cl]     = c[i][j][2] + bv.x;
                stage[(rl + 8) * 132 + cl + 1] = c[i][j][3] + bv.y;
            }
        }
        const int b = m0 >> 10;
        const int l0 = m0 & 1023;
        const int h0 = n0 >> 6;        // first of 2 heads in this col block
        {
            const int hh = tid >> 7, l = tid & 127;
            ziS[tid] = Zi[(size_t)(b * 16 + h0 + hh) * LL + l0 + l] * 1024.0f;
        }
        __syncthreads();
        const int k20 = l0 >> 1;
        #pragma unroll
        for (int p = 0; p < 32; p++) {
            const int i = tid + p * 256;          // 0..8191
            const int hh = i >> 12;
            const int k2r = (i >> 6) & 63;
            const int d = i & 63;
            float v0 = stage[(2 * k2r) * 132 + hh * 64 + d] * ziS[hh * 128 + 2 * k2r];
            float v1 = stage[(2 * k2r + 1) * 132 + hh * 64 + d] * ziS[hh * 128 + 2 * k2r + 1];
            Vout[((size_t)(b * 16 + h0 + hh) * 512 + k20 + k2r) * 64 + d] =
                pack_h2(v0, v1);
        }
        return;
    }

    #pragma unroll
    for (int j = 0; j < 4; j++) {
        const int col = n0 + wn * 32 + j * 8 + 2 * t;
        const float2 bv = *(const float2*)(bias + col);
        #pragma unroll
        for (int i = 0; i < 4; i++) {
            const int row = m0 + wm * 64 + i * 16 + g;
            float v0 = c[i][j][0] + bv.x, v1 = c[i][j][1] + bv.y;
            float v2 = c[i][j][2] + bv.x, v3 = c[i][j][3] + bv.y;
            if (mode == 0) {
                float* o = C + (size_t)row * DD + col;
                *(float2*)o = make_float2(v0, v1);
                *(float2*)(o + 8 * DD) = make_float2(v2, v3);
            } else {
                *(uint32_t*)(Hout + (size_t)row * DD + col) =
                    pack_h2(v0 * oscale, v1 * oscale);
                *(uint32_t*)(Hout + (size_t)(row + 8) * DD + col) =
                    pack_h2(v2 * oscale, v3 * oscale);
            }
        }
    }
}

// ---------------------------------------------------------------------------
// HMMA colsum (fp16, ldmatrix): zinv[bh,k] = 1 / sum_q exp(S_qk)
// ---------------------------------------------------------------------------
#define CS_KH  0
#define CS_QH  18432
#define CS_RED 36864
#define CS_SMEM 37888

__global__ __launch_bounds__(256, 2) void attn_colsum_tc(
    const __half* __restrict__ Qh, const __half* __restrict__ Kh,
    float* __restrict__ zinv)
{
    extern __shared__ char sm[];
    const uint32_t sb = smem_u32(sm);
    const int tid = threadIdx.x;
    const int wid = tid >> 5;
    const int lane = tid & 31;
    const int g = lane >> 2;
    const int t = lane & 3;
    const int wm = wid >> 2;
    const int wn = wid & 3;
    const int kt = blockIdx.x;
    const int bh = blockIdx.y;
    const int b = bh >> 4, h = bh & 15;

    // ldmatrix bases
    const uint32_t aFrag = sb + CS_QH
        + (wm * 64 + (lane & 15)) * 144 + (lane >> 4) * 16;
    const uint32_t bFrag = sb + CS_KH
        + (wn * 32 + ((lane >> 4) << 3) + (lane & 7)) * 144 + ((lane >> 3) & 1) * 16;

    #pragma unroll
    for (int p = 0; p < 4; p++) {
        const int idx = tid + p * 256;
        const int r = idx >> 3, c = idx & 7;
        const size_t go = ((size_t)(b * LL + kt * 128 + r)) * DD + h * HDIM + c * 8;
        CP_ASYNC16(sb + CS_KH + r * 144 + c * 16, Kh + go);
    }
    #pragma unroll
    for (int p = 0; p < 4; p++) {
        const int idx = tid + p * 256;
        const int r = idx >> 3, c = idx & 7;
        const size_t go = ((size_t)(b * LL + r)) * DD + h * HDIM + c * 8;
        CP_ASYNC16(sb + CS_QH + r * 144 + c * 16, Qh + go);
    }
    CP_COMMIT();

    float cs[4][2];
    #pragma unroll
    for (int j = 0; j < 4; j++) { cs[j][0] = 0.0f; cs[j][1] = 0.0f; }

    for (int qt = 0; qt < 8; qt++) {
        CP_WAIT(0);
        __syncthreads();

        float acc[4][4][4];
        #pragma unroll
        for (int i = 0; i < 4; i++)
            #pragma unroll
            for (int j = 0; j < 4; j++)
                #pragma unroll
                for (int q = 0; q < 4; q++) acc[i][j][q] = 0.0f;

        #pragma unroll
        for (int ks = 0; ks < 4; ks++) {
            uint32_t aH[4][4], bf[2][4];
            #pragma unroll
            for (int i = 0; i < 4; i++)
                ldsm4(aH[i], aFrag + i * (16 * 144) + ks * 32);
            #pragma unroll
            for (int j2 = 0; j2 < 2; j2++)
                ldsm4(bf[j2], bFrag + j2 * (16 * 144) + ks * 32);
            #pragma unroll
            for (int i = 0; i < 4; i++)
                #pragma unroll
                for (int j = 0; j < 4; j++)
                    mma16816(acc[i][j], aH[i][0], aH[i][1], aH[i][2], aH[i][3],
                             bf[j >> 1][2 * (j & 1)], bf[j >> 1][2 * (j & 1) + 1]);
        }

        #pragma unroll
        for (int i = 0; i < 4; i++)
            #pragma unroll
            for (int j = 0; j < 4; j++) {
                cs[j][0] += __expf(acc[i][j][0]) + __expf(acc[i][j][2]);
                cs[j][1] += __expf(acc[i][j][1]) + __expf(acc[i][j][3]);
            }

        __syncthreads();
        if (qt < 7) {
            #pragma unroll
            for (int p = 0; p < 4; p++) {
                const int idx = tid + p * 256;
                const int r = idx >> 3, c = idx & 7;
                const size_t go = ((size_t)(b * LL + (qt + 1) * 128 + r)) * DD + h * HDIM + c * 8;
                CP_ASYNC16(sb + CS_QH + r * 144 + c * 16, Qh + go);
            }
            CP_COMMIT();
        }
    }

    float* red = (float*)(sm + CS_RED);
    #pragma unroll
    for (int j = 0; j < 4; j++)
        #pragma unroll
        for (int hh = 0; hh < 2; hh++) {
            float v = cs[j][hh];
            v += __shfl_down_sync(0xffffffffu, v, 16);
            v += __shfl_down_sync(0xffffffffu, v, 8);
            v += __shfl_down_sync(0xffffffffu, v, 4);
            if (g == 0) red[wid * 32 + j * 8 + 2 * t + hh] = v;
        }
    __syncthreads();
    if (tid < 128) {
        const int col = tid;
        const int w2 = col >> 5, cl = col & 31;
        zinv[(size_t)bh * LL + kt * 128 + col] =
            1.0f / (red[w2 * 32 + cl] + red[(w2 + 4) * 32 + cl]);
    }
}

// ---------------------------------------------------------------------------
// HMMA AV (E = 1 + e, ldmatrix): out = Sv + (1/1024) * sum_k e * (1024*Vp)
// 64-row q tiles, occupancy 2. Grid (16, 128), 256 thr.
// SMEM: QH 9216 | KH 18432 | E 17408 | VP 2x17408 = 79872
// ---------------------------------------------------------------------------
#define AV_QH   0
#define AV_KH   9216
#define AV_E    27648
#define AV_VP0  45056
#define AV_VPB  17408
#define AV_SMEM 79872

__device__ __forceinline__ void av_load_kvp(
    uint32_t sb, int tid, int b, int h, int bh, int kt, int buf,
    const __half* __restrict__ Kh, const uint32_t* __restrict__ Vph)
{
    #pragma unroll
    for (int p = 0; p < 4; p++) {
        const int idx = tid + p * 256;
        const int r = idx >> 3, c = idx & 7;
        const size_t go = ((size_t)(b * LL + kt * 128 + r)) * DD + h * HDIM + c * 8;
        CP_ASYNC16(sb + AV_KH + r * 144 + c * 16, Kh + go);
    }
    const uint32_t vb = sb + AV_VP0 + buf * AV_VPB;
    #pragma unroll
    for (int p = 0; p < 4; p++) {
        const int idx = tid + p * 256;
        const int r = idx >> 4, c = idx & 15;
        const size_t go = ((size_t)bh * 512 + kt * 64 + r) * 64 + c * 4;
        CP_ASYNC16(vb + r * 272 + c * 16, Vph + go);
    }
}

__global__ __launch_bounds__(256, 2) void attn_av_tc(
    const __half* __restrict__ Qh, const __half* __restrict__ Kh,
    const uint32_t* __restrict__ Vph, const float* __restrict__ Sv,
    __half* __restrict__ Oh)
{
    extern __shared__ char sm[];
    const uint32_t sb = smem_u32(sm);
    const int tid = threadIdx.x;
    const int wid = tid >> 5;
    const int lane = tid & 31;
    const int g = lane >> 2;
    const int t = lane & 3;
    const int wm = wid >> 2;       // 0..1: 32-row slab
    const int wn = wid & 3;        // 0..3: 32-col (S) / 16-col (out) slab
    const int qt = blockIdx.x;     // 0..15, 64-row q tiles
    const int bh = blockIdx.y;
    const int b = bh >> 4, h = bh & 15;

    // ldmatrix bases
    const uint32_t aFragQ = sb + AV_QH
        + (wm * 32 + (lane & 15)) * 144 + (lane >> 4) * 16;
    const uint32_t bFragK = sb + AV_KH
        + (wn * 32 + ((lane >> 4) << 3) + (lane & 7)) * 144 + ((lane >> 3) & 1) * 16;
    const uint32_t eFrag = sb + AV_E
        + (wm * 32 + (lane & 15)) * 272 + (lane >> 4) * 16;

    // load Q tile 64x64 fp16 (512 chunks)
    #pragma unroll
    for (int p = 0; p < 2; p++) {
        const int idx = tid + p * 256;
        const int r = idx >> 3, c = idx & 7;
        const size_t go = ((size_t)(b * LL + qt * 64 + r)) * DD + h * HDIM + c * 8;
        CP_ASYNC16(sb + AV_QH + r * 144 + c * 16, Qh + go);
    }
    av_load_kvp(sb, tid, b, h, bh, 0, 0, Kh, Vph);
    CP_COMMIT();

    float out[2][2][4];
    #pragma unroll
    for (int i = 0; i < 2; i++)
        #pragma unroll
        for (int j = 0; j < 2; j++)
            #pragma unroll
            for (int q = 0; q < 4; q++) out[i][j][q] = 0.0f;

    for (int kt = 0; kt < 8; kt++) {
        const int buf = kt & 1;
        CP_WAIT(0);
        __syncthreads();

        // ---- GEMM1: S (64x128) = Q . K^T ----
        float acc[2][4][4];
        #pragma unroll
        for (int i = 0; i < 2; i++)
            #pragma unroll
            for (int j = 0; j < 4; j++)
                #pragma unroll
                for (int q = 0; q < 4; q++) acc[i][j][q] = 0.0f;

        #pragma unroll
        for (int ks = 0; ks < 4; ks++) {
            uint32_t aH[2][4], bf[2][4];
            #pragma unroll
            for (int i = 0; i < 2; i++)
                ldsm4(aH[i], aFragQ + i * (16 * 144) + ks * 32);
            #pragma unroll
            for (int j2 = 0; j2 < 2; j2++)
                ldsm4(bf[j2], bFragK + j2 * (16 * 144) + ks * 32);
            #pragma unroll
            for (int i = 0; i < 2; i++)
                #pragma unroll
                for (int j = 0; j < 4; j++)
                    mma16816(acc[i][j], aH[i][0], aH[i][1], aH[i][2], aH[i][3],
                             bf[j >> 1][2 * (j & 1)], bf[j >> 1][2 * (j & 1) + 1]);
        }

        // ---- e = exp(S) - 1 -> smem (pitch 272) ----
        #pragma unroll
        for (int i = 0; i < 2; i++) {
            const int row = wm * 32 + i * 16 + g;
            #pragma unroll
            for (int j = 0; j < 4; j++) {
                const int colb = (wn * 32 + j * 8 + 2 * t) * 2;
                float e0 = __expf(acc[i][j][0]) - 1.0f;
                float e1 = __expf(acc[i][j][1]) - 1.0f;
                float e2 = __expf(acc[i][j][2]) - 1.0f;
                float e3 = __expf(acc[i][j][3]) - 1.0f;
                *(uint32_t*)(sm + AV_E + row * 272 + colb) = pack_h2(e0, e1);
                *(uint32_t*)(sm + AV_E + (row + 8) * 272 + colb) = pack_h2(e2, e3);
            }
        }
        __syncthreads();

        if (kt < 7) {
            av_load_kvp(sb, tid, b, h, bh, kt + 1, buf ^ 1, Kh, Vph);
            CP_COMMIT();
        }

        // ---- GEMM2: out (64x64) += e . Vp ----
        const char* VH = sm + AV_VP0 + buf * AV_VPB;
        #pragma unroll
        for (int ks = 0; ks < 8; ks++) {
            uint32_t aE[2][4], bV[2][2];
            #pragma unroll
            for (int i = 0; i < 2; i++)
                ldsm4(aE[i], eFrag + i * (16 * 272) + ks * 32);
            #pragma unroll
            for (int j = 0; j < 2; j++) {
                const int off = (ks * 8 + t) * 272 + (wn * 16 + j * 8 + g) * 4;
                bV[j][0] = *(const uint32_t*)(VH + off);
                bV[j][1] = *(const uint32_t*)(VH + off + 4 * 272);
            }
            #pragma unroll
            for (int i = 0; i < 2; i++)
                #pragma unroll
                for (int j = 0; j < 2; j++)
                    mma16816(out[i][j], aE[i][0], aE[i][1], aE[i][2], aE[i][3],
                             bV[j][0], bV[j][1]);
        }
        __syncthreads();
    }

    const float s = 1.0f / 1024.0f;
    #pragma unroll
    for (int i = 0; i < 2; i++) {
        const int row = qt * 64 + wm * 32 + i * 16 + g;
        #pragma unroll
        for (int j = 0; j < 2; j++) {
            const int dcol = wn * 16 + j * 8 + 2 * t;
            const float sv0 = Sv[(size_t)bh * HDIM + dcol];
            const float sv1 = Sv[(size_t)bh * HDIM + dcol + 1];
            const size_t o0 = ((size_t)b * LL + row) * DD + h * HDIM + dcol;
            const size_t o1 = ((size_t)b * LL + row + 8) * DD + h * HDIM + dcol;
            *(uint32_t*)(Oh + o0) =
                pack_h2(out[i][j][0] * s + sv0, out[i][j][1] * s + sv1);
            *(uint32_t*)(Oh + o1) =
                pack_h2(out[i][j][2] * s + sv0, out[i][j][3] * s + sv1);
        }
    }
}

// ---------------------------------------------------------------------------
// Launch
// ---------------------------------------------------------------------------
extern "C" void kernel_launch(void* const* d_in, const int* in_sizes, int n_in,
                              void* d_out, int out_size)
{
    (void)in_sizes; (void)n_in; (void)out_size;

    const float* x_q = (const float*)d_in[0];
    const float* x_k = (const float*)d_in[1];
    const float* x_v = (const float*)d_in[2];
    // d_in[3] = mask: unused (reference never applies it)
    const float* Wq  = (const float*)d_in[4];
    const float* bq  = (const float*)d_in[5];
    const float* Wk  = (const float*)d_in[6];
    const float* bk  = (const float*)d_in[7];
    const float* Wv  = (const float*)d_in[8];
    const float* bv  = (const float*)d_in[9];
    const float* Wo  = (const float*)d_in[10];
    const float* bo  = (const float*)d_in[11];

    float *pZi, *pSz, *pSx, *pSv;
    __half *pAh, *pXk, *pXv, *pQh, *pKh;
    uint32_t *pWp, *pVh;
    cudaGetSymbolAddress((void**)&pZi, g_zinv);
    cudaGetSymbolAddress((void**)&pSz, g_sz);
    cudaGetSymbolAddress((void**)&pSx, g_sx);
    cudaGetSymbolAddress((void**)&pSv, g_Sv);
    cudaGetSymbolAddress((void**)&pAh, g_Ah);
    cudaGetSymbolAddress((void**)&pXk, g_Xk);
    cudaGetSymbolAddress((void**)&pXv, g_Xv);
    cudaGetSymbolAddress((void**)&pWp, g_Wp);
    cudaGetSymbolAddress((void**)&pQh, g_Qh);
    cudaGetSymbolAddress((void**)&pKh, g_Kh);
    cudaGetSymbolAddress((void**)&pVh, g_Vph);

    cudaFuncSetAttribute(tc_gemm_1p_kernel,
                         cudaFuncAttributeMaxDynamicSharedMemorySize, F_SMEM);
    cudaFuncSetAttribute(attn_colsum_tc,
                         cudaFuncAttributeMaxDynamicSharedMemorySize, CS_SMEM);
    cudaFuncSetAttribute(attn_av_tc,
                         cudaFuncAttributeMaxDynamicSharedMemorySize, AV_SMEM);
    cudaFuncSetAttribute(sx_kernel,
                         cudaFuncAttributeMaxDynamicSharedMemorySize, 65536);

    const int n4 = MTOT * DD / 4;
    const dim3 t256(256);
    const int npack = (DD / 2) * DD;
    const dim3 gGemm(DD / 128, MTOT / 128, 1);
    const dim3 gGemmQK(DD / 128, MTOT / 128, 2);

    // All fp32->fp16 conversions and W packs, batched
    tof16_batch<<<dim3((n4 + 255) / 256, 3), t256>>>(
        x_q, x_k, x_v, pAh, pXk, pXv, n4);
    pack_w_batch<<<dim3((npack + 255) / 256, 4), t256>>>(Wq, Wk, Wv, Wo, pWp);

    // Q + K projections in one launch (z=0: Q scaled 1/32; z=1: K)
    tc_gemm_1p_kernel<<<gGemmQK, 256, F_SMEM>>>(
        pAh, pWp, bq, nullptr, pQh, nullptr, nullptr, 0.03125f, 1,
        pXk, bk, pKh, 1.0f);

    // zinv = 1 / column-softmax sums (needs only Qh, Kh)
    attn_colsum_tc<<<dim3(8, BB * HH), 256, CS_SMEM>>>(pQh, pKh, pZi);

    // Exact Sv via commuted identity: Sv = (sum_k x_v zi) @ Wv + bv * sum(zi)
    sumz_kernel<<<BB * HH, 256>>>(pZi, pSz);
    sx_kernel<<<dim3(BB, 16), 256, 65536>>>(x_v, pZi, pSx);
    sv_kernel<<<BB * HH, 256>>>(pSx, Wv, bv, pSz, pSv);

    // V projection fused with Vp pack (mode 2): writes 1024*V/Z k-pairs
    tc_gemm_1p_kernel<<<gGemm, 256, F_SMEM>>>(
        pXv, pWp + 2 * WPS, bv, nullptr, nullptr, pZi, pVh, 1.0f, 2,
        nullptr, nullptr, nullptr, 0.0f);

    // AV -> fp16 attention output in g_Ah
    attn_av_tc<<<dim3(16, BB * HH), 256, AV_SMEM>>>(pQh, pKh, pVh, pSv, pAh);

    // Output projection (mode 0) -> d_out
    tc_gemm_1p_kernel<<<gGemm, 256, F_SMEM>>>(
        pAh, pWp + 3 * WPS, bo, (float*)d_out, nullptr, nullptr, nullptr, 1.0f, 0,
        nullptr, nullptr, nullptr, 0.0f);
}